// round 1
// baseline (speedup 1.0000x reference)
#include <cuda_runtime.h>

// ---------------- problem constants ----------------
namespace {
constexpr int B_  = 32;
constexpr int N_  = 1000;
constexpr int S_  = 200;
constexpr int D_  = 128;
constexpr int H_  = 8;
constexpr int DK_ = 16;
constexpr int FF_ = 512;
constexpr int NL_ = 3;
constexpr int HK_ = H_ * DK_;          // 128
constexpr int U_  = N_ - S_;           // 800 unselected
constexpr int L_  = U_ + 2;            // 802 sequence length
constexpr int M_  = B_ * L_;           // 25664 rows
constexpr int KVP = 20;                // padded K/V row stride (floats) for conflict-free LDS.128
constexpr int AT_SMEM = (2 * L_ * KVP + 16 * L_) * 4;   // 179,648 B dynamic smem
}

// ---------------- device scratch (no runtime allocation allowed) ----------------
__device__ float g_x   [M_ * D_];
__device__ float g_o   [M_ * D_];
__device__ float g_out1[M_ * D_];
__device__ float g_q   [M_ * D_];   // [B,H,L,DK]
__device__ float g_k   [M_ * D_];
__device__ float g_v   [M_ * D_];
__device__ float g_h   [M_ * FF_];
__device__ float g_logits[M_];
__device__ int   g_unsel[B_ * U_];

// ---------------- helpers ----------------
__device__ __forceinline__ void ld16(float* r, const float* p) {
    const float4* p4 = (const float4*)p;
    float4 x0 = p4[0], x1 = p4[1], x2 = p4[2], x3 = p4[3];
    r[0]=x0.x; r[1]=x0.y; r[2]=x0.z; r[3]=x0.w;
    r[4]=x1.x; r[5]=x1.y; r[6]=x1.z; r[7]=x1.w;
    r[8]=x2.x; r[9]=x2.y; r[10]=x2.z; r[11]=x2.w;
    r[12]=x3.x; r[13]=x3.y; r[14]=x3.z; r[15]=x3.w;
}

// ---------------- 1) unselected-index compaction (ascending) ----------------
__global__ void __launch_bounds__(1024) unselect_k(const int* __restrict__ sel,
                                                   int* __restrict__ unsel) {
    __shared__ int keep[1024];
    __shared__ int scan[1024];
    const int b = blockIdx.x, t = threadIdx.x;
    keep[t] = (t < N_) ? 1 : 0;
    __syncthreads();
    if (t < S_) keep[sel[b * S_ + t]] = 0;
    __syncthreads();
    const int k = keep[t];
    scan[t] = k;
    __syncthreads();
    #pragma unroll
    for (int off = 1; off < 1024; off <<= 1) {
        int add = (t >= off) ? scan[t - off] : 0;
        __syncthreads();
        scan[t] += add;
        __syncthreads();
    }
    if (k && t < N_) unsel[b * U_ + scan[t] - 1] = t;
}

// ---------------- 2) build x0 = [ef, gathered rows, el] ----------------
__global__ void __launch_bounds__(128) build_x0_k(
    const float* __restrict__ data, const int* __restrict__ sel,
    const int* __restrict__ unsel,
    const float* __restrict__ Wf, const float* __restrict__ bf,
    const float* __restrict__ Wl, const float* __restrict__ bl,
    float* __restrict__ x)
{
    const int l = blockIdx.x, b = blockIdx.y, t = threadIdx.x;
    float* xr = x + ((size_t)b * L_ + l) * D_;
    if (l == 0 || l == L_ - 1) {
        __shared__ float vin[D_];
        const int node = (l == 0) ? sel[b * S_] : sel[b * S_ + S_ - 1];
        vin[t] = data[((size_t)b * N_ + node) * D_ + t];
        __syncthreads();
        const float* W  = (l == 0) ? Wf : Wl;
        const float* bb = (l == 0) ? bf : bl;
        float acc = bb[t];
        #pragma unroll 16
        for (int i = 0; i < D_; i++) acc = fmaf(vin[i], W[i * D_ + t], acc);
        xr[t] = acc;
    } else {
        const int node = unsel[b * U_ + (l - 1)];
        xr[t] = data[((size_t)b * N_ + node) * D_ + t];
    }
}

// ---------------- 3) tiled SGEMM, 64x64x16 tiles, 4x4 per thread ----------------
// EPI 0: scatter to [B,H,L,DK]   (QKV projections)
// EPI 1: C = acc + bias[n] + res (Wo + residual, FF2 + residual)
// EPI 2: C = relu(acc + bias[n]) (FF1)
template <int EPI>
__global__ void __launch_bounds__(256) gemm_k(
    const float* __restrict__ A, const float* __restrict__ W,
    float* __restrict__ C, const float* __restrict__ bias,
    const float* __restrict__ res, int M, int Nn, int K)
{
    __shared__ float As[64][17];
    __shared__ float Bs[16][64];
    const int bm = blockIdx.y * 64;
    const int bn = blockIdx.x * 64;
    const int tid = threadIdx.x;
    const int tx = tid & 15, ty = tid >> 4;
    float acc[4][4] = {};
    for (int k0 = 0; k0 < K; k0 += 16) {
        #pragma unroll
        for (int i = 0; i < 4; i++) {
            int e = tid + i * 256;
            int m = e >> 4, kk = e & 15;
            As[m][kk] = A[(size_t)(bm + m) * K + k0 + kk];
        }
        #pragma unroll
        for (int i = 0; i < 4; i++) {
            int e = tid + i * 256;
            int kk = e >> 6, n = e & 63;
            Bs[kk][n] = W[(size_t)(k0 + kk) * Nn + bn + n];
        }
        __syncthreads();
        #pragma unroll
        for (int kk = 0; kk < 16; kk++) {
            float4 bv = *(const float4*)&Bs[kk][tx * 4];
            float bq[4] = {bv.x, bv.y, bv.z, bv.w};
            #pragma unroll
            for (int i = 0; i < 4; i++) {
                float a = As[ty * 4 + i][kk];
                #pragma unroll
                for (int j = 0; j < 4; j++) acc[i][j] = fmaf(a, bq[j], acc[i][j]);
            }
        }
        __syncthreads();
    }
    #pragma unroll
    for (int i = 0; i < 4; i++) {
        const int gm = bm + ty * 4 + i;
        if (EPI == 0) {
            const int bb = gm / L_;
            const int ll = gm - bb * L_;
            #pragma unroll
            for (int j = 0; j < 4; j++) {
                int gn = bn + tx * 4 + j;
                int hh = gn >> 4, dk = gn & 15;
                C[(((size_t)bb * H_ + hh) * L_ + ll) * DK_ + dk] = acc[i][j];
            }
        } else if (EPI == 1) {
            #pragma unroll
            for (int j = 0; j < 4; j++) {
                int gn = bn + tx * 4 + j;
                C[(size_t)gm * Nn + gn] = acc[i][j] + bias[gn] + res[(size_t)gm * Nn + gn];
            }
        } else {
            #pragma unroll
            for (int j = 0; j < 4; j++) {
                int gn = bn + tx * 4 + j;
                float vv = acc[i][j] + bias[gn];
                C[(size_t)gm * Nn + gn] = vv > 0.f ? vv : 0.f;
            }
        }
    }
}

// ---------------- 4) fused attention: one block per (b,h) ----------------
// K/V staged in smem (padded stride KVP); each warp handles 2 queries per pass.
__global__ void __launch_bounds__(256) attn_k(
    const float* __restrict__ q, const float* __restrict__ k,
    const float* __restrict__ v, float* __restrict__ o)
{
    extern __shared__ float sm[];
    float* Ks = sm;
    float* Vs = sm + L_ * KVP;
    float* Ws = sm + 2 * L_ * KVP;
    const int bh = blockIdx.x;
    const int b = bh >> 3, h = bh & 7;
    const int tid = threadIdx.x, lane = tid & 31, warp = tid >> 5;

    const float* kp = k + (size_t)bh * L_ * DK_;
    const float* vp = v + (size_t)bh * L_ * DK_;
    for (int i = tid; i < L_ * DK_; i += 256) {
        int j = i >> 4, d = i & 15;
        Ks[j * KVP + d] = kp[i];
        Vs[j * KVP + d] = vp[i];
    }
    __syncthreads();

    float* ws0 = Ws + (warp * 2 + 0) * L_;
    float* ws1 = Ws + (warp * 2 + 1) * L_;
    const float* qb = q + (size_t)bh * L_ * DK_;
    const int dd = lane & 15, half = lane >> 4;

    for (int q0 = warp * 2; q0 < L_; q0 += 16) {
        float qa[16], qc[16];
        ld16(qa, qb + (size_t)q0 * DK_);
        ld16(qc, qb + (size_t)(q0 + 1) * DK_);

        float m0 = -1e30f, m1 = -1e30f;
        for (int j = lane; j < L_; j += 32) {
            float kr[16];
            ld16(kr, Ks + j * KVP);
            float s0 = 0.f, s1 = 0.f;
            #pragma unroll
            for (int d = 0; d < 16; d++) {
                s0 = fmaf(qa[d], kr[d], s0);
                s1 = fmaf(qc[d], kr[d], s1);
            }
            s0 *= 0.25f; s1 *= 0.25f;          // 1/sqrt(DK)
            ws0[j] = s0; ws1[j] = s1;
            m0 = fmaxf(m0, s0); m1 = fmaxf(m1, s1);
        }
        #pragma unroll
        for (int off = 16; off; off >>= 1) {
            m0 = fmaxf(m0, __shfl_xor_sync(0xffffffffu, m0, off));
            m1 = fmaxf(m1, __shfl_xor_sync(0xffffffffu, m1, off));
        }
        float t0 = 0.f, t1 = 0.f;
        for (int j = lane; j < L_; j += 32) {
            float w0 = __expf(ws0[j] - m0);
            float w1 = __expf(ws1[j] - m1);
            ws0[j] = w0; ws1[j] = w1;
            t0 += w0; t1 += w1;
        }
        #pragma unroll
        for (int off = 16; off; off >>= 1) {
            t0 += __shfl_xor_sync(0xffffffffu, t0, off);
            t1 += __shfl_xor_sync(0xffffffffu, t1, off);
        }
        const float inv0 = 1.f / t0, inv1 = 1.f / t1;
        __syncwarp();
        float acc0 = 0.f, acc1 = 0.f;
        for (int j = half; j < L_; j += 2) {
            float vv = Vs[j * KVP + dd];
            acc0 = fmaf(ws0[j], vv, acc0);
            acc1 = fmaf(ws1[j], vv, acc1);
        }
        acc0 += __shfl_xor_sync(0xffffffffu, acc0, 16);
        acc1 += __shfl_xor_sync(0xffffffffu, acc1, 16);
        if (lane < 16) {
            o[((size_t)b * L_ + q0)     * HK_ + h * DK_ + dd] = acc0 * inv0;
            o[((size_t)b * L_ + q0 + 1) * HK_ + h * DK_ + dd] = acc1 * inv1;
        }
        __syncwarp();
    }
}

// ---------------- 5) logits GEMV: warp per row ----------------
__global__ void __launch_bounds__(256) logits_k(
    const float* __restrict__ x, const float* __restrict__ Wfin,
    const float* __restrict__ bfin, float* __restrict__ logits)
{
    const int row  = (int)((blockIdx.x * (size_t)blockDim.x + threadIdx.x) >> 5);
    const int lane = threadIdx.x & 31;
    if (row >= M_) return;
    float4 xv = ((const float4*)(x + (size_t)row * D_))[lane];
    float4 wv = ((const float4*)Wfin)[lane];
    float s = xv.x * wv.x + xv.y * wv.y + xv.z * wv.z + xv.w * wv.w;
    #pragma unroll
    for (int off = 16; off; off >>= 1) s += __shfl_xor_sync(0xffffffffu, s, off);
    if (lane == 0) logits[row] = s + bfin[0];
}

// ---------------- 6) bias add + softmax + scatter, one block per batch ----------------
__global__ void __launch_bounds__(1024) finalize_k(
    const float* __restrict__ logits, const float* __restrict__ ab,
    const int* __restrict__ sel, const int* __restrict__ unsel,
    float* __restrict__ out)
{
    __shared__ float red[32];
    const int b = blockIdx.x, t = threadIdx.x;
    const int lane = t & 31, warp = t >> 5;
    const int last = sel[b * S_ + S_ - 1];
    const float* abrow = ab + ((size_t)b * N_ + last) * N_;

    int u = 0;
    float val = -3.0e38f;
    const bool active = (t < U_);
    if (active) {
        u = unsel[b * U_ + t];
        val = logits[b * L_ + 1 + t] + abrow[u];
    }
    // block max
    float m = val;
    #pragma unroll
    for (int off = 16; off; off >>= 1) m = fmaxf(m, __shfl_xor_sync(0xffffffffu, m, off));
    if (lane == 0) red[warp] = m;
    __syncthreads();
    if (warp == 0) {
        float mm = red[lane];
        #pragma unroll
        for (int off = 16; off; off >>= 1) mm = fmaxf(mm, __shfl_xor_sync(0xffffffffu, mm, off));
        red[lane] = mm;
    }
    __syncthreads();
    m = red[0];
    __syncthreads();
    // block sum
    const float e = active ? __expf(val - m) : 0.f;
    float s = e;
    #pragma unroll
    for (int off = 16; off; off >>= 1) s += __shfl_xor_sync(0xffffffffu, s, off);
    if (lane == 0) red[warp] = s;
    __syncthreads();
    if (warp == 0) {
        float ss = red[lane];
        #pragma unroll
        for (int off = 16; off; off >>= 1) ss += __shfl_xor_sync(0xffffffffu, ss, off);
        red[lane] = ss;
    }
    __syncthreads();
    const float inv = 1.f / red[0];

    for (int i = t; i < N_; i += 1024) out[(size_t)b * N_ + i] = -2.0f;
    __syncthreads();
    if (active) {
        float p = e * inv;
        if (p <= 1e-5f) p += 1e-7f;
        out[(size_t)b * N_ + u] = p;
    }
}

// ---------------- launch ----------------
extern "C" void kernel_launch(void* const* d_in, const int* in_sizes, int n_in,
                              void* d_out, int out_size) {
    (void)in_sizes; (void)n_in; (void)out_size;
    const float* data   = (const float*)d_in[0];
    const float* ab     = (const float*)d_in[1];
    const float* Wfirst = (const float*)d_in[2];
    const float* bfirst = (const float*)d_in[3];
    const float* Wlast  = (const float*)d_in[4];
    const float* blast  = (const float*)d_in[5];
    const float* Wq     = (const float*)d_in[6];
    const float* Wk     = (const float*)d_in[7];
    const float* Wv     = (const float*)d_in[8];
    const float* Wo     = (const float*)d_in[9];
    const float* bo     = (const float*)d_in[10];
    const float* W1     = (const float*)d_in[11];
    const float* b1     = (const float*)d_in[12];
    const float* W2     = (const float*)d_in[13];
    const float* b2     = (const float*)d_in[14];
    const float* Wfin   = (const float*)d_in[15];
    const float* bfin   = (const float*)d_in[16];
    const int*   sel    = (const int*)d_in[17];
    float* out = (float*)d_out;

    void *px, *po, *pout1, *pq, *pk, *pv, *ph, *plog, *pun;
    cudaGetSymbolAddress(&px,    g_x);
    cudaGetSymbolAddress(&po,    g_o);
    cudaGetSymbolAddress(&pout1, g_out1);
    cudaGetSymbolAddress(&pq,    g_q);
    cudaGetSymbolAddress(&pk,    g_k);
    cudaGetSymbolAddress(&pv,    g_v);
    cudaGetSymbolAddress(&ph,    g_h);
    cudaGetSymbolAddress(&plog,  g_logits);
    cudaGetSymbolAddress(&pun,   g_unsel);
    float* x    = (float*)px;
    float* o    = (float*)po;
    float* out1 = (float*)pout1;
    float* q    = (float*)pq;
    float* k    = (float*)pk;
    float* v    = (float*)pv;
    float* hbuf = (float*)ph;
    float* logits = (float*)plog;
    int*   unsel  = (int*)pun;

    cudaFuncSetAttribute(attn_k, cudaFuncAttributeMaxDynamicSharedMemorySize, AT_SMEM);

    unselect_k<<<B_, 1024>>>(sel, unsel);
    build_x0_k<<<dim3(L_, B_), D_>>>(data, sel, unsel, Wfirst, bfirst, Wlast, blast, x);

    const dim3 g128(HK_ / 64, M_ / 64);   // (2, 401)
    const dim3 g512(FF_ / 64, M_ / 64);   // (8, 401)
    for (int il = 0; il < NL_; il++) {
        const float* wq = Wq + (size_t)il * D_ * HK_;
        const float* wk = Wk + (size_t)il * D_ * HK_;
        const float* wv = Wv + (size_t)il * D_ * HK_;
        const float* wo = Wo + (size_t)il * HK_ * D_;
        const float* bol = bo + (size_t)il * D_;
        const float* w1 = W1 + (size_t)il * D_ * FF_;
        const float* b1l = b1 + (size_t)il * FF_;
        const float* w2 = W2 + (size_t)il * FF_ * D_;
        const float* b2l = b2 + (size_t)il * D_;

        gemm_k<0><<<g128, 256>>>(x, wq, q, nullptr, nullptr, M_, HK_, D_);
        gemm_k<0><<<g128, 256>>>(x, wk, k, nullptr, nullptr, M_, HK_, D_);
        gemm_k<0><<<g128, 256>>>(x, wv, v, nullptr, nullptr, M_, HK_, D_);
        attn_k<<<B_ * H_, 256, AT_SMEM>>>(q, k, v, o);
        gemm_k<1><<<g128, 256>>>(o, wo, out1, bol, x, M_, D_, HK_);
        gemm_k<2><<<g512, 256>>>(out1, w1, hbuf, b1l, nullptr, M_, FF_, D_);
        gemm_k<1><<<g128, 256>>>(hbuf, w2, x, b2l, out1, M_, D_, FF_);
    }

    logits_k<<<(M_ * 32 + 255) / 256, 256>>>(x, Wfin, bfin, logits);
    finalize_k<<<B_, 1024>>>(logits, ab, sel, unsel, out);
}

// round 2
// speedup vs baseline: 1.8020x; 1.8020x over previous
#include <cuda_runtime.h>

// ---------------- problem constants ----------------
namespace {
constexpr int B_  = 32;
constexpr int N_  = 1000;
constexpr int S_  = 200;
constexpr int D_  = 128;
constexpr int H_  = 8;
constexpr int DK_ = 16;
constexpr int FF_ = 512;
constexpr int NL_ = 3;
constexpr int HK_ = H_ * DK_;          // 128
constexpr int U_  = N_ - S_;           // 800 unselected
constexpr int L_  = U_ + 2;            // 802 sequence length
constexpr int M_  = B_ * L_;           // 25664 rows
constexpr int MT_ = ((M_ + 127) / 128); // 201 row-tiles
constexpr int MP_ = MT_ * 128;         // 25728 padded rows
constexpr int KVP = 20;                // padded K/V row stride (floats)
constexpr int AT_SMEM = (2 * L_ * KVP) * 4;   // 128,320 B dynamic smem
}

// ---------------- device scratch (no runtime allocation allowed) ----------------
__device__ float g_x   [MP_ * D_];
__device__ float g_o   [MP_ * D_];
__device__ float g_out1[MP_ * D_];
__device__ float g_q   [M_ * D_];   // [B,H,L,DK]
__device__ float g_k   [M_ * D_];
__device__ float g_v   [M_ * D_];
__device__ float g_h   [MP_ * FF_];
__device__ float g_logits[M_];
__device__ int   g_unsel[B_ * U_];

// ---------------- helpers ----------------
__device__ __forceinline__ void ld16(float* r, const float* p) {
    const float4* p4 = (const float4*)p;
    float4 x0 = p4[0], x1 = p4[1], x2 = p4[2], x3 = p4[3];
    r[0]=x0.x; r[1]=x0.y; r[2]=x0.z; r[3]=x0.w;
    r[4]=x1.x; r[5]=x1.y; r[6]=x1.z; r[7]=x1.w;
    r[8]=x2.x; r[9]=x2.y; r[10]=x2.z; r[11]=x2.w;
    r[12]=x3.x; r[13]=x3.y; r[14]=x3.z; r[15]=x3.w;
}

__device__ __forceinline__ unsigned f2tf32(float x) {
    unsigned r;
    asm("cvt.rna.tf32.f32 %0, %1;" : "=r"(r) : "f"(x));
    return r;
}

__device__ __forceinline__ void mma_tf32(float& d0, float& d1, float& d2, float& d3,
                                         unsigned a0, unsigned a1, unsigned a2, unsigned a3,
                                         unsigned b0, unsigned b1) {
    asm volatile(
        "mma.sync.aligned.m16n8k8.row.col.f32.tf32.tf32.f32 "
        "{%0,%1,%2,%3}, {%4,%5,%6,%7}, {%8,%9}, {%0,%1,%2,%3};"
        : "+f"(d0), "+f"(d1), "+f"(d2), "+f"(d3)
        : "r"(a0), "r"(a1), "r"(a2), "r"(a3), "r"(b0), "r"(b1));
}

// ---------------- 1) unselected-index compaction (ascending) ----------------
__global__ void __launch_bounds__(1024) unselect_k(const int* __restrict__ sel,
                                                   int* __restrict__ unsel) {
    __shared__ int keep[1024];
    __shared__ int scan[1024];
    const int b = blockIdx.x, t = threadIdx.x;
    keep[t] = (t < N_) ? 1 : 0;
    __syncthreads();
    if (t < S_) keep[sel[b * S_ + t]] = 0;
    __syncthreads();
    const int k = keep[t];
    scan[t] = k;
    __syncthreads();
    #pragma unroll
    for (int off = 1; off < 1024; off <<= 1) {
        int add = (t >= off) ? scan[t - off] : 0;
        __syncthreads();
        scan[t] += add;
        __syncthreads();
    }
    if (k && t < N_) unsel[b * U_ + scan[t] - 1] = t;
}

// ---------------- 2) build x0 = [ef, gathered rows, el] ----------------
__global__ void __launch_bounds__(128) build_x0_k(
    const float* __restrict__ data, const int* __restrict__ sel,
    const int* __restrict__ unsel,
    const float* __restrict__ Wf, const float* __restrict__ bf,
    const float* __restrict__ Wl, const float* __restrict__ bl,
    float* __restrict__ x)
{
    const int l = blockIdx.x, b = blockIdx.y, t = threadIdx.x;
    float* xr = x + ((size_t)b * L_ + l) * D_;
    if (l == 0 || l == L_ - 1) {
        __shared__ float vin[D_];
        const int node = (l == 0) ? sel[b * S_] : sel[b * S_ + S_ - 1];
        vin[t] = data[((size_t)b * N_ + node) * D_ + t];
        __syncthreads();
        const float* W  = (l == 0) ? Wf : Wl;
        const float* bb = (l == 0) ? bf : bl;
        float acc = bb[t];
        #pragma unroll 16
        for (int i = 0; i < D_; i++) acc = fmaf(vin[i], W[i * D_ + t], acc);
        xr[t] = acc;
    } else {
        const int node = unsel[b * U_ + (l - 1)];
        xr[t] = data[((size_t)b * N_ + node) * D_ + t];
    }
}

// ---------------- 3) tf32 tensor-core GEMM, 128x64x16 tiles ----------------
// 256 threads, 8 warps in 4(M) x 2(N); each warp: 32x32 via m16n8k8 (2x4 tiles)
// EPI 0: scatter to [B,H,L,DK] (QKV); EPI 1: +bias +res; EPI 2: relu(+bias)
template <int EPI>
__global__ void __launch_bounds__(256) gemm_tc(
    const float* __restrict__ A, const float* __restrict__ W,
    float* __restrict__ C, const float* __restrict__ bias,
    const float* __restrict__ res, int Mreal, int Nn, int K)
{
    __shared__ float As[128][20];
    __shared__ float Bs[16][72];
    const int bm = blockIdx.y * 128;
    const int bn = blockIdx.x * 64;
    const int tid = threadIdx.x;
    const int warp = tid >> 5, lane = tid & 31;
    const int wm = warp >> 1, wn = warp & 1;
    const int g = lane >> 2, tg = lane & 3;

    float acc[2][4][4];
    #pragma unroll
    for (int a = 0; a < 2; a++)
        #pragma unroll
        for (int b = 0; b < 4; b++)
            #pragma unroll
            for (int c = 0; c < 4; c++) acc[a][b][c] = 0.f;

    for (int k0 = 0; k0 < K; k0 += 16) {
        #pragma unroll
        for (int i = 0; i < 2; i++) {
            int e = tid + i * 256;
            int r = e >> 2, c = (e & 3) * 4;
            float4 v = *(const float4*)&A[(size_t)(bm + r) * K + k0 + c];
            *(float4*)&As[r][c] = v;
        }
        {
            int r = tid >> 4, c = (tid & 15) * 4;
            float4 v = *(const float4*)&W[(size_t)(k0 + r) * Nn + bn + c];
            *(float4*)&Bs[r][c] = v;
        }
        __syncthreads();
        #pragma unroll
        for (int ks = 0; ks < 2; ks++) {
            const int kb = ks * 8;
            unsigned af[2][4];
            #pragma unroll
            for (int mt = 0; mt < 2; mt++) {
                const int rb = wm * 32 + mt * 16;
                af[mt][0] = f2tf32(As[rb + g    ][kb + tg    ]);
                af[mt][1] = f2tf32(As[rb + g + 8][kb + tg    ]);
                af[mt][2] = f2tf32(As[rb + g    ][kb + tg + 4]);
                af[mt][3] = f2tf32(As[rb + g + 8][kb + tg + 4]);
            }
            unsigned bf_[4][2];
            #pragma unroll
            for (int nt = 0; nt < 4; nt++) {
                const int cb = wn * 32 + nt * 8;
                bf_[nt][0] = f2tf32(Bs[kb + tg    ][cb + g]);
                bf_[nt][1] = f2tf32(Bs[kb + tg + 4][cb + g]);
            }
            #pragma unroll
            for (int mt = 0; mt < 2; mt++)
                #pragma unroll
                for (int nt = 0; nt < 4; nt++)
                    mma_tf32(acc[mt][nt][0], acc[mt][nt][1], acc[mt][nt][2], acc[mt][nt][3],
                             af[mt][0], af[mt][1], af[mt][2], af[mt][3],
                             bf_[nt][0], bf_[nt][1]);
        }
        __syncthreads();
    }

    // epilogue
    #pragma unroll
    for (int mt = 0; mt < 2; mt++) {
        const int r_lo = bm + wm * 32 + mt * 16 + g;
        const int r_hi = r_lo + 8;
        #pragma unroll
        for (int nt = 0; nt < 4; nt++) {
            const int cn = bn + wn * 32 + nt * 8 + tg * 2;
            float d0 = acc[mt][nt][0], d1 = acc[mt][nt][1];
            float d2 = acc[mt][nt][2], d3 = acc[mt][nt][3];
            if (EPI == 0) {
                const int hh = cn >> 4, dk = cn & 15;
                if (r_lo < Mreal) {
                    const int bb = r_lo / L_, ll = r_lo - bb * L_;
                    *(float2*)&C[(((size_t)bb * H_ + hh) * L_ + ll) * DK_ + dk] = make_float2(d0, d1);
                }
                if (r_hi < Mreal) {
                    const int bb = r_hi / L_, ll = r_hi - bb * L_;
                    *(float2*)&C[(((size_t)bb * H_ + hh) * L_ + ll) * DK_ + dk] = make_float2(d2, d3);
                }
            } else if (EPI == 1) {
                const float b0 = bias[cn], b1 = bias[cn + 1];
                {
                    const float2 rv = *(const float2*)&res[(size_t)r_lo * Nn + cn];
                    *(float2*)&C[(size_t)r_lo * Nn + cn] = make_float2(d0 + b0 + rv.x, d1 + b1 + rv.y);
                }
                {
                    const float2 rv = *(const float2*)&res[(size_t)r_hi * Nn + cn];
                    *(float2*)&C[(size_t)r_hi * Nn + cn] = make_float2(d2 + b0 + rv.x, d3 + b1 + rv.y);
                }
            } else {
                const float b0 = bias[cn], b1 = bias[cn + 1];
                float v0 = d0 + b0, v1 = d1 + b1, v2 = d2 + b0, v3 = d3 + b1;
                *(float2*)&C[(size_t)r_lo * Nn + cn] = make_float2(v0 > 0.f ? v0 : 0.f, v1 > 0.f ? v1 : 0.f);
                *(float2*)&C[(size_t)r_hi * Nn + cn] = make_float2(v2 > 0.f ? v2 : 0.f, v3 > 0.f ? v3 : 0.f);
            }
        }
    }
}

// ---------------- 4) fused attention v2: two-pass, register accumulators ----------------
// one block per (b,h); 8 warps; each warp does 4 queries per pass.
__global__ void __launch_bounds__(256) attn_k(
    const float* __restrict__ q, const float* __restrict__ k,
    const float* __restrict__ v, float* __restrict__ o)
{
    extern __shared__ float sm[];
    float* Ks = sm;
    float* Vs = sm + L_ * KVP;
    const int bh = blockIdx.x;
    const int b = bh >> 3, h = bh & 7;
    const int tid = threadIdx.x, lane = tid & 31, warp = tid >> 5;

    const float* kp = k + (size_t)bh * L_ * DK_;
    const float* vp = v + (size_t)bh * L_ * DK_;
    for (int i = tid; i < L_ * DK_; i += 256) {
        int j = i >> 4, d = i & 15;
        Ks[j * KVP + d] = kp[i];
        Vs[j * KVP + d] = vp[i];
    }
    __syncthreads();

    const float* qb = q + (size_t)bh * L_ * DK_;

    for (int q0 = warp * 4; q0 < L_; q0 += 32) {
        float qr[4][16];
        #pragma unroll
        for (int qq = 0; qq < 4; qq++) {
            int qi = q0 + qq; if (qi > L_ - 1) qi = L_ - 1;
            ld16(qr[qq], qb + (size_t)qi * DK_);
        }

        // pass A: row max
        float m[4] = {-1e30f, -1e30f, -1e30f, -1e30f};
        for (int j = lane; j < L_; j += 32) {
            float kr[16];
            ld16(kr, Ks + j * KVP);
            #pragma unroll
            for (int qq = 0; qq < 4; qq++) {
                float s = 0.f;
                #pragma unroll
                for (int d = 0; d < 16; d++) s = fmaf(qr[qq][d], kr[d], s);
                m[qq] = fmaxf(m[qq], s * 0.25f);
            }
        }
        #pragma unroll
        for (int off = 16; off; off >>= 1)
            #pragma unroll
            for (int qq = 0; qq < 4; qq++)
                m[qq] = fmaxf(m[qq], __shfl_xor_sync(0xffffffffu, m[qq], off));

        // pass B: exp + accumulate into registers
        float l[4] = {0.f, 0.f, 0.f, 0.f};
        float pv[4][16];
        #pragma unroll
        for (int qq = 0; qq < 4; qq++)
            #pragma unroll
            for (int d = 0; d < 16; d++) pv[qq][d] = 0.f;

        for (int j = lane; j < L_; j += 32) {
            float kr[16], vr[16];
            ld16(kr, Ks + j * KVP);
            ld16(vr, Vs + j * KVP);
            #pragma unroll
            for (int qq = 0; qq < 4; qq++) {
                float s = 0.f;
                #pragma unroll
                for (int d = 0; d < 16; d++) s = fmaf(qr[qq][d], kr[d], s);
                float p = __expf(fmaf(s, 0.25f, -m[qq]));
                l[qq] += p;
                #pragma unroll
                for (int d = 0; d < 16; d++) pv[qq][d] = fmaf(p, vr[d], pv[qq][d]);
            }
        }
        // cross-lane reduction
        #pragma unroll
        for (int off = 16; off; off >>= 1) {
            #pragma unroll
            for (int qq = 0; qq < 4; qq++) {
                l[qq] += __shfl_xor_sync(0xffffffffu, l[qq], off);
                #pragma unroll
                for (int d = 0; d < 16; d++)
                    pv[qq][d] += __shfl_xor_sync(0xffffffffu, pv[qq][d], off);
            }
        }
        #pragma unroll
        for (int qq = 0; qq < 4; qq++) {
            if (lane == qq && q0 + qq < L_) {
                const float inv = 1.f / l[qq];
                float4* dst = (float4*)&o[((size_t)b * L_ + q0 + qq) * HK_ + h * DK_];
                #pragma unroll
                for (int c = 0; c < 4; c++)
                    dst[c] = make_float4(pv[qq][4*c] * inv, pv[qq][4*c+1] * inv,
                                         pv[qq][4*c+2] * inv, pv[qq][4*c+3] * inv);
            }
        }
    }
}

// ---------------- 5) logits GEMV: warp per row ----------------
__global__ void __launch_bounds__(256) logits_k(
    const float* __restrict__ x, const float* __restrict__ Wfin,
    const float* __restrict__ bfin, float* __restrict__ logits)
{
    const int row  = (int)((blockIdx.x * (size_t)blockDim.x + threadIdx.x) >> 5);
    const int lane = threadIdx.x & 31;
    if (row >= M_) return;
    float4 xv = ((const float4*)(x + (size_t)row * D_))[lane];
    float4 wv = ((const float4*)Wfin)[lane];
    float s = xv.x * wv.x + xv.y * wv.y + xv.z * wv.z + xv.w * wv.w;
    #pragma unroll
    for (int off = 16; off; off >>= 1) s += __shfl_xor_sync(0xffffffffu, s, off);
    if (lane == 0) logits[row] = s + bfin[0];
}

// ---------------- 6) bias add + softmax + scatter, one block per batch ----------------
__global__ void __launch_bounds__(1024) finalize_k(
    const float* __restrict__ logits, const float* __restrict__ ab,
    const int* __restrict__ sel, const int* __restrict__ unsel,
    float* __restrict__ out)
{
    __shared__ float red[32];
    const int b = blockIdx.x, t = threadIdx.x;
    const int lane = t & 31, warp = t >> 5;
    const int last = sel[b * S_ + S_ - 1];
    const float* abrow = ab + ((size_t)b * N_ + last) * N_;

    int u = 0;
    float val = -3.0e38f;
    const bool active = (t < U_);
    if (active) {
        u = unsel[b * U_ + t];
        val = logits[b * L_ + 1 + t] + abrow[u];
    }
    float m = val;
    #pragma unroll
    for (int off = 16; off; off >>= 1) m = fmaxf(m, __shfl_xor_sync(0xffffffffu, m, off));
    if (lane == 0) red[warp] = m;
    __syncthreads();
    if (warp == 0) {
        float mm = red[lane];
        #pragma unroll
        for (int off = 16; off; off >>= 1) mm = fmaxf(mm, __shfl_xor_sync(0xffffffffu, mm, off));
        red[lane] = mm;
    }
    __syncthreads();
    m = red[0];
    __syncthreads();
    const float e = active ? __expf(val - m) : 0.f;
    float s = e;
    #pragma unroll
    for (int off = 16; off; off >>= 1) s += __shfl_xor_sync(0xffffffffu, s, off);
    if (lane == 0) red[warp] = s;
    __syncthreads();
    if (warp == 0) {
        float ss = red[lane];
        #pragma unroll
        for (int off = 16; off; off >>= 1) ss += __shfl_xor_sync(0xffffffffu, ss, off);
        red[lane] = ss;
    }
    __syncthreads();
    const float inv = 1.f / red[0];

    for (int i = t; i < N_; i += 1024) out[(size_t)b * N_ + i] = -2.0f;
    __syncthreads();
    if (active) {
        float p = e * inv;
        if (p <= 1e-5f) p += 1e-7f;
        out[(size_t)b * N_ + u] = p;
    }
}

// ---------------- launch ----------------
extern "C" void kernel_launch(void* const* d_in, const int* in_sizes, int n_in,
                              void* d_out, int out_size) {
    (void)in_sizes; (void)n_in; (void)out_size;
    const float* data   = (const float*)d_in[0];
    const float* ab     = (const float*)d_in[1];
    const float* Wfirst = (const float*)d_in[2];
    const float* bfirst = (const float*)d_in[3];
    const float* Wlast  = (const float*)d_in[4];
    const float* blast  = (const float*)d_in[5];
    const float* Wq     = (const float*)d_in[6];
    const float* Wk     = (const float*)d_in[7];
    const float* Wv     = (const float*)d_in[8];
    const float* Wo     = (const float*)d_in[9];
    const float* bo     = (const float*)d_in[10];
    const float* W1     = (const float*)d_in[11];
    const float* b1     = (const float*)d_in[12];
    const float* W2     = (const float*)d_in[13];
    const float* b2     = (const float*)d_in[14];
    const float* Wfin   = (const float*)d_in[15];
    const float* bfin   = (const float*)d_in[16];
    const int*   sel    = (const int*)d_in[17];
    float* out = (float*)d_out;

    void *px, *po, *pout1, *pq, *pk, *pv, *ph, *plog, *pun;
    cudaGetSymbolAddress(&px,    g_x);
    cudaGetSymbolAddress(&po,    g_o);
    cudaGetSymbolAddress(&pout1, g_out1);
    cudaGetSymbolAddress(&pq,    g_q);
    cudaGetSymbolAddress(&pk,    g_k);
    cudaGetSymbolAddress(&pv,    g_v);
    cudaGetSymbolAddress(&ph,    g_h);
    cudaGetSymbolAddress(&plog,  g_logits);
    cudaGetSymbolAddress(&pun,   g_unsel);
    float* x    = (float*)px;
    float* o    = (float*)po;
    float* out1 = (float*)pout1;
    float* q    = (float*)pq;
    float* k    = (float*)pk;
    float* v    = (float*)pv;
    float* hbuf = (float*)ph;
    float* logits = (float*)plog;
    int*   unsel  = (int*)pun;

    cudaFuncSetAttribute(attn_k, cudaFuncAttributeMaxDynamicSharedMemorySize, AT_SMEM);

    unselect_k<<<B_, 1024>>>(sel, unsel);
    build_x0_k<<<dim3(L_, B_), D_>>>(data, sel, unsel, Wfirst, bfirst, Wlast, blast, x);

    const dim3 g128(HK_ / 64, MT_);   // (2, 201)
    const dim3 g512(FF_ / 64, MT_);   // (8, 201)
    for (int il = 0; il < NL_; il++) {
        const float* wq = Wq + (size_t)il * D_ * HK_;
        const float* wk = Wk + (size_t)il * D_ * HK_;
        const float* wv = Wv + (size_t)il * D_ * HK_;
        const float* wo = Wo + (size_t)il * HK_ * D_;
        const float* bol = bo + (size_t)il * D_;
        const float* w1 = W1 + (size_t)il * D_ * FF_;
        const float* b1l = b1 + (size_t)il * FF_;
        const float* w2 = W2 + (size_t)il * FF_ * D_;
        const float* b2l = b2 + (size_t)il * D_;

        gemm_tc<0><<<g128, 256>>>(x, wq, q, nullptr, nullptr, M_, HK_, D_);
        gemm_tc<0><<<g128, 256>>>(x, wk, k, nullptr, nullptr, M_, HK_, D_);
        gemm_tc<0><<<g128, 256>>>(x, wv, v, nullptr, nullptr, M_, HK_, D_);
        attn_k<<<B_ * H_, 256, AT_SMEM>>>(q, k, v, o);
        gemm_tc<1><<<g128, 256>>>(o, wo, out1, bol, x, M_, D_, HK_);
        gemm_tc<2><<<g512, 256>>>(out1, w1, hbuf, b1l, nullptr, M_, FF_, D_);
        gemm_tc<1><<<g128, 256>>>(hbuf, w2, x, b2l, out1, M_, D_, FF_);
    }

    logits_k<<<(M_ * 32 + 255) / 256, 256>>>(x, Wfin, bfin, logits);
    finalize_k<<<B_, 1024>>>(logits, ab, sel, unsel, out);
}

// round 3
// speedup vs baseline: 4.2210x; 2.3424x over previous
#include <cuda_runtime.h>

// ---------------- problem constants ----------------
namespace {
constexpr int B_  = 32;
constexpr int N_  = 1000;
constexpr int S_  = 200;
constexpr int D_  = 128;
constexpr int H_  = 8;
constexpr int DK_ = 16;
constexpr int FF_ = 512;
constexpr int NL_ = 3;
constexpr int HK_ = H_ * DK_;          // 128
constexpr int U_  = N_ - S_;           // 800 unselected
constexpr int L_  = U_ + 2;            // 802 sequence length
constexpr int M_  = B_ * L_;           // 25664 rows
constexpr int MT_ = ((M_ + 127) / 128); // 201 row-tiles
constexpr int MP_ = MT_ * 128;         // padded rows
constexpr int QT_ = 128;               // attention query tile
constexpr int KT_ = 64;                // attention key tile
constexpr int QTILES_ = (L_ + QT_ - 1) / QT_;  // 7
}

// ---------------- device scratch (no runtime allocation allowed) ----------------
__device__ float g_x   [MP_ * D_];
__device__ float g_o   [MP_ * D_];
__device__ float g_out1[MP_ * D_];
__device__ float g_q   [M_ * D_];   // [B,H,L,DK]
__device__ float g_k   [M_ * D_];
__device__ float g_v   [M_ * D_];
__device__ float g_h   [MP_ * FF_];
__device__ float g_logits[M_];
__device__ int   g_unsel[B_ * U_];

// ---------------- helpers ----------------
__device__ __forceinline__ unsigned f2tf32(float x) {
    unsigned r;
    asm("cvt.rna.tf32.f32 %0, %1;" : "=r"(r) : "f"(x));
    return r;
}

__device__ __forceinline__ void mma_tf32(float& d0, float& d1, float& d2, float& d3,
                                         unsigned a0, unsigned a1, unsigned a2, unsigned a3,
                                         unsigned b0, unsigned b1) {
    asm volatile(
        "mma.sync.aligned.m16n8k8.row.col.f32.tf32.tf32.f32 "
        "{%0,%1,%2,%3}, {%4,%5,%6,%7}, {%8,%9}, {%0,%1,%2,%3};"
        : "+f"(d0), "+f"(d1), "+f"(d2), "+f"(d3)
        : "r"(a0), "r"(a1), "r"(a2), "r"(a3), "r"(b0), "r"(b1));
}

// ---------------- 1) unselected-index compaction (ascending) ----------------
__global__ void __launch_bounds__(1024) unselect_k(const int* __restrict__ sel,
                                                   int* __restrict__ unsel) {
    __shared__ int keep[1024];
    __shared__ int scan[1024];
    const int b = blockIdx.x, t = threadIdx.x;
    keep[t] = (t < N_) ? 1 : 0;
    __syncthreads();
    if (t < S_) keep[sel[b * S_ + t]] = 0;
    __syncthreads();
    const int k = keep[t];
    scan[t] = k;
    __syncthreads();
    #pragma unroll
    for (int off = 1; off < 1024; off <<= 1) {
        int add = (t >= off) ? scan[t - off] : 0;
        __syncthreads();
        scan[t] += add;
        __syncthreads();
    }
    if (k && t < N_) unsel[b * U_ + scan[t] - 1] = t;
}

// ---------------- 2) build x0 = [ef, gathered rows, el] ----------------
__global__ void __launch_bounds__(128) build_x0_k(
    const float* __restrict__ data, const int* __restrict__ sel,
    const int* __restrict__ unsel,
    const float* __restrict__ Wf, const float* __restrict__ bf,
    const float* __restrict__ Wl, const float* __restrict__ bl,
    float* __restrict__ x)
{
    const int l = blockIdx.x, b = blockIdx.y, t = threadIdx.x;
    float* xr = x + ((size_t)b * L_ + l) * D_;
    if (l == 0 || l == L_ - 1) {
        __shared__ float vin[D_];
        const int node = (l == 0) ? sel[b * S_] : sel[b * S_ + S_ - 1];
        vin[t] = data[((size_t)b * N_ + node) * D_ + t];
        __syncthreads();
        const float* W  = (l == 0) ? Wf : Wl;
        const float* bb = (l == 0) ? bf : bl;
        float acc = bb[t];
        #pragma unroll 16
        for (int i = 0; i < D_; i++) acc = fmaf(vin[i], W[i * D_ + t], acc);
        xr[t] = acc;
    } else {
        const int node = unsel[b * U_ + (l - 1)];
        xr[t] = data[((size_t)b * N_ + node) * D_ + t];
    }
}

// ---------------- 3) tf32 tensor-core GEMM, 128x64x16 tiles ----------------
template <int EPI>
__global__ void __launch_bounds__(256) gemm_tc(
    const float* __restrict__ A, const float* __restrict__ W,
    float* __restrict__ C, const float* __restrict__ bias,
    const float* __restrict__ res, int Mreal, int Nn, int K)
{
    __shared__ float As[128][20];
    __shared__ float Bs[16][72];
    const int bm = blockIdx.y * 128;
    const int bn = blockIdx.x * 64;
    const int tid = threadIdx.x;
    const int warp = tid >> 5, lane = tid & 31;
    const int wm = warp >> 1, wn = warp & 1;
    const int g = lane >> 2, tg = lane & 3;

    float acc[2][4][4];
    #pragma unroll
    for (int a = 0; a < 2; a++)
        #pragma unroll
        for (int b = 0; b < 4; b++)
            #pragma unroll
            for (int c = 0; c < 4; c++) acc[a][b][c] = 0.f;

    for (int k0 = 0; k0 < K; k0 += 16) {
        #pragma unroll
        for (int i = 0; i < 2; i++) {
            int e = tid + i * 256;
            int r = e >> 2, c = (e & 3) * 4;
            float4 v = *(const float4*)&A[(size_t)(bm + r) * K + k0 + c];
            *(float4*)&As[r][c] = v;
        }
        {
            int r = tid >> 4, c = (tid & 15) * 4;
            float4 v = *(const float4*)&W[(size_t)(k0 + r) * Nn + bn + c];
            *(float4*)&Bs[r][c] = v;
        }
        __syncthreads();
        #pragma unroll
        for (int ks = 0; ks < 2; ks++) {
            const int kb = ks * 8;
            unsigned af[2][4];
            #pragma unroll
            for (int mt = 0; mt < 2; mt++) {
                const int rb = wm * 32 + mt * 16;
                af[mt][0] = f2tf32(As[rb + g    ][kb + tg    ]);
                af[mt][1] = f2tf32(As[rb + g + 8][kb + tg    ]);
                af[mt][2] = f2tf32(As[rb + g    ][kb + tg + 4]);
                af[mt][3] = f2tf32(As[rb + g + 8][kb + tg + 4]);
            }
            unsigned bf_[4][2];
            #pragma unroll
            for (int nt = 0; nt < 4; nt++) {
                const int cb = wn * 32 + nt * 8;
                bf_[nt][0] = f2tf32(Bs[kb + tg    ][cb + g]);
                bf_[nt][1] = f2tf32(Bs[kb + tg + 4][cb + g]);
            }
            #pragma unroll
            for (int mt = 0; mt < 2; mt++)
                #pragma unroll
                for (int nt = 0; nt < 4; nt++)
                    mma_tf32(acc[mt][nt][0], acc[mt][nt][1], acc[mt][nt][2], acc[mt][nt][3],
                             af[mt][0], af[mt][1], af[mt][2], af[mt][3],
                             bf_[nt][0], bf_[nt][1]);
        }
        __syncthreads();
    }

    #pragma unroll
    for (int mt = 0; mt < 2; mt++) {
        const int r_lo = bm + wm * 32 + mt * 16 + g;
        const int r_hi = r_lo + 8;
        #pragma unroll
        for (int nt = 0; nt < 4; nt++) {
            const int cn = bn + wn * 32 + nt * 8 + tg * 2;
            float d0 = acc[mt][nt][0], d1 = acc[mt][nt][1];
            float d2 = acc[mt][nt][2], d3 = acc[mt][nt][3];
            if (EPI == 0) {
                const int hh = cn >> 4, dk = cn & 15;
                if (r_lo < Mreal) {
                    const int bb = r_lo / L_, ll = r_lo - bb * L_;
                    *(float2*)&C[(((size_t)bb * H_ + hh) * L_ + ll) * DK_ + dk] = make_float2(d0, d1);
                }
                if (r_hi < Mreal) {
                    const int bb = r_hi / L_, ll = r_hi - bb * L_;
                    *(float2*)&C[(((size_t)bb * H_ + hh) * L_ + ll) * DK_ + dk] = make_float2(d2, d3);
                }
            } else if (EPI == 1) {
                const float b0 = bias[cn], b1 = bias[cn + 1];
                {
                    const float2 rv = *(const float2*)&res[(size_t)r_lo * Nn + cn];
                    *(float2*)&C[(size_t)r_lo * Nn + cn] = make_float2(d0 + b0 + rv.x, d1 + b1 + rv.y);
                }
                {
                    const float2 rv = *(const float2*)&res[(size_t)r_hi * Nn + cn];
                    *(float2*)&C[(size_t)r_hi * Nn + cn] = make_float2(d2 + b0 + rv.x, d3 + b1 + rv.y);
                }
            } else {
                const float b0 = bias[cn], b1 = bias[cn + 1];
                float v0 = d0 + b0, v1 = d1 + b1, v2 = d2 + b0, v3 = d3 + b1;
                *(float2*)&C[(size_t)r_lo * Nn + cn] = make_float2(v0 > 0.f ? v0 : 0.f, v1 > 0.f ? v1 : 0.f);
                *(float2*)&C[(size_t)r_hi * Nn + cn] = make_float2(v2 > 0.f ? v2 : 0.f, v3 > 0.f ? v3 : 0.f);
            }
        }
    }
}

// ---------------- 3b) fused QKV GEMM: one launch, selects W/output by tile ----------------
__global__ void __launch_bounds__(256) gemm_qkv(
    const float* __restrict__ A,
    const float* __restrict__ Wq, const float* __restrict__ Wk, const float* __restrict__ Wv,
    float* __restrict__ Cq, float* __restrict__ Ck, float* __restrict__ Cv,
    int Mreal)
{
    __shared__ float As[128][20];
    __shared__ float Bs[16][72];
    const int which = blockIdx.x >> 1;
    const float* W = (which == 0) ? Wq : (which == 1) ? Wk : Wv;
    float* C = (which == 0) ? Cq : (which == 1) ? Ck : Cv;
    const int bm = blockIdx.y * 128;
    const int bn = (blockIdx.x & 1) * 64;
    const int tid = threadIdx.x;
    const int warp = tid >> 5, lane = tid & 31;
    const int wm = warp >> 1, wn = warp & 1;
    const int g = lane >> 2, tg = lane & 3;

    float acc[2][4][4];
    #pragma unroll
    for (int a = 0; a < 2; a++)
        #pragma unroll
        for (int b = 0; b < 4; b++)
            #pragma unroll
            for (int c = 0; c < 4; c++) acc[a][b][c] = 0.f;

    for (int k0 = 0; k0 < D_; k0 += 16) {
        #pragma unroll
        for (int i = 0; i < 2; i++) {
            int e = tid + i * 256;
            int r = e >> 2, c = (e & 3) * 4;
            *(float4*)&As[r][c] = *(const float4*)&A[(size_t)(bm + r) * D_ + k0 + c];
        }
        {
            int r = tid >> 4, c = (tid & 15) * 4;
            *(float4*)&Bs[r][c] = *(const float4*)&W[(size_t)(k0 + r) * HK_ + bn + c];
        }
        __syncthreads();
        #pragma unroll
        for (int ks = 0; ks < 2; ks++) {
            const int kb = ks * 8;
            unsigned af[2][4];
            #pragma unroll
            for (int mt = 0; mt < 2; mt++) {
                const int rb = wm * 32 + mt * 16;
                af[mt][0] = f2tf32(As[rb + g    ][kb + tg    ]);
                af[mt][1] = f2tf32(As[rb + g + 8][kb + tg    ]);
                af[mt][2] = f2tf32(As[rb + g    ][kb + tg + 4]);
                af[mt][3] = f2tf32(As[rb + g + 8][kb + tg + 4]);
            }
            unsigned bf_[4][2];
            #pragma unroll
            for (int nt = 0; nt < 4; nt++) {
                const int cb = wn * 32 + nt * 8;
                bf_[nt][0] = f2tf32(Bs[kb + tg    ][cb + g]);
                bf_[nt][1] = f2tf32(Bs[kb + tg + 4][cb + g]);
            }
            #pragma unroll
            for (int mt = 0; mt < 2; mt++)
                #pragma unroll
                for (int nt = 0; nt < 4; nt++)
                    mma_tf32(acc[mt][nt][0], acc[mt][nt][1], acc[mt][nt][2], acc[mt][nt][3],
                             af[mt][0], af[mt][1], af[mt][2], af[mt][3],
                             bf_[nt][0], bf_[nt][1]);
        }
        __syncthreads();
    }

    #pragma unroll
    for (int mt = 0; mt < 2; mt++) {
        const int r_lo = bm + wm * 32 + mt * 16 + g;
        const int r_hi = r_lo + 8;
        #pragma unroll
        for (int nt = 0; nt < 4; nt++) {
            const int cn = bn + wn * 32 + nt * 8 + tg * 2;
            const int hh = cn >> 4, dk = cn & 15;
            if (r_lo < Mreal) {
                const int bb = r_lo / L_, ll = r_lo - bb * L_;
                *(float2*)&C[(((size_t)bb * H_ + hh) * L_ + ll) * DK_ + dk] =
                    make_float2(acc[mt][nt][0], acc[mt][nt][1]);
            }
            if (r_hi < Mreal) {
                const int bb = r_hi / L_, ll = r_hi - bb * L_;
                *(float2*)&C[(((size_t)bb * H_ + hh) * L_ + ll) * DK_ + dk] =
                    make_float2(acc[mt][nt][2], acc[mt][nt][3]);
            }
        }
    }
}

// ---------------- 4) tensor-core flash attention ----------------
// grid: (B*H, QTILES). 8 warps; warp owns 16 query rows. Online softmax.
__global__ void __launch_bounds__(256) attn_tc(
    const float* __restrict__ q, const float* __restrict__ k,
    const float* __restrict__ v, float* __restrict__ o)
{
    __shared__ float Ks[KT_][20];        // K tile, row-major [j][d]
    __shared__ float Vt[DK_][KT_ + 4];   // V tile transposed [d][j]
    __shared__ float Ps[8][16][KT_ + 4]; // per-warp P tile

    const int bh = blockIdx.x;
    const int b = bh >> 3, h = bh & 7;
    const int qt = blockIdx.y;
    const int tid = threadIdx.x, lane = tid & 31, warp = tid >> 5;
    const int g = lane >> 2, tg = lane & 3;

    const float* qp = q + (size_t)bh * L_ * DK_;
    const float* kp = k + (size_t)bh * L_ * DK_;
    const float* vp = v + (size_t)bh * L_ * DK_;

    // Q fragment (scaled by 1/sqrt(DK)=0.25, exact power of two)
    const int r0 = qt * QT_ + warp * 16 + g;
    const int r1 = r0 + 8;
    const int r0c = r0 < L_ ? r0 : L_ - 1;
    const int r1c = r1 < L_ ? r1 : L_ - 1;
    unsigned qat[2][4];
    #pragma unroll
    for (int ks = 0; ks < 2; ks++) {
        qat[ks][0] = f2tf32(0.25f * qp[(size_t)r0c * DK_ + ks * 8 + tg]);
        qat[ks][1] = f2tf32(0.25f * qp[(size_t)r1c * DK_ + ks * 8 + tg]);
        qat[ks][2] = f2tf32(0.25f * qp[(size_t)r0c * DK_ + ks * 8 + tg + 4]);
        qat[ks][3] = f2tf32(0.25f * qp[(size_t)r1c * DK_ + ks * 8 + tg + 4]);
    }

    float m0 = -1e30f, m1 = -1e30f;
    float l0 = 0.f, l1 = 0.f;
    float oc[2][4];
    #pragma unroll
    for (int nt = 0; nt < 2; nt++)
        #pragma unroll
        for (int c = 0; c < 4; c++) oc[nt][c] = 0.f;

    const int jl = tid >> 2;            // 0..63
    const int d4 = (tid & 3) * 4;       // 0,4,8,12

    for (int j0 = 0; j0 < L_; j0 += KT_) {
        __syncthreads();  // previous iteration's PV reads of Vt done
        // stage K and V tiles
        const int j = j0 + jl;
        float4 kv = (j < L_) ? *(const float4*)&kp[(size_t)j * DK_ + d4]
                             : make_float4(0.f, 0.f, 0.f, 0.f);
        *(float4*)&Ks[jl][d4] = kv;
        float4 vv = (j < L_) ? *(const float4*)&vp[(size_t)j * DK_ + d4]
                             : make_float4(0.f, 0.f, 0.f, 0.f);
        Vt[d4 + 0][jl] = vv.x;
        Vt[d4 + 1][jl] = vv.y;
        Vt[d4 + 2][jl] = vv.z;
        Vt[d4 + 3][jl] = vv.w;
        __syncthreads();

        // S = Q·K^T (already scaled)
        float sc[8][4];
        #pragma unroll
        for (int nt = 0; nt < 8; nt++)
            #pragma unroll
            for (int c = 0; c < 4; c++) sc[nt][c] = 0.f;
        #pragma unroll
        for (int ks = 0; ks < 2; ks++) {
            #pragma unroll
            for (int nt = 0; nt < 8; nt++) {
                const unsigned b0 = f2tf32(Ks[nt * 8 + g][ks * 8 + tg]);
                const unsigned b1 = f2tf32(Ks[nt * 8 + g][ks * 8 + tg + 4]);
                mma_tf32(sc[nt][0], sc[nt][1], sc[nt][2], sc[nt][3],
                         qat[ks][0], qat[ks][1], qat[ks][2], qat[ks][3], b0, b1);
            }
        }
        // mask out-of-range keys (only possible in last tile)
        if (j0 + KT_ > L_) {
            #pragma unroll
            for (int nt = 0; nt < 8; nt++) {
                const int c = j0 + nt * 8 + 2 * tg;
                if (c     >= L_) { sc[nt][0] = -1e30f; sc[nt][2] = -1e30f; }
                if (c + 1 >= L_) { sc[nt][1] = -1e30f; sc[nt][3] = -1e30f; }
            }
        }
        // new row max
        float nm0 = m0, nm1 = m1;
        #pragma unroll
        for (int nt = 0; nt < 8; nt++) {
            nm0 = fmaxf(nm0, fmaxf(sc[nt][0], sc[nt][1]));
            nm1 = fmaxf(nm1, fmaxf(sc[nt][2], sc[nt][3]));
        }
        nm0 = fmaxf(nm0, __shfl_xor_sync(0xffffffffu, nm0, 1));
        nm0 = fmaxf(nm0, __shfl_xor_sync(0xffffffffu, nm0, 2));
        nm1 = fmaxf(nm1, __shfl_xor_sync(0xffffffffu, nm1, 1));
        nm1 = fmaxf(nm1, __shfl_xor_sync(0xffffffffu, nm1, 2));
        // rescale
        const float f0 = __expf(m0 - nm0);
        const float f1 = __expf(m1 - nm1);
        m0 = nm0; m1 = nm1;
        l0 *= f0; l1 *= f1;
        #pragma unroll
        for (int nt = 0; nt < 2; nt++) {
            oc[nt][0] *= f0; oc[nt][1] *= f0;
            oc[nt][2] *= f1; oc[nt][3] *= f1;
        }
        // P = exp(S - m), row sums, store P to per-warp smem
        float rs0 = 0.f, rs1 = 0.f;
        #pragma unroll
        for (int nt = 0; nt < 8; nt++) {
            const float p0 = __expf(sc[nt][0] - m0);
            const float p1 = __expf(sc[nt][1] - m0);
            const float p2 = __expf(sc[nt][2] - m1);
            const float p3 = __expf(sc[nt][3] - m1);
            rs0 += p0 + p1;
            rs1 += p2 + p3;
            *(float2*)&Ps[warp][g    ][nt * 8 + 2 * tg] = make_float2(p0, p1);
            *(float2*)&Ps[warp][g + 8][nt * 8 + 2 * tg] = make_float2(p2, p3);
        }
        rs0 += __shfl_xor_sync(0xffffffffu, rs0, 1);
        rs0 += __shfl_xor_sync(0xffffffffu, rs0, 2);
        rs1 += __shfl_xor_sync(0xffffffffu, rs1, 1);
        rs1 += __shfl_xor_sync(0xffffffffu, rs1, 2);
        l0 += rs0; l1 += rs1;
        __syncwarp();
        // O += P·V
        #pragma unroll
        for (int ks = 0; ks < 8; ks++) {
            const unsigned a0 = f2tf32(Ps[warp][g    ][ks * 8 + tg    ]);
            const unsigned a1 = f2tf32(Ps[warp][g + 8][ks * 8 + tg    ]);
            const unsigned a2 = f2tf32(Ps[warp][g    ][ks * 8 + tg + 4]);
            const unsigned a3 = f2tf32(Ps[warp][g + 8][ks * 8 + tg + 4]);
            #pragma unroll
            for (int nt = 0; nt < 2; nt++) {
                const unsigned b0 = f2tf32(Vt[nt * 8 + g][ks * 8 + tg    ]);
                const unsigned b1 = f2tf32(Vt[nt * 8 + g][ks * 8 + tg + 4]);
                mma_tf32(oc[nt][0], oc[nt][1], oc[nt][2], oc[nt][3],
                         a0, a1, a2, a3, b0, b1);
            }
        }
        __syncwarp();  // PV LDS of Ps done before next-iter STS
    }

    // write O / l
    const float inv0 = 1.f / l0;
    const float inv1 = 1.f / l1;
    #pragma unroll
    for (int nt = 0; nt < 2; nt++) {
        const int dn = h * DK_ + nt * 8 + 2 * tg;
        if (r0 < L_)
            *(float2*)&o[((size_t)b * L_ + r0) * HK_ + dn] =
                make_float2(oc[nt][0] * inv0, oc[nt][1] * inv0);
        if (r1 < L_)
            *(float2*)&o[((size_t)b * L_ + r1) * HK_ + dn] =
                make_float2(oc[nt][2] * inv1, oc[nt][3] * inv1);
    }
}

// ---------------- 5) logits GEMV: warp per row ----------------
__global__ void __launch_bounds__(256) logits_k(
    const float* __restrict__ x, const float* __restrict__ Wfin,
    const float* __restrict__ bfin, float* __restrict__ logits)
{
    const int row  = (int)((blockIdx.x * (size_t)blockDim.x + threadIdx.x) >> 5);
    const int lane = threadIdx.x & 31;
    if (row >= M_) return;
    float4 xv = ((const float4*)(x + (size_t)row * D_))[lane];
    float4 wv = ((const float4*)Wfin)[lane];
    float s = xv.x * wv.x + xv.y * wv.y + xv.z * wv.z + xv.w * wv.w;
    #pragma unroll
    for (int off = 16; off; off >>= 1) s += __shfl_xor_sync(0xffffffffu, s, off);
    if (lane == 0) logits[row] = s + bfin[0];
}

// ---------------- 6) bias add + softmax + scatter ----------------
__global__ void __launch_bounds__(1024) finalize_k(
    const float* __restrict__ logits, const float* __restrict__ ab,
    const int* __restrict__ sel, const int* __restrict__ unsel,
    float* __restrict__ out)
{
    __shared__ float red[32];
    const int b = blockIdx.x, t = threadIdx.x;
    const int lane = t & 31, warp = t >> 5;
    const int last = sel[b * S_ + S_ - 1];
    const float* abrow = ab + ((size_t)b * N_ + last) * N_;

    int u = 0;
    float val = -3.0e38f;
    const bool active = (t < U_);
    if (active) {
        u = unsel[b * U_ + t];
        val = logits[b * L_ + 1 + t] + abrow[u];
    }
    float m = val;
    #pragma unroll
    for (int off = 16; off; off >>= 1) m = fmaxf(m, __shfl_xor_sync(0xffffffffu, m, off));
    if (lane == 0) red[warp] = m;
    __syncthreads();
    if (warp == 0) {
        float mm = red[lane];
        #pragma unroll
        for (int off = 16; off; off >>= 1) mm = fmaxf(mm, __shfl_xor_sync(0xffffffffu, mm, off));
        red[lane] = mm;
    }
    __syncthreads();
    m = red[0];
    __syncthreads();
    const float e = active ? __expf(val - m) : 0.f;
    float s = e;
    #pragma unroll
    for (int off = 16; off; off >>= 1) s += __shfl_xor_sync(0xffffffffu, s, off);
    if (lane == 0) red[warp] = s;
    __syncthreads();
    if (warp == 0) {
        float ss = red[lane];
        #pragma unroll
        for (int off = 16; off; off >>= 1) ss += __shfl_xor_sync(0xffffffffu, ss, off);
        red[lane] = ss;
    }
    __syncthreads();
    const float inv = 1.f / red[0];

    for (int i = t; i < N_; i += 1024) out[(size_t)b * N_ + i] = -2.0f;
    __syncthreads();
    if (active) {
        float p = e * inv;
        if (p <= 1e-5f) p += 1e-7f;
        out[(size_t)b * N_ + u] = p;
    }
}

// ---------------- launch ----------------
extern "C" void kernel_launch(void* const* d_in, const int* in_sizes, int n_in,
                              void* d_out, int out_size) {
    (void)in_sizes; (void)n_in; (void)out_size;
    const float* data   = (const float*)d_in[0];
    const float* ab     = (const float*)d_in[1];
    const float* Wfirst = (const float*)d_in[2];
    const float* bfirst = (const float*)d_in[3];
    const float* Wlast  = (const float*)d_in[4];
    const float* blast  = (const float*)d_in[5];
    const float* Wq     = (const float*)d_in[6];
    const float* Wk     = (const float*)d_in[7];
    const float* Wv     = (const float*)d_in[8];
    const float* Wo     = (const float*)d_in[9];
    const float* bo     = (const float*)d_in[10];
    const float* W1     = (const float*)d_in[11];
    const float* b1     = (const float*)d_in[12];
    const float* W2     = (const float*)d_in[13];
    const float* b2     = (const float*)d_in[14];
    const float* Wfin   = (const float*)d_in[15];
    const float* bfin   = (const float*)d_in[16];
    const int*   sel    = (const int*)d_in[17];
    float* out = (float*)d_out;

    void *px, *po, *pout1, *pq, *pk, *pv, *ph, *plog, *pun;
    cudaGetSymbolAddress(&px,    g_x);
    cudaGetSymbolAddress(&po,    g_o);
    cudaGetSymbolAddress(&pout1, g_out1);
    cudaGetSymbolAddress(&pq,    g_q);
    cudaGetSymbolAddress(&pk,    g_k);
    cudaGetSymbolAddress(&pv,    g_v);
    cudaGetSymbolAddress(&ph,    g_h);
    cudaGetSymbolAddress(&plog,  g_logits);
    cudaGetSymbolAddress(&pun,   g_unsel);
    float* x    = (float*)px;
    float* o    = (float*)po;
    float* out1 = (float*)pout1;
    float* q    = (float*)pq;
    float* k    = (float*)pk;
    float* v    = (float*)pv;
    float* hbuf = (float*)ph;
    float* logits = (float*)plog;
    int*   unsel  = (int*)pun;

    unselect_k<<<B_, 1024>>>(sel, unsel);
    build_x0_k<<<dim3(L_, B_), D_>>>(data, sel, unsel, Wfirst, bfirst, Wlast, blast, x);

    const dim3 g128(HK_ / 64, MT_);   // (2, 201)
    const dim3 g512(FF_ / 64, MT_);   // (8, 201)
    const dim3 gqkv(6, MT_);          // 3 outputs x 2 N-tiles
    const dim3 gattn(B_ * H_, QTILES_);
    for (int il = 0; il < NL_; il++) {
        const float* wq = Wq + (size_t)il * D_ * HK_;
        const float* wk = Wk + (size_t)il * D_ * HK_;
        const float* wv = Wv + (size_t)il * D_ * HK_;
        const float* wo = Wo + (size_t)il * HK_ * D_;
        const float* bol = bo + (size_t)il * D_;
        const float* w1 = W1 + (size_t)il * D_ * FF_;
        const float* b1l = b1 + (size_t)il * FF_;
        const float* w2 = W2 + (size_t)il * FF_ * D_;
        const float* b2l = b2 + (size_t)il * D_;

        gemm_qkv<<<gqkv, 256>>>(x, wq, wk, wv, q, k, v, M_);
        attn_tc<<<gattn, 256>>>(q, k, v, o);
        gemm_tc<1><<<g128, 256>>>(o, wo, out1, bol, x, M_, D_, HK_);
        gemm_tc<2><<<g512, 256>>>(out1, w1, hbuf, b1l, nullptr, M_, FF_, D_);
        gemm_tc<1><<<g128, 256>>>(hbuf, w2, x, b2l, out1, M_, D_, FF_);
    }

    logits_k<<<(M_ * 32 + 255) / 256, 256>>>(x, Wfin, bfin, logits);
    finalize_k<<<B_, 1024>>>(logits, ab, sel, unsel, out);
}

// round 4
// speedup vs baseline: 4.5945x; 1.0885x over previous
#include <cuda_runtime.h>

// ---------------- problem constants ----------------
namespace {
constexpr int B_  = 32;
constexpr int N_  = 1000;
constexpr int S_  = 200;
constexpr int D_  = 128;
constexpr int H_  = 8;
constexpr int DK_ = 16;
constexpr int FF_ = 512;
constexpr int NL_ = 3;
constexpr int HK_ = H_ * DK_;          // 128
constexpr int U_  = N_ - S_;           // 800 unselected
constexpr int L_  = U_ + 2;            // 802 sequence length
constexpr int M_  = B_ * L_;           // 25664 rows
constexpr int MT_ = ((M_ + 127) / 128); // 201 row-tiles
constexpr int MP_ = MT_ * 128;         // padded rows
constexpr int QT_ = 128;               // attention query tile
constexpr int KT_ = 64;                // attention key tile
constexpr int QTILES_ = (L_ + QT_ - 1) / QT_;  // 7
constexpr float LOG2E = 1.44269504088896f;
}

// ---------------- device scratch (no runtime allocation allowed) ----------------
__device__ float g_x   [MP_ * D_];
__device__ float g_o   [MP_ * D_];
__device__ float g_out1[MP_ * D_];
__device__ float g_q   [M_ * D_];   // [B,H,L,DK]
__device__ float g_k   [M_ * D_];
__device__ float g_v   [M_ * D_];
__device__ float g_h   [MP_ * FF_];
__device__ float g_logits[M_];
__device__ int   g_unsel[B_ * U_];

// ---------------- helpers ----------------
__device__ __forceinline__ unsigned f2tf32(float x) {
    unsigned r;
    asm("cvt.rna.tf32.f32 %0, %1;" : "=r"(r) : "f"(x));
    return r;
}

__device__ __forceinline__ float ex2(float x) {
    float y;
    asm("ex2.approx.f32 %0, %1;" : "=f"(y) : "f"(x));
    return y;
}

__device__ __forceinline__ void mma_tf32(float& d0, float& d1, float& d2, float& d3,
                                         unsigned a0, unsigned a1, unsigned a2, unsigned a3,
                                         unsigned b0, unsigned b1) {
    asm volatile(
        "mma.sync.aligned.m16n8k8.row.col.f32.tf32.tf32.f32 "
        "{%0,%1,%2,%3}, {%4,%5,%6,%7}, {%8,%9}, {%0,%1,%2,%3};"
        : "+f"(d0), "+f"(d1), "+f"(d2), "+f"(d3)
        : "r"(a0), "r"(a1), "r"(a2), "r"(a3), "r"(b0), "r"(b1));
}

__device__ __forceinline__ void cp16(void* smem, const void* gmem) {
    unsigned s = (unsigned)__cvta_generic_to_shared(smem);
    asm volatile("cp.async.ca.shared.global [%0], [%1], 16;" :: "r"(s), "l"(gmem));
}
__device__ __forceinline__ void cp_commit() { asm volatile("cp.async.commit_group;"); }
__device__ __forceinline__ void cp_wait0()  { asm volatile("cp.async.wait_group 0;"); }

// ---------------- 1) unselected-index compaction (ascending) ----------------
__global__ void __launch_bounds__(1024) unselect_k(const int* __restrict__ sel,
                                                   int* __restrict__ unsel) {
    __shared__ int keep[1024];
    __shared__ int scan[1024];
    const int b = blockIdx.x, t = threadIdx.x;
    keep[t] = (t < N_) ? 1 : 0;
    __syncthreads();
    if (t < S_) keep[sel[b * S_ + t]] = 0;
    __syncthreads();
    const int k = keep[t];
    scan[t] = k;
    __syncthreads();
    #pragma unroll
    for (int off = 1; off < 1024; off <<= 1) {
        int add = (t >= off) ? scan[t - off] : 0;
        __syncthreads();
        scan[t] += add;
        __syncthreads();
    }
    if (k && t < N_) unsel[b * U_ + scan[t] - 1] = t;
}

// ---------------- 2) build x0 = [ef, gathered rows, el] ----------------
__global__ void __launch_bounds__(128) build_x0_k(
    const float* __restrict__ data, const int* __restrict__ sel,
    const int* __restrict__ unsel,
    const float* __restrict__ Wf, const float* __restrict__ bf,
    const float* __restrict__ Wl, const float* __restrict__ bl,
    float* __restrict__ x)
{
    const int l = blockIdx.x, b = blockIdx.y, t = threadIdx.x;
    float* xr = x + ((size_t)b * L_ + l) * D_;
    if (l == 0 || l == L_ - 1) {
        __shared__ float vin[D_];
        const int node = (l == 0) ? sel[b * S_] : sel[b * S_ + S_ - 1];
        vin[t] = data[((size_t)b * N_ + node) * D_ + t];
        __syncthreads();
        const float* W  = (l == 0) ? Wf : Wl;
        const float* bb = (l == 0) ? bf : bl;
        float acc = bb[t];
        #pragma unroll 16
        for (int i = 0; i < D_; i++) acc = fmaf(vin[i], W[i * D_ + t], acc);
        xr[t] = acc;
    } else {
        const int node = unsel[b * U_ + (l - 1)];
        xr[t] = data[((size_t)b * N_ + node) * D_ + t];
    }
}

// ---------------- 3) tf32 GEMM, 128x64x16 tiles, cp.async double-buffered ----------------
template <int EPI>
__global__ void __launch_bounds__(256) gemm_tc(
    const float* __restrict__ A, const float* __restrict__ W,
    float* __restrict__ C, const float* __restrict__ bias,
    const float* __restrict__ res, int Mreal, int Nn, int K)
{
    __shared__ float As[2][128][20];
    __shared__ float Bs[2][16][72];
    const int bm = blockIdx.y * 128;
    const int bn = blockIdx.x * 64;
    const int tid = threadIdx.x;
    const int warp = tid >> 5, lane = tid & 31;
    const int wm = warp >> 1, wn = warp & 1;
    const int g = lane >> 2, tg = lane & 3;

    const int ar = tid >> 2, ac = (tid & 3) * 4;
    const int br = tid >> 4, bc = (tid & 15) * 4;

    float acc[2][4][4];
    #pragma unroll
    for (int a = 0; a < 2; a++)
        #pragma unroll
        for (int b = 0; b < 4; b++)
            #pragma unroll
            for (int c = 0; c < 4; c++) acc[a][b][c] = 0.f;

    // prefetch tile 0
    cp16(&As[0][ar][ac],       &A[(size_t)(bm + ar) * K + ac]);
    cp16(&As[0][ar + 64][ac],  &A[(size_t)(bm + ar + 64) * K + ac]);
    cp16(&Bs[0][br][bc],       &W[(size_t)br * Nn + bn + bc]);
    cp_commit();

    const int KT = K >> 4;
    for (int kt = 0; kt < KT; kt++) {
        const int buf = kt & 1;
        cp_wait0();
        __syncthreads();
        if (kt + 1 < KT) {
            const int k0 = (kt + 1) * 16;
            const int nb = buf ^ 1;
            cp16(&As[nb][ar][ac],      &A[(size_t)(bm + ar) * K + k0 + ac]);
            cp16(&As[nb][ar + 64][ac], &A[(size_t)(bm + ar + 64) * K + k0 + ac]);
            cp16(&Bs[nb][br][bc],      &W[(size_t)(k0 + br) * Nn + bn + bc]);
            cp_commit();
        }
        #pragma unroll
        for (int ks = 0; ks < 2; ks++) {
            const int kb = ks * 8;
            unsigned af[2][4];
            #pragma unroll
            for (int mt = 0; mt < 2; mt++) {
                const int rb = wm * 32 + mt * 16;
                af[mt][0] = f2tf32(As[buf][rb + g    ][kb + tg    ]);
                af[mt][1] = f2tf32(As[buf][rb + g + 8][kb + tg    ]);
                af[mt][2] = f2tf32(As[buf][rb + g    ][kb + tg + 4]);
                af[mt][3] = f2tf32(As[buf][rb + g + 8][kb + tg + 4]);
            }
            unsigned bf_[4][2];
            #pragma unroll
            for (int nt = 0; nt < 4; nt++) {
                const int cb = wn * 32 + nt * 8;
                bf_[nt][0] = f2tf32(Bs[buf][kb + tg    ][cb + g]);
                bf_[nt][1] = f2tf32(Bs[buf][kb + tg + 4][cb + g]);
            }
            #pragma unroll
            for (int mt = 0; mt < 2; mt++)
                #pragma unroll
                for (int nt = 0; nt < 4; nt++)
                    mma_tf32(acc[mt][nt][0], acc[mt][nt][1], acc[mt][nt][2], acc[mt][nt][3],
                             af[mt][0], af[mt][1], af[mt][2], af[mt][3],
                             bf_[nt][0], bf_[nt][1]);
        }
    }

    #pragma unroll
    for (int mt = 0; mt < 2; mt++) {
        const int r_lo = bm + wm * 32 + mt * 16 + g;
        const int r_hi = r_lo + 8;
        #pragma unroll
        for (int nt = 0; nt < 4; nt++) {
            const int cn = bn + wn * 32 + nt * 8 + tg * 2;
            float d0 = acc[mt][nt][0], d1 = acc[mt][nt][1];
            float d2 = acc[mt][nt][2], d3 = acc[mt][nt][3];
            if (EPI == 0) {
                const int hh = cn >> 4, dk = cn & 15;
                if (r_lo < Mreal) {
                    const int bb = r_lo / L_, ll = r_lo - bb * L_;
                    *(float2*)&C[(((size_t)bb * H_ + hh) * L_ + ll) * DK_ + dk] = make_float2(d0, d1);
                }
                if (r_hi < Mreal) {
                    const int bb = r_hi / L_, ll = r_hi - bb * L_;
                    *(float2*)&C[(((size_t)bb * H_ + hh) * L_ + ll) * DK_ + dk] = make_float2(d2, d3);
                }
            } else if (EPI == 1) {
                const float b0 = bias[cn], b1 = bias[cn + 1];
                {
                    const float2 rv = *(const float2*)&res[(size_t)r_lo * Nn + cn];
                    *(float2*)&C[(size_t)r_lo * Nn + cn] = make_float2(d0 + b0 + rv.x, d1 + b1 + rv.y);
                }
                {
                    const float2 rv = *(const float2*)&res[(size_t)r_hi * Nn + cn];
                    *(float2*)&C[(size_t)r_hi * Nn + cn] = make_float2(d2 + b0 + rv.x, d3 + b1 + rv.y);
                }
            } else {
                const float b0 = bias[cn], b1 = bias[cn + 1];
                float v0 = d0 + b0, v1 = d1 + b1, v2 = d2 + b0, v3 = d3 + b1;
                *(float2*)&C[(size_t)r_lo * Nn + cn] = make_float2(v0 > 0.f ? v0 : 0.f, v1 > 0.f ? v1 : 0.f);
                *(float2*)&C[(size_t)r_hi * Nn + cn] = make_float2(v2 > 0.f ? v2 : 0.f, v3 > 0.f ? v3 : 0.f);
            }
        }
    }
}

// ---------------- 3b) fused QKV GEMM, cp.async double-buffered ----------------
__global__ void __launch_bounds__(256) gemm_qkv(
    const float* __restrict__ A,
    const float* __restrict__ Wq, const float* __restrict__ Wk, const float* __restrict__ Wv,
    float* __restrict__ Cq, float* __restrict__ Ck, float* __restrict__ Cv,
    int Mreal)
{
    __shared__ float As[2][128][20];
    __shared__ float Bs[2][16][72];
    const int which = blockIdx.x >> 1;
    const float* W = (which == 0) ? Wq : (which == 1) ? Wk : Wv;
    float* C = (which == 0) ? Cq : (which == 1) ? Ck : Cv;
    const int bm = blockIdx.y * 128;
    const int bn = (blockIdx.x & 1) * 64;
    const int tid = threadIdx.x;
    const int warp = tid >> 5, lane = tid & 31;
    const int wm = warp >> 1, wn = warp & 1;
    const int g = lane >> 2, tg = lane & 3;

    const int ar = tid >> 2, ac = (tid & 3) * 4;
    const int br = tid >> 4, bc = (tid & 15) * 4;

    float acc[2][4][4];
    #pragma unroll
    for (int a = 0; a < 2; a++)
        #pragma unroll
        for (int b = 0; b < 4; b++)
            #pragma unroll
            for (int c = 0; c < 4; c++) acc[a][b][c] = 0.f;

    cp16(&As[0][ar][ac],      &A[(size_t)(bm + ar) * D_ + ac]);
    cp16(&As[0][ar + 64][ac], &A[(size_t)(bm + ar + 64) * D_ + ac]);
    cp16(&Bs[0][br][bc],      &W[(size_t)br * HK_ + bn + bc]);
    cp_commit();

    #pragma unroll 1
    for (int kt = 0; kt < 8; kt++) {
        const int buf = kt & 1;
        cp_wait0();
        __syncthreads();
        if (kt + 1 < 8) {
            const int k0 = (kt + 1) * 16;
            const int nb = buf ^ 1;
            cp16(&As[nb][ar][ac],      &A[(size_t)(bm + ar) * D_ + k0 + ac]);
            cp16(&As[nb][ar + 64][ac], &A[(size_t)(bm + ar + 64) * D_ + k0 + ac]);
            cp16(&Bs[nb][br][bc],      &W[(size_t)(k0 + br) * HK_ + bn + bc]);
            cp_commit();
        }
        #pragma unroll
        for (int ks = 0; ks < 2; ks++) {
            const int kb = ks * 8;
            unsigned af[2][4];
            #pragma unroll
            for (int mt = 0; mt < 2; mt++) {
                const int rb = wm * 32 + mt * 16;
                af[mt][0] = f2tf32(As[buf][rb + g    ][kb + tg    ]);
                af[mt][1] = f2tf32(As[buf][rb + g + 8][kb + tg    ]);
                af[mt][2] = f2tf32(As[buf][rb + g    ][kb + tg + 4]);
                af[mt][3] = f2tf32(As[buf][rb + g + 8][kb + tg + 4]);
            }
            unsigned bf_[4][2];
            #pragma unroll
            for (int nt = 0; nt < 4; nt++) {
                const int cb = wn * 32 + nt * 8;
                bf_[nt][0] = f2tf32(Bs[buf][kb + tg    ][cb + g]);
                bf_[nt][1] = f2tf32(Bs[buf][kb + tg + 4][cb + g]);
            }
            #pragma unroll
            for (int mt = 0; mt < 2; mt++)
                #pragma unroll
                for (int nt = 0; nt < 4; nt++)
                    mma_tf32(acc[mt][nt][0], acc[mt][nt][1], acc[mt][nt][2], acc[mt][nt][3],
                             af[mt][0], af[mt][1], af[mt][2], af[mt][3],
                             bf_[nt][0], bf_[nt][1]);
        }
    }

    #pragma unroll
    for (int mt = 0; mt < 2; mt++) {
        const int r_lo = bm + wm * 32 + mt * 16 + g;
        const int r_hi = r_lo + 8;
        #pragma unroll
        for (int nt = 0; nt < 4; nt++) {
            const int cn = bn + wn * 32 + nt * 8 + tg * 2;
            const int hh = cn >> 4, dk = cn & 15;
            if (r_lo < Mreal) {
                const int bb = r_lo / L_, ll = r_lo - bb * L_;
                *(float2*)&C[(((size_t)bb * H_ + hh) * L_ + ll) * DK_ + dk] =
                    make_float2(acc[mt][nt][0], acc[mt][nt][1]);
            }
            if (r_hi < Mreal) {
                const int bb = r_hi / L_, ll = r_hi - bb * L_;
                *(float2*)&C[(((size_t)bb * H_ + hh) * L_ + ll) * DK_ + dk] =
                    make_float2(acc[mt][nt][2], acc[mt][nt][3]);
            }
        }
    }
}

// ---------------- 4) tensor-core flash attention (tf32-staged, exp2 domain) ----------------
__global__ void __launch_bounds__(256) attn_tc(
    const float* __restrict__ q, const float* __restrict__ k,
    const float* __restrict__ v, float* __restrict__ o)
{
    __shared__ unsigned Ks[KT_][20];        // K tile tf32 bits [j][d]
    __shared__ unsigned Vt[DK_][KT_ + 4];   // V tile tf32 bits, transposed [d][j]
    __shared__ unsigned Ps[8][16][72];      // per-warp P tile tf32 bits

    const int bh = blockIdx.x;
    const int b = bh >> 3, h = bh & 7;
    const int qt = blockIdx.y;
    const int tid = threadIdx.x, lane = tid & 31, warp = tid >> 5;
    const int g = lane >> 2, tg = lane & 3;

    const float* qp = q + (size_t)bh * L_ * DK_;
    const float* kp = k + (size_t)bh * L_ * DK_;
    const float* vp = v + (size_t)bh * L_ * DK_;

    // Q fragment scaled by (1/sqrt(DK)) * log2(e)  -> scores in log2 domain
    const float qs = 0.25f * LOG2E;
    const int r0 = qt * QT_ + warp * 16 + g;
    const int r1 = r0 + 8;
    const int r0c = r0 < L_ ? r0 : L_ - 1;
    const int r1c = r1 < L_ ? r1 : L_ - 1;
    unsigned qat[2][4];
    #pragma unroll
    for (int ks = 0; ks < 2; ks++) {
        qat[ks][0] = f2tf32(qs * qp[(size_t)r0c * DK_ + ks * 8 + tg]);
        qat[ks][1] = f2tf32(qs * qp[(size_t)r1c * DK_ + ks * 8 + tg]);
        qat[ks][2] = f2tf32(qs * qp[(size_t)r0c * DK_ + ks * 8 + tg + 4]);
        qat[ks][3] = f2tf32(qs * qp[(size_t)r1c * DK_ + ks * 8 + tg + 4]);
    }

    float m0 = -1e30f, m1 = -1e30f;
    float l0 = 0.f, l1 = 0.f;
    float oc[2][4];
    #pragma unroll
    for (int nt = 0; nt < 2; nt++)
        #pragma unroll
        for (int c = 0; c < 4; c++) oc[nt][c] = 0.f;

    const int jl = tid >> 2;            // 0..63
    const int d4 = (tid & 3) * 4;       // 0,4,8,12

    auto tile = [&](int j0, bool mask_tail) {
        __syncthreads();
        const int j = j0 + jl;
        float4 kv = (j < L_) ? *(const float4*)&kp[(size_t)j * DK_ + d4]
                             : make_float4(0.f, 0.f, 0.f, 0.f);
        Ks[jl][d4 + 0] = f2tf32(kv.x);
        Ks[jl][d4 + 1] = f2tf32(kv.y);
        Ks[jl][d4 + 2] = f2tf32(kv.z);
        Ks[jl][d4 + 3] = f2tf32(kv.w);
        float4 vv = (j < L_) ? *(const float4*)&vp[(size_t)j * DK_ + d4]
                             : make_float4(0.f, 0.f, 0.f, 0.f);
        Vt[d4 + 0][jl] = f2tf32(vv.x);
        Vt[d4 + 1][jl] = f2tf32(vv.y);
        Vt[d4 + 2][jl] = f2tf32(vv.z);
        Vt[d4 + 3][jl] = f2tf32(vv.w);
        __syncthreads();

        // S = Q·K^T  (log2 domain)
        float sc[8][4];
        #pragma unroll
        for (int nt = 0; nt < 8; nt++)
            #pragma unroll
            for (int c = 0; c < 4; c++) sc[nt][c] = 0.f;
        #pragma unroll
        for (int ks = 0; ks < 2; ks++) {
            #pragma unroll
            for (int nt = 0; nt < 8; nt++) {
                const unsigned b0 = Ks[nt * 8 + g][ks * 8 + tg];
                const unsigned b1 = Ks[nt * 8 + g][ks * 8 + tg + 4];
                mma_tf32(sc[nt][0], sc[nt][1], sc[nt][2], sc[nt][3],
                         qat[ks][0], qat[ks][1], qat[ks][2], qat[ks][3], b0, b1);
            }
        }
        if (mask_tail) {
            #pragma unroll
            for (int nt = 0; nt < 8; nt++) {
                const int c = j0 + nt * 8 + 2 * tg;
                if (c     >= L_) { sc[nt][0] = -1e30f; sc[nt][2] = -1e30f; }
                if (c + 1 >= L_) { sc[nt][1] = -1e30f; sc[nt][3] = -1e30f; }
            }
        }
        // new row max
        float nm0 = m0, nm1 = m1;
        #pragma unroll
        for (int nt = 0; nt < 8; nt++) {
            nm0 = fmaxf(nm0, fmaxf(sc[nt][0], sc[nt][1]));
            nm1 = fmaxf(nm1, fmaxf(sc[nt][2], sc[nt][3]));
        }
        nm0 = fmaxf(nm0, __shfl_xor_sync(0xffffffffu, nm0, 1));
        nm0 = fmaxf(nm0, __shfl_xor_sync(0xffffffffu, nm0, 2));
        nm1 = fmaxf(nm1, __shfl_xor_sync(0xffffffffu, nm1, 1));
        nm1 = fmaxf(nm1, __shfl_xor_sync(0xffffffffu, nm1, 2));
        const float f0 = ex2(m0 - nm0);
        const float f1 = ex2(m1 - nm1);
        m0 = nm0; m1 = nm1;
        l0 *= f0; l1 *= f1;
        #pragma unroll
        for (int nt = 0; nt < 2; nt++) {
            oc[nt][0] *= f0; oc[nt][1] *= f0;
            oc[nt][2] *= f1; oc[nt][3] *= f1;
        }
        // P = 2^(S - m), row sums, store P (tf32 bits) to per-warp smem
        float rs0 = 0.f, rs1 = 0.f;
        #pragma unroll
        for (int nt = 0; nt < 8; nt++) {
            const float p0 = ex2(sc[nt][0] - m0);
            const float p1 = ex2(sc[nt][1] - m0);
            const float p2 = ex2(sc[nt][2] - m1);
            const float p3 = ex2(sc[nt][3] - m1);
            rs0 += p0 + p1;
            rs1 += p2 + p3;
            uint2 w0; w0.x = f2tf32(p0); w0.y = f2tf32(p1);
            uint2 w1; w1.x = f2tf32(p2); w1.y = f2tf32(p3);
            *(uint2*)&Ps[warp][g    ][nt * 8 + 2 * tg] = w0;
            *(uint2*)&Ps[warp][g + 8][nt * 8 + 2 * tg] = w1;
        }
        rs0 += __shfl_xor_sync(0xffffffffu, rs0, 1);
        rs0 += __shfl_xor_sync(0xffffffffu, rs0, 2);
        rs1 += __shfl_xor_sync(0xffffffffu, rs1, 1);
        rs1 += __shfl_xor_sync(0xffffffffu, rs1, 2);
        l0 += rs0; l1 += rs1;
        __syncwarp();
        // O += P·V
        #pragma unroll
        for (int ks = 0; ks < 8; ks++) {
            const unsigned a0 = Ps[warp][g    ][ks * 8 + tg    ];
            const unsigned a1 = Ps[warp][g + 8][ks * 8 + tg    ];
            const unsigned a2 = Ps[warp][g    ][ks * 8 + tg + 4];
            const unsigned a3 = Ps[warp][g + 8][ks * 8 + tg + 4];
            #pragma unroll
            for (int nt = 0; nt < 2; nt++) {
                const unsigned b0 = Vt[nt * 8 + g][ks * 8 + tg    ];
                const unsigned b1 = Vt[nt * 8 + g][ks * 8 + tg + 4];
                mma_tf32(oc[nt][0], oc[nt][1], oc[nt][2], oc[nt][3],
                         a0, a1, a2, a3, b0, b1);
            }
        }
        __syncwarp();
    };

    int j0 = 0;
    #pragma unroll 1
    for (; j0 + KT_ <= L_; j0 += KT_) tile(j0, false);
    if (j0 < L_) tile(j0, true);

    const float inv0 = 1.f / l0;
    const float inv1 = 1.f / l1;
    #pragma unroll
    for (int nt = 0; nt < 2; nt++) {
        const int dn = h * DK_ + nt * 8 + 2 * tg;
        if (r0 < L_)
            *(float2*)&o[((size_t)b * L_ + r0) * HK_ + dn] =
                make_float2(oc[nt][0] * inv0, oc[nt][1] * inv0);
        if (r1 < L_)
            *(float2*)&o[((size_t)b * L_ + r1) * HK_ + dn] =
                make_float2(oc[nt][2] * inv1, oc[nt][3] * inv1);
    }
}

// ---------------- 5) logits GEMV: warp per row ----------------
__global__ void __launch_bounds__(256) logits_k(
    const float* __restrict__ x, const float* __restrict__ Wfin,
    const float* __restrict__ bfin, float* __restrict__ logits)
{
    const int row  = (int)((blockIdx.x * (size_t)blockDim.x + threadIdx.x) >> 5);
    const int lane = threadIdx.x & 31;
    if (row >= M_) return;
    float4 xv = ((const float4*)(x + (size_t)row * D_))[lane];
    float4 wv = ((const float4*)Wfin)[lane];
    float s = xv.x * wv.x + xv.y * wv.y + xv.z * wv.z + xv.w * wv.w;
    #pragma unroll
    for (int off = 16; off; off >>= 1) s += __shfl_xor_sync(0xffffffffu, s, off);
    if (lane == 0) logits[row] = s + bfin[0];
}

// ---------------- 6) bias add + softmax + scatter ----------------
__global__ void __launch_bounds__(1024) finalize_k(
    const float* __restrict__ logits, const float* __restrict__ ab,
    const int* __restrict__ sel, const int* __restrict__ unsel,
    float* __restrict__ out)
{
    __shared__ float red[32];
    const int b = blockIdx.x, t = threadIdx.x;
    const int lane = t & 31, warp = t >> 5;
    const int last = sel[b * S_ + S_ - 1];
    const float* abrow = ab + ((size_t)b * N_ + last) * N_;

    int u = 0;
    float val = -3.0e38f;
    const bool active = (t < U_);
    if (active) {
        u = unsel[b * U_ + t];
        val = logits[b * L_ + 1 + t] + abrow[u];
    }
    float m = val;
    #pragma unroll
    for (int off = 16; off; off >>= 1) m = fmaxf(m, __shfl_xor_sync(0xffffffffu, m, off));
    if (lane == 0) red[warp] = m;
    __syncthreads();
    if (warp == 0) {
        float mm = red[lane];
        #pragma unroll
        for (int off = 16; off; off >>= 1) mm = fmaxf(mm, __shfl_xor_sync(0xffffffffu, mm, off));
        red[lane] = mm;
    }
    __syncthreads();
    m = red[0];
    __syncthreads();
    const float e = active ? __expf(val - m) : 0.f;
    float s = e;
    #pragma unroll
    for (int off = 16; off; off >>= 1) s += __shfl_xor_sync(0xffffffffu, s, off);
    if (lane == 0) red[warp] = s;
    __syncthreads();
    if (warp == 0) {
        float ss = red[lane];
        #pragma unroll
        for (int off = 16; off; off >>= 1) ss += __shfl_xor_sync(0xffffffffu, ss, off);
        red[lane] = ss;
    }
    __syncthreads();
    const float inv = 1.f / red[0];

    for (int i = t; i < N_; i += 1024) out[(size_t)b * N_ + i] = -2.0f;
    __syncthreads();
    if (active) {
        float p = e * inv;
        if (p <= 1e-5f) p += 1e-7f;
        out[(size_t)b * N_ + u] = p;
    }
}

// ---------------- launch ----------------
extern "C" void kernel_launch(void* const* d_in, const int* in_sizes, int n_in,
                              void* d_out, int out_size) {
    (void)in_sizes; (void)n_in; (void)out_size;
    const float* data   = (const float*)d_in[0];
    const float* ab     = (const float*)d_in[1];
    const float* Wfirst = (const float*)d_in[2];
    const float* bfirst = (const float*)d_in[3];
    const float* Wlast  = (const float*)d_in[4];
    const float* blast  = (const float*)d_in[5];
    const float* Wq     = (const float*)d_in[6];
    const float* Wk     = (const float*)d_in[7];
    const float* Wv     = (const float*)d_in[8];
    const float* Wo     = (const float*)d_in[9];
    const float* bo     = (const float*)d_in[10];
    const float* W1     = (const float*)d_in[11];
    const float* b1     = (const float*)d_in[12];
    const float* W2     = (const float*)d_in[13];
    const float* b2     = (const float*)d_in[14];
    const float* Wfin   = (const float*)d_in[15];
    const float* bfin   = (const float*)d_in[16];
    const int*   sel    = (const int*)d_in[17];
    float* out = (float*)d_out;

    void *px, *po, *pout1, *pq, *pk, *pv, *ph, *plog, *pun;
    cudaGetSymbolAddress(&px,    g_x);
    cudaGetSymbolAddress(&po,    g_o);
    cudaGetSymbolAddress(&pout1, g_out1);
    cudaGetSymbolAddress(&pq,    g_q);
    cudaGetSymbolAddress(&pk,    g_k);
    cudaGetSymbolAddress(&pv,    g_v);
    cudaGetSymbolAddress(&ph,    g_h);
    cudaGetSymbolAddress(&plog,  g_logits);
    cudaGetSymbolAddress(&pun,   g_unsel);
    float* x    = (float*)px;
    float* o    = (float*)po;
    float* out1 = (float*)pout1;
    float* q    = (float*)pq;
    float* k    = (float*)pk;
    float* v    = (float*)pv;
    float* hbuf = (float*)ph;
    float* logits = (float*)plog;
    int*   unsel  = (int*)pun;

    unselect_k<<<B_, 1024>>>(sel, unsel);
    build_x0_k<<<dim3(L_, B_), D_>>>(data, sel, unsel, Wfirst, bfirst, Wlast, blast, x);

    const dim3 g128(HK_ / 64, MT_);   // (2, 201)
    const dim3 g512(FF_ / 64, MT_);   // (8, 201)
    const dim3 gqkv(6, MT_);          // 3 outputs x 2 N-tiles
    const dim3 gattn(B_ * H_, QTILES_);
    for (int il = 0; il < NL_; il++) {
        const float* wq = Wq + (size_t)il * D_ * HK_;
        const float* wk = Wk + (size_t)il * D_ * HK_;
        const float* wv = Wv + (size_t)il * D_ * HK_;
        const float* wo = Wo + (size_t)il * HK_ * D_;
        const float* bol = bo + (size_t)il * D_;
        const float* w1 = W1 + (size_t)il * D_ * FF_;
        const float* b1l = b1 + (size_t)il * FF_;
        const float* w2 = W2 + (size_t)il * FF_ * D_;
        const float* b2l = b2 + (size_t)il * D_;

        gemm_qkv<<<gqkv, 256>>>(x, wq, wk, wv, q, k, v, M_);
        attn_tc<<<gattn, 256>>>(q, k, v, o);
        gemm_tc<1><<<g128, 256>>>(o, wo, out1, bol, x, M_, D_, HK_);
        gemm_tc<2><<<g512, 256>>>(out1, w1, hbuf, b1l, nullptr, M_, FF_, D_);
        gemm_tc<1><<<g128, 256>>>(hbuf, w2, x, b2l, out1, M_, D_, FF_);
    }

    logits_k<<<(M_ * 32 + 255) / 256, 256>>>(x, Wfin, bfin, logits);
    finalize_k<<<B_, 1024>>>(logits, ab, sel, unsel, out);
}

// round 6
// speedup vs baseline: 7.3063x; 1.5902x over previous
#include <cuda_runtime.h>
#include <cuda_bf16.h>

// ---------------- problem constants ----------------
namespace {
constexpr int B_  = 32;
constexpr int N_  = 1000;
constexpr int S_  = 200;
constexpr int D_  = 128;
constexpr int H_  = 8;
constexpr int DK_ = 16;
constexpr int FF_ = 512;
constexpr int NL_ = 3;
constexpr int HK_ = H_ * DK_;          // 128
constexpr int U_  = N_ - S_;           // 800 unselected
constexpr int L_  = U_ + 2;            // 802 sequence length
constexpr int M_  = B_ * L_;           // 25664 rows
constexpr int MT_ = ((M_ + 127) / 128); // 201 row-tiles
constexpr int MP_ = MT_ * 128;         // padded rows
constexpr int QT_ = 128;               // attention query tile
constexpr int KT_ = 64;                // attention key tile
constexpr int QTILES_  = (L_ + QT_ - 1) / QT_;  // 7
constexpr int NKTILES_ = (L_ + KT_ - 1) / KT_;  // 13
constexpr float LOG2E = 1.44269504088896f;
constexpr float QS_ = 0.25f * LOG2E;   // folded into Q at QKV epilogue
constexpr int SQW_ = NL_ * D_ * HK_;   // 49152 (per q/k/v/o weight set)
constexpr int SFW_ = NL_ * D_ * FF_;   // 196608
constexpr int WB_TOTAL_ = 4 * SQW_ + 2 * SFW_;  // 589824
}

// ---------------- device scratch (no runtime allocation allowed) ----------------
__device__ float g_x    [MP_ * D_];
__device__ float g_out1 [MP_ * D_];
__device__ float g_logits[M_];
__device__ int   g_unsel[B_ * U_];
__device__ __nv_bfloat16 g_xb   [MP_ * D_];
__device__ __nv_bfloat16 g_out1b[MP_ * D_];
__device__ __nv_bfloat16 g_hb   [MP_ * FF_];
__device__ __nv_bfloat16 g_qb   [M_ * D_];   // [B,H,L,DK]
__device__ __nv_bfloat16 g_kb   [M_ * D_];
__device__ __nv_bfloat16 g_vb   [M_ * D_];
__device__ __nv_bfloat16 g_ob   [MP_ * D_];
__device__ __nv_bfloat16 g_wb   [WB_TOTAL_];

// ---------------- helpers ----------------
__device__ __forceinline__ float ex2(float x) {
    float y;
    asm("ex2.approx.f32 %0, %1;" : "=f"(y) : "f"(x));
    return y;
}

// pack (lo, hi) floats -> bf16x2 (lo in low 16 bits)
__device__ __forceinline__ unsigned pk(float lo, float hi) {
    unsigned r;
    asm("cvt.rn.bf16x2.f32 %0, %1, %2;" : "=r"(r) : "f"(hi), "f"(lo));
    return r;
}

__device__ __forceinline__ void ldsm4(unsigned& r0, unsigned& r1, unsigned& r2, unsigned& r3,
                                      const void* p) {
    unsigned a = (unsigned)__cvta_generic_to_shared(p);
    asm volatile("ldmatrix.sync.aligned.m8n8.x4.shared.b16 {%0,%1,%2,%3}, [%4];"
                 : "=r"(r0), "=r"(r1), "=r"(r2), "=r"(r3) : "r"(a));
}
__device__ __forceinline__ void ldsm4t(unsigned& r0, unsigned& r1, unsigned& r2, unsigned& r3,
                                       const void* p) {
    unsigned a = (unsigned)__cvta_generic_to_shared(p);
    asm volatile("ldmatrix.sync.aligned.m8n8.x4.trans.shared.b16 {%0,%1,%2,%3}, [%4];"
                 : "=r"(r0), "=r"(r1), "=r"(r2), "=r"(r3) : "r"(a));
}

__device__ __forceinline__ void mma_bf16(float& d0, float& d1, float& d2, float& d3,
                                         unsigned a0, unsigned a1, unsigned a2, unsigned a3,
                                         unsigned b0, unsigned b1) {
    asm volatile(
        "mma.sync.aligned.m16n8k16.row.col.f32.bf16.bf16.f32 "
        "{%0,%1,%2,%3}, {%4,%5,%6,%7}, {%8,%9}, {%0,%1,%2,%3};"
        : "+f"(d0), "+f"(d1), "+f"(d2), "+f"(d3)
        : "r"(a0), "r"(a1), "r"(a2), "r"(a3), "r"(b0), "r"(b1));
}

__device__ __forceinline__ void cp16(void* smem, const void* gmem) {
    unsigned s = (unsigned)__cvta_generic_to_shared(smem);
    asm volatile("cp.async.ca.shared.global [%0], [%1], 16;" :: "r"(s), "l"(gmem));
}
__device__ __forceinline__ void cp_commit() { asm volatile("cp.async.commit_group;"); }
__device__ __forceinline__ void cp_wait0()  { asm volatile("cp.async.wait_group 0;"); }

// ---------------- 0) weight conversion fp32 -> bf16 ----------------
__global__ void __launch_bounds__(256) cvt_w_k(
    const float* __restrict__ Wq, const float* __restrict__ Wk,
    const float* __restrict__ Wv, const float* __restrict__ Wo,
    const float* __restrict__ W1, const float* __restrict__ W2,
    __nv_bfloat16* __restrict__ dst)
{
    const int i = blockIdx.x * 256 + threadIdx.x;
    if (i >= WB_TOTAL_) return;
    float v;
    if      (i <     SQW_)        v = Wq[i];
    else if (i < 2 * SQW_)        v = Wk[i - SQW_];
    else if (i < 3 * SQW_)        v = Wv[i - 2 * SQW_];
    else if (i < 4 * SQW_)        v = Wo[i - 3 * SQW_];
    else if (i < 4 * SQW_ + SFW_) v = W1[i - 4 * SQW_];
    else                          v = W2[i - 4 * SQW_ - SFW_];
    dst[i] = __float2bfloat16(v);
}

// ---------------- 1) unselected-index compaction (ascending) ----------------
__global__ void __launch_bounds__(1024) unselect_k(const int* __restrict__ sel,
                                                   int* __restrict__ unsel) {
    __shared__ int keep[1024];
    __shared__ int scan[1024];
    const int b = blockIdx.x, t = threadIdx.x;
    keep[t] = (t < N_) ? 1 : 0;
    __syncthreads();
    if (t < S_) keep[sel[b * S_ + t]] = 0;
    __syncthreads();
    const int k = keep[t];
    scan[t] = k;
    __syncthreads();
    #pragma unroll
    for (int off = 1; off < 1024; off <<= 1) {
        int add = (t >= off) ? scan[t - off] : 0;
        __syncthreads();
        scan[t] += add;
        __syncthreads();
    }
    if (k && t < N_) unsel[b * U_ + scan[t] - 1] = t;
}

// ---------------- 2) build x0 (fp32 + bf16) ----------------
__global__ void __launch_bounds__(128) build_x0_k(
    const float* __restrict__ data, const int* __restrict__ sel,
    const int* __restrict__ unsel,
    const float* __restrict__ Wf, const float* __restrict__ bf,
    const float* __restrict__ Wl, const float* __restrict__ bl,
    float* __restrict__ x, __nv_bfloat16* __restrict__ xb)
{
    const int l = blockIdx.x, b = blockIdx.y, t = threadIdx.x;
    const size_t ro = ((size_t)b * L_ + l) * D_;
    float val;
    if (l == 0 || l == L_ - 1) {
        __shared__ float vin[D_];
        const int node = (l == 0) ? sel[b * S_] : sel[b * S_ + S_ - 1];
        vin[t] = data[((size_t)b * N_ + node) * D_ + t];
        __syncthreads();
        const float* W  = (l == 0) ? Wf : Wl;
        const float* bb = (l == 0) ? bf : bl;
        float acc = bb[t];
        #pragma unroll 16
        for (int i = 0; i < D_; i++) acc = fmaf(vin[i], W[i * D_ + t], acc);
        val = acc;
    } else {
        const int node = unsel[b * U_ + (l - 1)];
        val = data[((size_t)b * N_ + node) * D_ + t];
    }
    x[ro + t] = val;
    xb[ro + t] = __float2bfloat16(val);
}

// ---------------- 3) bf16 GEMM core (128x64 tile, k-step 16, ldmatrix) ----------------
// EPI 1: Cf = acc+bias+res (fp32), Cb = bf16 copy
// EPI 2: Cb = relu(acc+bias) (bf16 only)
template <int EPI>
__global__ void __launch_bounds__(256) gemm_bf16(
    const __nv_bfloat16* __restrict__ A, const __nv_bfloat16* __restrict__ W,
    float* __restrict__ Cf, __nv_bfloat16* __restrict__ Cb,
    const float* __restrict__ bias, const float* __restrict__ res,
    int Mreal, int Nn, int K)
{
    __shared__ __align__(16) __nv_bfloat16 As[2][128][24];   // stride 48B
    __shared__ __align__(16) __nv_bfloat16 Bs[2][16][72];    // stride 144B
    const int bm = blockIdx.y * 128;
    const int bn = blockIdx.x * 64;
    const int tid = threadIdx.x;
    const int warp = tid >> 5, lane = tid & 31;
    const int wm = warp >> 1, wn = warp & 1;
    const int g = lane >> 2, tg = lane & 3;

    const int arow = tid >> 1, ahalf = tid & 1;          // A staging
    const int brow = tid >> 3, bcol = (tid & 7) * 8;     // B staging (tid<128)

    float acc[2][4][4];
    #pragma unroll
    for (int a = 0; a < 2; a++)
        #pragma unroll
        for (int b = 0; b < 4; b++)
            #pragma unroll
            for (int c = 0; c < 4; c++) acc[a][b][c] = 0.f;

    // prefetch k-tile 0
    cp16(&As[0][arow][ahalf * 8], &A[(size_t)(bm + arow) * K + ahalf * 8]);
    if (tid < 128) cp16(&Bs[0][brow][bcol], &W[(size_t)brow * Nn + bn + bcol]);
    cp_commit();

    const int NKT = K >> 4;
    #pragma unroll 1
    for (int kt = 0; kt < NKT; kt++) {
        const int buf = kt & 1;
        cp_wait0();
        __syncthreads();
        if (kt + 1 < NKT) {
            const int k0 = (kt + 1) * 16;
            const int nb = buf ^ 1;
            cp16(&As[nb][arow][ahalf * 8], &A[(size_t)(bm + arow) * K + k0 + ahalf * 8]);
            if (tid < 128) cp16(&Bs[nb][brow][bcol], &W[(size_t)(k0 + brow) * Nn + bn + bcol]);
            cp_commit();
        }
        unsigned aa[2][4];
        #pragma unroll
        for (int mt = 0; mt < 2; mt++) {
            const int row = wm * 32 + mt * 16 + (lane & 7) + ((lane >> 3) & 1) * 8;
            const int c8 = ((lane >> 4) & 1) * 8;
            ldsm4(aa[mt][0], aa[mt][1], aa[mt][2], aa[mt][3], &As[buf][row][c8]);
        }
        #pragma unroll
        for (int ntp = 0; ntp < 2; ntp++) {
            unsigned b0, b1, b2, b3;
            const int kr = (lane & 7) + ((lane >> 3) & 1) * 8;
            const int nn = wn * 32 + ntp * 16 + ((lane >> 4) & 1) * 8;
            ldsm4t(b0, b1, b2, b3, &Bs[buf][kr][nn]);
            #pragma unroll
            for (int mt = 0; mt < 2; mt++) {
                mma_bf16(acc[mt][2*ntp][0], acc[mt][2*ntp][1], acc[mt][2*ntp][2], acc[mt][2*ntp][3],
                         aa[mt][0], aa[mt][1], aa[mt][2], aa[mt][3], b0, b1);
                mma_bf16(acc[mt][2*ntp+1][0], acc[mt][2*ntp+1][1], acc[mt][2*ntp+1][2], acc[mt][2*ntp+1][3],
                         aa[mt][0], aa[mt][1], aa[mt][2], aa[mt][3], b2, b3);
            }
        }
    }

    #pragma unroll
    for (int mt = 0; mt < 2; mt++) {
        const int r_lo = bm + wm * 32 + mt * 16 + g;
        const int r_hi = r_lo + 8;
        #pragma unroll
        for (int nt = 0; nt < 4; nt++) {
            const int cn = bn + wn * 32 + nt * 8 + tg * 2;
            float d0 = acc[mt][nt][0], d1 = acc[mt][nt][1];
            float d2 = acc[mt][nt][2], d3 = acc[mt][nt][3];
            if (EPI == 1) {
                const float b0 = bias[cn], b1 = bias[cn + 1];
                if (r_lo < Mreal) {
                    const float2 rv = *(const float2*)&res[(size_t)r_lo * Nn + cn];
                    float v0 = d0 + b0 + rv.x, v1 = d1 + b1 + rv.y;
                    *(float2*)&Cf[(size_t)r_lo * Nn + cn] = make_float2(v0, v1);
                    *(unsigned*)&Cb[(size_t)r_lo * Nn + cn] = pk(v0, v1);
                }
                if (r_hi < Mreal) {
                    const float2 rv = *(const float2*)&res[(size_t)r_hi * Nn + cn];
                    float v2 = d2 + b0 + rv.x, v3 = d3 + b1 + rv.y;
                    *(float2*)&Cf[(size_t)r_hi * Nn + cn] = make_float2(v2, v3);
                    *(unsigned*)&Cb[(size_t)r_hi * Nn + cn] = pk(v2, v3);
                }
            } else {
                const float b0 = bias[cn], b1 = bias[cn + 1];
                float v0 = fmaxf(d0 + b0, 0.f), v1 = fmaxf(d1 + b1, 0.f);
                float v2 = fmaxf(d2 + b0, 0.f), v3 = fmaxf(d3 + b1, 0.f);
                if (r_lo < Mreal) *(unsigned*)&Cb[(size_t)r_lo * Nn + cn] = pk(v0, v1);
                if (r_hi < Mreal) *(unsigned*)&Cb[(size_t)r_hi * Nn + cn] = pk(v2, v3);
            }
        }
    }
}

// ---------------- 3b) fused QKV GEMM (bf16 in/out, q pre-scaled) ----------------
__global__ void __launch_bounds__(256) gemm_qkv(
    const __nv_bfloat16* __restrict__ A,
    const __nv_bfloat16* __restrict__ Wq, const __nv_bfloat16* __restrict__ Wk,
    const __nv_bfloat16* __restrict__ Wv,
    __nv_bfloat16* __restrict__ Cq, __nv_bfloat16* __restrict__ Ck,
    __nv_bfloat16* __restrict__ Cv, int Mreal)
{
    __shared__ __align__(16) __nv_bfloat16 As[2][128][24];
    __shared__ __align__(16) __nv_bfloat16 Bs[2][16][72];
    const int which = blockIdx.x >> 1;
    const __nv_bfloat16* W = (which == 0) ? Wq : (which == 1) ? Wk : Wv;
    __nv_bfloat16* C = (which == 0) ? Cq : (which == 1) ? Ck : Cv;
    const float osc = (which == 0) ? QS_ : 1.f;
    const int bm = blockIdx.y * 128;
    const int bn = (blockIdx.x & 1) * 64;
    const int tid = threadIdx.x;
    const int warp = tid >> 5, lane = tid & 31;
    const int wm = warp >> 1, wn = warp & 1;
    const int g = lane >> 2, tg = lane & 3;

    const int arow = tid >> 1, ahalf = tid & 1;
    const int brow = tid >> 3, bcol = (tid & 7) * 8;

    float acc[2][4][4];
    #pragma unroll
    for (int a = 0; a < 2; a++)
        #pragma unroll
        for (int b = 0; b < 4; b++)
            #pragma unroll
            for (int c = 0; c < 4; c++) acc[a][b][c] = 0.f;

    cp16(&As[0][arow][ahalf * 8], &A[(size_t)(bm + arow) * D_ + ahalf * 8]);
    if (tid < 128) cp16(&Bs[0][brow][bcol], &W[(size_t)brow * HK_ + bn + bcol]);
    cp_commit();

    #pragma unroll 1
    for (int kt = 0; kt < 8; kt++) {
        const int buf = kt & 1;
        cp_wait0();
        __syncthreads();
        if (kt + 1 < 8) {
            const int k0 = (kt + 1) * 16;
            const int nb = buf ^ 1;
            cp16(&As[nb][arow][ahalf * 8], &A[(size_t)(bm + arow) * D_ + k0 + ahalf * 8]);
            if (tid < 128) cp16(&Bs[nb][brow][bcol], &W[(size_t)(k0 + brow) * HK_ + bn + bcol]);
            cp_commit();
        }
        unsigned aa[2][4];
        #pragma unroll
        for (int mt = 0; mt < 2; mt++) {
            const int row = wm * 32 + mt * 16 + (lane & 7) + ((lane >> 3) & 1) * 8;
            const int c8 = ((lane >> 4) & 1) * 8;
            ldsm4(aa[mt][0], aa[mt][1], aa[mt][2], aa[mt][3], &As[buf][row][c8]);
        }
        #pragma unroll
        for (int ntp = 0; ntp < 2; ntp++) {
            unsigned b0, b1, b2, b3;
            const int kr = (lane & 7) + ((lane >> 3) & 1) * 8;
            const int nn = wn * 32 + ntp * 16 + ((lane >> 4) & 1) * 8;
            ldsm4t(b0, b1, b2, b3, &Bs[buf][kr][nn]);
            #pragma unroll
            for (int mt = 0; mt < 2; mt++) {
                mma_bf16(acc[mt][2*ntp][0], acc[mt][2*ntp][1], acc[mt][2*ntp][2], acc[mt][2*ntp][3],
                         aa[mt][0], aa[mt][1], aa[mt][2], aa[mt][3], b0, b1);
                mma_bf16(acc[mt][2*ntp+1][0], acc[mt][2*ntp+1][1], acc[mt][2*ntp+1][2], acc[mt][2*ntp+1][3],
                         aa[mt][0], aa[mt][1], aa[mt][2], aa[mt][3], b2, b3);
            }
        }
    }

    #pragma unroll
    for (int mt = 0; mt < 2; mt++) {
        const int r_lo = bm + wm * 32 + mt * 16 + g;
        const int r_hi = r_lo + 8;
        #pragma unroll
        for (int nt = 0; nt < 4; nt++) {
            const int cn = bn + wn * 32 + nt * 8 + tg * 2;
            const int hh = cn >> 4, dk = cn & 15;
            if (r_lo < Mreal) {
                const int bb = r_lo / L_, ll = r_lo - bb * L_;
                *(unsigned*)&C[(((size_t)bb * H_ + hh) * L_ + ll) * DK_ + dk] =
                    pk(acc[mt][nt][0] * osc, acc[mt][nt][1] * osc);
            }
            if (r_hi < Mreal) {
                const int bb = r_hi / L_, ll = r_hi - bb * L_;
                *(unsigned*)&C[(((size_t)bb * H_ + hh) * L_ + ll) * DK_ + dk] =
                    pk(acc[mt][nt][2] * osc, acc[mt][nt][3] * osc);
            }
        }
    }
}

// ---------------- 4) bf16 flash attention (ldmatrix, exp2 domain) ----------------
__global__ void __launch_bounds__(256) attn_bf16(
    const __nv_bfloat16* __restrict__ q, const __nv_bfloat16* __restrict__ k,
    const __nv_bfloat16* __restrict__ v, __nv_bfloat16* __restrict__ o)
{
    __shared__ __align__(16) __nv_bfloat16 Ks[2][KT_][24];   // [j][dk], stride 48B
    __shared__ __align__(16) __nv_bfloat16 Vs[2][KT_][24];   // [j][dk], stride 48B
    __shared__ __align__(16) unsigned Pp[8][16][36];          // per-warp P pairs (32 used), stride 144B

    const int bh = blockIdx.x;
    const int b = bh >> 3, h = bh & 7;
    const int qt = blockIdx.y;
    const int tid = threadIdx.x, lane = tid & 31, warp = tid >> 5;
    const int g = lane >> 2, tg = lane & 3;

    const __nv_bfloat16* qp = q + (size_t)bh * L_ * DK_;
    const __nv_bfloat16* kp = k + (size_t)bh * L_ * DK_;
    const __nv_bfloat16* vp = v + (size_t)bh * L_ * DK_;

    // Q fragment (already scaled by QS_ at QKV epilogue); k16 covers full DK
    const int r0 = qt * QT_ + warp * 16 + g;
    const int r1 = r0 + 8;
    const int r0c = r0 < L_ ? r0 : L_ - 1;
    const int r1c = r1 < L_ ? r1 : L_ - 1;
    const unsigned qa0 = *(const unsigned*)&qp[(size_t)r0c * DK_ + 2 * tg];
    const unsigned qa1 = *(const unsigned*)&qp[(size_t)r1c * DK_ + 2 * tg];
    const unsigned qa2 = *(const unsigned*)&qp[(size_t)r0c * DK_ + 2 * tg + 8];
    const unsigned qa3 = *(const unsigned*)&qp[(size_t)r1c * DK_ + 2 * tg + 8];

    float m0 = -1e30f, m1 = -1e30f, l0 = 0.f, l1 = 0.f;
    float oc[2][4];
    #pragma unroll
    for (int nt = 0; nt < 2; nt++)
        #pragma unroll
        for (int c = 0; c < 4; c++) oc[nt][c] = 0.f;

    // staging: threads 0-127 -> K, 128-255 -> V; each thread one 16B chunk
    const int srow = (tid & 127) >> 1;
    const int shalf = (tid & 1) * 8;
    const bool isv = tid >= 128;

    auto stage = [&](int buf, int j0) {
        int jc = j0 + srow; if (jc > L_ - 1) jc = L_ - 1;
        const __nv_bfloat16* src = (isv ? vp : kp) + (size_t)jc * DK_ + shalf;
        if (isv) cp16(&Vs[buf][srow][shalf], src);
        else     cp16(&Ks[buf][srow][shalf], src);
    };

    stage(0, 0);
    cp_commit();

    #pragma unroll 1
    for (int ti = 0; ti < NKTILES_; ti++) {
        const int buf = ti & 1;
        const int j0 = ti * KT_;
        cp_wait0();
        __syncthreads();
        if (ti + 1 < NKTILES_) { stage(buf ^ 1, j0 + KT_); cp_commit(); }

        // S = Q·K^T : B frags via non-trans ldsm (Ks stored j-major = mma col-major)
        float sc[8][4];
        #pragma unroll
        for (int nt = 0; nt < 8; nt++)
            #pragma unroll
            for (int c = 0; c < 4; c++) sc[nt][c] = 0.f;
        #pragma unroll
        for (int ntp = 0; ntp < 4; ntp++) {
            unsigned b0, b1, b2, b3;
            const int jrow = ntp * 16 + (lane & 7) + ((lane >> 4) & 1) * 8;
            const int kcol = ((lane >> 3) & 1) * 8;
            ldsm4(b0, b1, b2, b3, &Ks[buf][jrow][kcol]);
            mma_bf16(sc[2*ntp][0], sc[2*ntp][1], sc[2*ntp][2], sc[2*ntp][3],
                     qa0, qa1, qa2, qa3, b0, b1);
            mma_bf16(sc[2*ntp+1][0], sc[2*ntp+1][1], sc[2*ntp+1][2], sc[2*ntp+1][3],
                     qa0, qa1, qa2, qa3, b2, b3);
        }
        if (j0 + KT_ > L_) {
            #pragma unroll
            for (int nt = 0; nt < 8; nt++) {
                const int c = j0 + nt * 8 + 2 * tg;
                if (c     >= L_) { sc[nt][0] = -1e30f; sc[nt][2] = -1e30f; }
                if (c + 1 >= L_) { sc[nt][1] = -1e30f; sc[nt][3] = -1e30f; }
            }
        }
        // online max / rescale (log2 domain)
        float nm0 = m0, nm1 = m1;
        #pragma unroll
        for (int nt = 0; nt < 8; nt++) {
            nm0 = fmaxf(nm0, fmaxf(sc[nt][0], sc[nt][1]));
            nm1 = fmaxf(nm1, fmaxf(sc[nt][2], sc[nt][3]));
        }
        nm0 = fmaxf(nm0, __shfl_xor_sync(0xffffffffu, nm0, 1));
        nm0 = fmaxf(nm0, __shfl_xor_sync(0xffffffffu, nm0, 2));
        nm1 = fmaxf(nm1, __shfl_xor_sync(0xffffffffu, nm1, 1));
        nm1 = fmaxf(nm1, __shfl_xor_sync(0xffffffffu, nm1, 2));
        const float f0 = ex2(m0 - nm0);
        const float f1 = ex2(m1 - nm1);
        m0 = nm0; m1 = nm1;
        l0 *= f0; l1 *= f1;
        #pragma unroll
        for (int nt = 0; nt < 2; nt++) {
            oc[nt][0] *= f0; oc[nt][1] *= f0;
            oc[nt][2] *= f1; oc[nt][3] *= f1;
        }
        // P = 2^(S-m): pack to bf16 pairs in per-warp smem
        float rs0 = 0.f, rs1 = 0.f;
        #pragma unroll
        for (int nt = 0; nt < 8; nt++) {
            const float p0 = ex2(sc[nt][0] - m0);
            const float p1 = ex2(sc[nt][1] - m0);
            const float p2 = ex2(sc[nt][2] - m1);
            const float p3 = ex2(sc[nt][3] - m1);
            rs0 += p0 + p1;
            rs1 += p2 + p3;
            Pp[warp][g    ][nt * 4 + tg] = pk(p0, p1);
            Pp[warp][g + 8][nt * 4 + tg] = pk(p2, p3);
        }
        rs0 += __shfl_xor_sync(0xffffffffu, rs0, 1);
        rs0 += __shfl_xor_sync(0xffffffffu, rs0, 2);
        rs1 += __shfl_xor_sync(0xffffffffu, rs1, 1);
        rs1 += __shfl_xor_sync(0xffffffffu, rs1, 2);
        l0 += rs0; l1 += rs1;
        __syncwarp();
        // O += P·V : A via non-trans ldsm on Pp, B via trans ldsm on Vs
        #pragma unroll
        for (int ks = 0; ks < 4; ks++) {
            unsigned a0, a1, a2, a3;
            const unsigned* pa = &Pp[warp][(lane & 7) + ((lane >> 3) & 1) * 8]
                                         [ks * 8 + ((lane >> 4) & 1) * 4];
            ldsm4(a0, a1, a2, a3, pa);
            unsigned v0, v1, v2, v3;
            const int jrow = ks * 16 + (lane & 7) + ((lane >> 3) & 1) * 8;
            const int dkc = ((lane >> 4) & 1) * 8;
            ldsm4t(v0, v1, v2, v3, &Vs[buf][jrow][dkc]);
            mma_bf16(oc[0][0], oc[0][1], oc[0][2], oc[0][3], a0, a1, a2, a3, v0, v1);
            mma_bf16(oc[1][0], oc[1][1], oc[1][2], oc[1][3], a0, a1, a2, a3, v2, v3);
        }
        __syncwarp();
    }

    const float inv0 = 1.f / l0;
    const float inv1 = 1.f / l1;
    #pragma unroll
    for (int nt = 0; nt < 2; nt++) {
        const int dn = h * DK_ + nt * 8 + 2 * tg;
        if (r0 < L_)
            *(unsigned*)&o[((size_t)b * L_ + r0) * HK_ + dn] =
                pk(oc[nt][0] * inv0, oc[nt][1] * inv0);
        if (r1 < L_)
            *(unsigned*)&o[((size_t)b * L_ + r1) * HK_ + dn] =
                pk(oc[nt][2] * inv1, oc[nt][3] * inv1);
    }
}

// ---------------- 5) logits GEMV: warp per row (fp32 x) ----------------
__global__ void __launch_bounds__(256) logits_k(
    const float* __restrict__ x, const float* __restrict__ Wfin,
    const float* __restrict__ bfin, float* __restrict__ logits)
{
    const int row  = (int)((blockIdx.x * (size_t)blockDim.x + threadIdx.x) >> 5);
    const int lane = threadIdx.x & 31;
    if (row >= M_) return;
    float4 xv = ((const float4*)(x + (size_t)row * D_))[lane];
    float4 wv = ((const float4*)Wfin)[lane];
    float s = xv.x * wv.x + xv.y * wv.y + xv.z * wv.z + xv.w * wv.w;
    #pragma unroll
    for (int off = 16; off; off >>= 1) s += __shfl_xor_sync(0xffffffffu, s, off);
    if (lane == 0) logits[row] = s + bfin[0];
}

// ---------------- 6) bias add + softmax + scatter ----------------
__global__ void __launch_bounds__(1024) finalize_k(
    const float* __restrict__ logits, const float* __restrict__ ab,
    const int* __restrict__ sel, const int* __restrict__ unsel,
    float* __restrict__ out)
{
    __shared__ float red[32];
    const int b = blockIdx.x, t = threadIdx.x;
    const int lane = t & 31, warp = t >> 5;
    const int last = sel[b * S_ + S_ - 1];
    const float* abrow = ab + ((size_t)b * N_ + last) * N_;

    int u = 0;
    float val = -3.0e38f;
    const bool active = (t < U_);
    if (active) {
        u = unsel[b * U_ + t];
        val = logits[b * L_ + 1 + t] + abrow[u];
    }
    float m = val;
    #pragma unroll
    for (int off = 16; off; off >>= 1) m = fmaxf(m, __shfl_xor_sync(0xffffffffu, m, off));
    if (lane == 0) red[warp] = m;
    __syncthreads();
    if (warp == 0) {
        float mm = red[lane];
        #pragma unroll
        for (int off = 16; off; off >>= 1) mm = fmaxf(mm, __shfl_xor_sync(0xffffffffu, mm, off));
        red[lane] = mm;
    }
    __syncthreads();
    m = red[0];
    __syncthreads();
    const float e = active ? __expf(val - m) : 0.f;
    float s = e;
    #pragma unroll
    for (int off = 16; off; off >>= 1) s += __shfl_xor_sync(0xffffffffu, s, off);
    if (lane == 0) red[warp] = s;
    __syncthreads();
    if (warp == 0) {
        float ss = red[lane];
        #pragma unroll
        for (int off = 16; off; off >>= 1) ss += __shfl_xor_sync(0xffffffffu, ss, off);
        red[lane] = ss;
    }
    __syncthreads();
    const float inv = 1.f / red[0];

    for (int i = t; i < N_; i += 1024) out[(size_t)b * N_ + i] = -2.0f;
    __syncthreads();
    if (active) {
        float p = e * inv;
        if (p <= 1e-5f) p += 1e-7f;
        out[(size_t)b * N_ + u] = p;
    }
}

// ---------------- launch ----------------
extern "C" void kernel_launch(void* const* d_in, const int* in_sizes, int n_in,
                              void* d_out, int out_size) {
    (void)in_sizes; (void)n_in; (void)out_size;
    const float* data   = (const float*)d_in[0];
    const float* ab     = (const float*)d_in[1];
    const float* Wfirst = (const float*)d_in[2];
    const float* bfirst = (const float*)d_in[3];
    const float* Wlast  = (const float*)d_in[4];
    const float* blast  = (const float*)d_in[5];
    const float* Wq     = (const float*)d_in[6];
    const float* Wk     = (const float*)d_in[7];
    const float* Wv     = (const float*)d_in[8];
    const float* Wo     = (const float*)d_in[9];
    const float* bo     = (const float*)d_in[10];
    const float* W1     = (const float*)d_in[11];
    const float* b1     = (const float*)d_in[12];
    const float* W2     = (const float*)d_in[13];
    const float* b2     = (const float*)d_in[14];
    const float* Wfin   = (const float*)d_in[15];
    const float* bfin   = (const float*)d_in[16];
    const int*   sel    = (const int*)d_in[17];
    float* out = (float*)d_out;

    void *px, *pout1, *plog, *pun;
    void *pxb, *pout1b, *phb, *pqb, *pkb, *pvb, *pob, *pwb;
    cudaGetSymbolAddress(&px,     g_x);
    cudaGetSymbolAddress(&pout1,  g_out1);
    cudaGetSymbolAddress(&plog,   g_logits);
    cudaGetSymbolAddress(&pun,    g_unsel);
    cudaGetSymbolAddress(&pxb,    g_xb);
    cudaGetSymbolAddress(&pout1b, g_out1b);
    cudaGetSymbolAddress(&phb,    g_hb);
    cudaGetSymbolAddress(&pqb,    g_qb);
    cudaGetSymbolAddress(&pkb,    g_kb);
    cudaGetSymbolAddress(&pvb,    g_vb);
    cudaGetSymbolAddress(&pob,    g_ob);
    cudaGetSymbolAddress(&pwb,    g_wb);
    float* x      = (float*)px;
    float* out1   = (float*)pout1;
    float* logits = (float*)plog;
    int*   unsel  = (int*)pun;
    __nv_bfloat16* xb    = (__nv_bfloat16*)pxb;
    __nv_bfloat16* out1b = (__nv_bfloat16*)pout1b;
    __nv_bfloat16* hb    = (__nv_bfloat16*)phb;
    __nv_bfloat16* qb    = (__nv_bfloat16*)pqb;
    __nv_bfloat16* kb    = (__nv_bfloat16*)pkb;
    __nv_bfloat16* vb    = (__nv_bfloat16*)pvb;
    __nv_bfloat16* ob    = (__nv_bfloat16*)pob;
    __nv_bfloat16* wb    = (__nv_bfloat16*)pwb;

    cvt_w_k<<<(WB_TOTAL_ + 255) / 256, 256>>>(Wq, Wk, Wv, Wo, W1, W2, wb);
    unselect_k<<<B_, 1024>>>(sel, unsel);
    build_x0_k<<<dim3(L_, B_), D_>>>(data, sel, unsel, Wfirst, bfirst, Wlast, blast, x, xb);

    const dim3 g128(HK_ / 64, MT_);   // (2, 201)
    const dim3 g512(FF_ / 64, MT_);   // (8, 201)
    const dim3 gqkv(6, MT_);
    const dim3 gattn(B_ * H_, QTILES_);
    for (int il = 0; il < NL_; il++) {
        const __nv_bfloat16* wqb = wb + (size_t)il * D_ * HK_;
        const __nv_bfloat16* wkb = wb + SQW_ + (size_t)il * D_ * HK_;
        const __nv_bfloat16* wvb = wb + 2 * SQW_ + (size_t)il * D_ * HK_;
        const __nv_bfloat16* wob = wb + 3 * SQW_ + (size_t)il * HK_ * D_;
        const __nv_bfloat16* w1b = wb + 4 * SQW_ + (size_t)il * D_ * FF_;
        const __nv_bfloat16* w2b = wb + 4 * SQW_ + SFW_ + (size_t)il * FF_ * D_;
        const float* bol = bo + (size_t)il * D_;
        const float* b1l = b1 + (size_t)il * FF_;
        const float* b2l = b2 + (size_t)il * D_;

        gemm_qkv<<<gqkv, 256>>>(xb, wqb, wkb, wvb, qb, kb, vb, M_);
        attn_bf16<<<gattn, 256>>>(qb, kb, vb, ob);
        gemm_bf16<1><<<g128, 256>>>(ob, wob, out1, out1b, bol, x, M_, D_, HK_);
        gemm_bf16<2><<<g512, 256>>>(out1b, w1b, nullptr, hb, b1l, nullptr, M_, FF_, D_);
        gemm_bf16<1><<<g128, 256>>>(hb, w2b, x, xb, b2l, out1, M_, D_, FF_);
    }

    logits_k<<<(M_ * 32 + 255) / 256, 256>>>(x, Wfin, bfin, logits);
    finalize_k<<<B_, 1024>>>(logits, ab, sel, unsel, out);
}

// round 8
// speedup vs baseline: 7.6894x; 1.0524x over previous
#include <cuda_runtime.h>
#include <cuda_bf16.h>

// ---------------- problem constants ----------------
namespace {
constexpr int B_  = 32;
constexpr int N_  = 1000;
constexpr int S_  = 200;
constexpr int D_  = 128;
constexpr int H_  = 8;
constexpr int DK_ = 16;
constexpr int FF_ = 512;
constexpr int NL_ = 3;
constexpr int HK_ = H_ * DK_;          // 128
constexpr int U_  = N_ - S_;           // 800 unselected
constexpr int L_  = U_ + 2;            // 802 sequence length
constexpr int M_  = B_ * L_;           // 25664 rows
constexpr int MT_ = ((M_ + 127) / 128); // 201 row-tiles
constexpr int MP_ = MT_ * 128;         // padded rows
constexpr int QT_ = 128;               // attention query tile
constexpr int KT_ = 64;                // attention key tile
constexpr int QTILES_  = (L_ + QT_ - 1) / QT_;  // 7
constexpr int NKTILES_ = (L_ + KT_ - 1) / KT_;  // 13
constexpr float LOG2E = 1.44269504088896f;
constexpr float QS_ = 0.25f * LOG2E;   // folded into Q at QKV epilogue
constexpr int SQW_ = NL_ * D_ * HK_;   // 49152 (per q/k/v/o weight set)
constexpr int SFW_ = NL_ * D_ * FF_;   // 196608
constexpr int WB_TOTAL_ = 4 * SQW_ + 2 * SFW_;  // 589824
}

// ---------------- device scratch (no runtime allocation allowed) ----------------
__device__ float g_x    [MP_ * D_];
__device__ float g_out1 [MP_ * D_];
__device__ float g_logits[M_];
__device__ int   g_unsel[B_ * U_];
__device__ __nv_bfloat16 g_xb   [MP_ * D_];
__device__ __nv_bfloat16 g_out1b[MP_ * D_];
__device__ __nv_bfloat16 g_hb   [MP_ * FF_];
__device__ __nv_bfloat16 g_qb   [M_ * D_];   // [B,H,L,DK]
__device__ __nv_bfloat16 g_kb   [M_ * D_];
__device__ __nv_bfloat16 g_vb   [M_ * D_];
__device__ __nv_bfloat16 g_ob   [MP_ * D_];
__device__ __nv_bfloat16 g_wb   [WB_TOTAL_];

// ---------------- helpers ----------------
__device__ __forceinline__ float ex2(float x) {
    float y;
    asm("ex2.approx.f32 %0, %1;" : "=f"(y) : "f"(x));
    return y;
}

// pack (lo, hi) floats -> bf16x2 (lo in low 16 bits)
__device__ __forceinline__ unsigned pk(float lo, float hi) {
    unsigned r;
    asm("cvt.rn.bf16x2.f32 %0, %1, %2;" : "=r"(r) : "f"(hi), "f"(lo));
    return r;
}

__device__ __forceinline__ void ldsm4(unsigned& r0, unsigned& r1, unsigned& r2, unsigned& r3,
                                      const void* p) {
    unsigned a = (unsigned)__cvta_generic_to_shared(p);
    asm volatile("ldmatrix.sync.aligned.m8n8.x4.shared.b16 {%0,%1,%2,%3}, [%4];"
                 : "=r"(r0), "=r"(r1), "=r"(r2), "=r"(r3) : "r"(a));
}
__device__ __forceinline__ void ldsm4t(unsigned& r0, unsigned& r1, unsigned& r2, unsigned& r3,
                                       const void* p) {
    unsigned a = (unsigned)__cvta_generic_to_shared(p);
    asm volatile("ldmatrix.sync.aligned.m8n8.x4.trans.shared.b16 {%0,%1,%2,%3}, [%4];"
                 : "=r"(r0), "=r"(r1), "=r"(r2), "=r"(r3) : "r"(a));
}

__device__ __forceinline__ void mma_bf16(float& d0, float& d1, float& d2, float& d3,
                                         unsigned a0, unsigned a1, unsigned a2, unsigned a3,
                                         unsigned b0, unsigned b1) {
    asm volatile(
        "mma.sync.aligned.m16n8k16.row.col.f32.bf16.bf16.f32 "
        "{%0,%1,%2,%3}, {%4,%5,%6,%7}, {%8,%9}, {%0,%1,%2,%3};"
        : "+f"(d0), "+f"(d1), "+f"(d2), "+f"(d3)
        : "r"(a0), "r"(a1), "r"(a2), "r"(a3), "r"(b0), "r"(b1));
}

__device__ __forceinline__ void cp16(void* smem, const void* gmem) {
    unsigned s = (unsigned)__cvta_generic_to_shared(smem);
    asm volatile("cp.async.ca.shared.global [%0], [%1], 16;" :: "r"(s), "l"(gmem));
}
__device__ __forceinline__ void cp_commit() { asm volatile("cp.async.commit_group;"); }
__device__ __forceinline__ void cp_wait0()  { asm volatile("cp.async.wait_group 0;"); }
__device__ __forceinline__ void cp_wait1()  { asm volatile("cp.async.wait_group 1;"); }

// ---------------- 0) weight conversion fp32 -> bf16 ----------------
__global__ void __launch_bounds__(256) cvt_w_k(
    const float* __restrict__ Wq, const float* __restrict__ Wk,
    const float* __restrict__ Wv, const float* __restrict__ Wo,
    const float* __restrict__ W1, const float* __restrict__ W2,
    __nv_bfloat16* __restrict__ dst)
{
    const int i = blockIdx.x * 256 + threadIdx.x;
    if (i >= WB_TOTAL_) return;
    float v;
    if      (i <     SQW_)        v = Wq[i];
    else if (i < 2 * SQW_)        v = Wk[i - SQW_];
    else if (i < 3 * SQW_)        v = Wv[i - 2 * SQW_];
    else if (i < 4 * SQW_)        v = Wo[i - 3 * SQW_];
    else if (i < 4 * SQW_ + SFW_) v = W1[i - 4 * SQW_];
    else                          v = W2[i - 4 * SQW_ - SFW_];
    dst[i] = __float2bfloat16(v);
}

// ---------------- 1) unselected-index compaction (ascending) ----------------
__global__ void __launch_bounds__(1024) unselect_k(const int* __restrict__ sel,
                                                   int* __restrict__ unsel) {
    __shared__ int keep[1024];
    __shared__ int scan[1024];
    const int b = blockIdx.x, t = threadIdx.x;
    keep[t] = (t < N_) ? 1 : 0;
    __syncthreads();
    if (t < S_) keep[sel[b * S_ + t]] = 0;
    __syncthreads();
    const int k = keep[t];
    scan[t] = k;
    __syncthreads();
    #pragma unroll
    for (int off = 1; off < 1024; off <<= 1) {
        int add = (t >= off) ? scan[t - off] : 0;
        __syncthreads();
        scan[t] += add;
        __syncthreads();
    }
    if (k && t < N_) unsel[b * U_ + scan[t] - 1] = t;
}

// ---------------- 2) build x0 (fp32 + bf16) ----------------
__global__ void __launch_bounds__(128) build_x0_k(
    const float* __restrict__ data, const int* __restrict__ sel,
    const int* __restrict__ unsel,
    const float* __restrict__ Wf, const float* __restrict__ bf,
    const float* __restrict__ Wl, const float* __restrict__ bl,
    float* __restrict__ x, __nv_bfloat16* __restrict__ xb)
{
    const int l = blockIdx.x, b = blockIdx.y, t = threadIdx.x;
    const size_t ro = ((size_t)b * L_ + l) * D_;
    float val;
    if (l == 0 || l == L_ - 1) {
        __shared__ float vin[D_];
        const int node = (l == 0) ? sel[b * S_] : sel[b * S_ + S_ - 1];
        vin[t] = data[((size_t)b * N_ + node) * D_ + t];
        __syncthreads();
        const float* W  = (l == 0) ? Wf : Wl;
        const float* bb = (l == 0) ? bf : bl;
        float acc = bb[t];
        #pragma unroll 16
        for (int i = 0; i < D_; i++) acc = fmaf(vin[i], W[i * D_ + t], acc);
        val = acc;
    } else {
        const int node = unsel[b * U_ + (l - 1)];
        val = data[((size_t)b * N_ + node) * D_ + t];
    }
    x[ro + t] = val;
    xb[ro + t] = __float2bfloat16(val);
}

// ================= GEMM 128x128 tile core (shared by generic + qkv) =================
// 256 threads, 8 warps in 4(M) x 2(N); warp tile 32x64; 3-stage cp.async pipeline.
struct GemmSmem {
    __nv_bfloat16 As[3][128][24];   // 48B stride
    __nv_bfloat16 Bs[3][16][136];   // 272B stride
};

// compute one k16 step on stage buf into acc[2][8][4]
__device__ __forceinline__ void gemm_step(
    const GemmSmem& sm, int buf, int wm, int wn, int lane, float acc[2][8][4])
{
    unsigned aa[2][4];
    #pragma unroll
    for (int mt = 0; mt < 2; mt++) {
        const int row = wm * 32 + mt * 16 + (lane & 7) + ((lane >> 3) & 1) * 8;
        const int c8 = ((lane >> 4) & 1) * 8;
        ldsm4(aa[mt][0], aa[mt][1], aa[mt][2], aa[mt][3], &sm.As[buf][row][c8]);
    }
    const int kr = (lane & 7) + ((lane >> 3) & 1) * 8;
    #pragma unroll
    for (int ntp = 0; ntp < 4; ntp++) {
        unsigned b0, b1, b2, b3;
        const int nn = wn * 64 + ntp * 16 + ((lane >> 4) & 1) * 8;
        ldsm4t(b0, b1, b2, b3, &sm.Bs[buf][kr][nn]);
        #pragma unroll
        for (int mt = 0; mt < 2; mt++) {
            mma_bf16(acc[mt][2*ntp][0], acc[mt][2*ntp][1], acc[mt][2*ntp][2], acc[mt][2*ntp][3],
                     aa[mt][0], aa[mt][1], aa[mt][2], aa[mt][3], b0, b1);
            mma_bf16(acc[mt][2*ntp+1][0], acc[mt][2*ntp+1][1], acc[mt][2*ntp+1][2], acc[mt][2*ntp+1][3],
                     aa[mt][0], aa[mt][1], aa[mt][2], aa[mt][3], b2, b3);
        }
    }
}

// ---------------- 3) generic bf16 GEMM (N multiple of 128) ----------------
// EPI 1: Cf = acc+bias+res (fp32), Cb = bf16 copy
// EPI 2: Cb = relu(acc+bias) (bf16 only)
template <int EPI>
__global__ void __launch_bounds__(256) gemm_bf16(
    const __nv_bfloat16* __restrict__ A, const __nv_bfloat16* __restrict__ W,
    float* __restrict__ Cf, __nv_bfloat16* __restrict__ Cb,
    const float* __restrict__ bias, const float* __restrict__ res,
    int Mreal, int Nn, int K)
{
    __shared__ GemmSmem sm;
    const int bm = blockIdx.y * 128;
    const int bn = blockIdx.x * 128;
    const int tid = threadIdx.x;
    const int warp = tid >> 5, lane = tid & 31;
    const int wm = warp >> 1, wn = warp & 1;
    const int g = lane >> 2, tg = lane & 3;

    const int arow = tid >> 1, ahalf = (tid & 1) * 8;
    const int brow = tid >> 4, bcol = (tid & 15) * 8;

    float acc[2][8][4];
    #pragma unroll
    for (int a = 0; a < 2; a++)
        #pragma unroll
        for (int b = 0; b < 8; b++)
            #pragma unroll
            for (int c = 0; c < 4; c++) acc[a][b][c] = 0.f;

    const int NKT = K >> 4;
    // prefetch tiles 0, 1
    cp16(&sm.As[0][arow][ahalf], &A[(size_t)(bm + arow) * K + ahalf]);
    cp16(&sm.Bs[0][brow][bcol], &W[(size_t)brow * Nn + bn + bcol]);
    cp_commit();
    cp16(&sm.As[1][arow][ahalf], &A[(size_t)(bm + arow) * K + 16 + ahalf]);
    cp16(&sm.Bs[1][brow][bcol], &W[(size_t)(16 + brow) * Nn + bn + bcol]);
    cp_commit();

    int buf = 0;
    #pragma unroll 1
    for (int kt = 0; kt < NKT; kt++) {
        // last committed group is tile kt+1 except on the final iteration,
        // where it is tile kt itself -> must fully drain there.
        if (kt + 1 < NKT) cp_wait1(); else cp_wait0();
        __syncthreads();
        if (kt + 2 < NKT) {
            const int k0 = (kt + 2) * 16;
            const int nb = (buf + 2 >= 3) ? buf - 1 : buf + 2;
            cp16(&sm.As[nb][arow][ahalf], &A[(size_t)(bm + arow) * K + k0 + ahalf]);
            cp16(&sm.Bs[nb][brow][bcol], &W[(size_t)(k0 + brow) * Nn + bn + bcol]);
            cp_commit();
        }
        gemm_step(sm, buf, wm, wn, lane, acc);
        buf = (buf + 1 == 3) ? 0 : buf + 1;
    }

    #pragma unroll
    for (int mt = 0; mt < 2; mt++) {
        const int r_lo = bm + wm * 32 + mt * 16 + g;
        const int r_hi = r_lo + 8;
        #pragma unroll
        for (int nt = 0; nt < 8; nt++) {
            const int cn = bn + wn * 64 + nt * 8 + tg * 2;
            float d0 = acc[mt][nt][0], d1 = acc[mt][nt][1];
            float d2 = acc[mt][nt][2], d3 = acc[mt][nt][3];
            if (EPI == 1) {
                const float b0 = bias[cn], b1 = bias[cn + 1];
                if (r_lo < Mreal) {
                    const float2 rv = *(const float2*)&res[(size_t)r_lo * Nn + cn];
                    float v0 = d0 + b0 + rv.x, v1 = d1 + b1 + rv.y;
                    *(float2*)&Cf[(size_t)r_lo * Nn + cn] = make_float2(v0, v1);
                    *(unsigned*)&Cb[(size_t)r_lo * Nn + cn] = pk(v0, v1);
                }
                if (r_hi < Mreal) {
                    const float2 rv = *(const float2*)&res[(size_t)r_hi * Nn + cn];
                    float v2 = d2 + b0 + rv.x, v3 = d3 + b1 + rv.y;
                    *(float2*)&Cf[(size_t)r_hi * Nn + cn] = make_float2(v2, v3);
                    *(unsigned*)&Cb[(size_t)r_hi * Nn + cn] = pk(v2, v3);
                }
            } else {
                const float b0 = bias[cn], b1 = bias[cn + 1];
                float v0 = fmaxf(d0 + b0, 0.f), v1 = fmaxf(d1 + b1, 0.f);
                float v2 = fmaxf(d2 + b0, 0.f), v3 = fmaxf(d3 + b1, 0.f);
                if (r_lo < Mreal) *(unsigned*)&Cb[(size_t)r_lo * Nn + cn] = pk(v0, v1);
                if (r_hi < Mreal) *(unsigned*)&Cb[(size_t)r_hi * Nn + cn] = pk(v2, v3);
            }
        }
    }
}

// ---------------- 3b) fused QKV GEMM (full N=128 per block) ----------------
__global__ void __launch_bounds__(256) gemm_qkv(
    const __nv_bfloat16* __restrict__ A,
    const __nv_bfloat16* __restrict__ Wq, const __nv_bfloat16* __restrict__ Wk,
    const __nv_bfloat16* __restrict__ Wv,
    __nv_bfloat16* __restrict__ Cq, __nv_bfloat16* __restrict__ Ck,
    __nv_bfloat16* __restrict__ Cv, int Mreal)
{
    __shared__ GemmSmem sm;
    const int which = blockIdx.x;
    const __nv_bfloat16* W = (which == 0) ? Wq : (which == 1) ? Wk : Wv;
    __nv_bfloat16* C = (which == 0) ? Cq : (which == 1) ? Ck : Cv;
    const float osc = (which == 0) ? QS_ : 1.f;
    const int bm = blockIdx.y * 128;
    const int tid = threadIdx.x;
    const int warp = tid >> 5, lane = tid & 31;
    const int wm = warp >> 1, wn = warp & 1;
    const int g = lane >> 2, tg = lane & 3;

    const int arow = tid >> 1, ahalf = (tid & 1) * 8;
    const int brow = tid >> 4, bcol = (tid & 15) * 8;

    float acc[2][8][4];
    #pragma unroll
    for (int a = 0; a < 2; a++)
        #pragma unroll
        for (int b = 0; b < 8; b++)
            #pragma unroll
            for (int c = 0; c < 4; c++) acc[a][b][c] = 0.f;

    cp16(&sm.As[0][arow][ahalf], &A[(size_t)(bm + arow) * D_ + ahalf]);
    cp16(&sm.Bs[0][brow][bcol], &W[(size_t)brow * HK_ + bcol]);
    cp_commit();
    cp16(&sm.As[1][arow][ahalf], &A[(size_t)(bm + arow) * D_ + 16 + ahalf]);
    cp16(&sm.Bs[1][brow][bcol], &W[(size_t)(16 + brow) * HK_ + bcol]);
    cp_commit();

    int buf = 0;
    #pragma unroll 1
    for (int kt = 0; kt < 8; kt++) {
        if (kt + 1 < 8) cp_wait1(); else cp_wait0();   // drain on final tile
        __syncthreads();
        if (kt + 2 < 8) {
            const int k0 = (kt + 2) * 16;
            const int nb = (buf + 2 >= 3) ? buf - 1 : buf + 2;
            cp16(&sm.As[nb][arow][ahalf], &A[(size_t)(bm + arow) * D_ + k0 + ahalf]);
            cp16(&sm.Bs[nb][brow][bcol], &W[(size_t)(k0 + brow) * HK_ + bcol]);
            cp_commit();
        }
        gemm_step(sm, buf, wm, wn, lane, acc);
        buf = (buf + 1 == 3) ? 0 : buf + 1;
    }

    #pragma unroll
    for (int mt = 0; mt < 2; mt++) {
        const int r_lo = bm + wm * 32 + mt * 16 + g;
        const int r_hi = r_lo + 8;
        #pragma unroll
        for (int nt = 0; nt < 8; nt++) {
            const int cn = wn * 64 + nt * 8 + tg * 2;
            const int hh = cn >> 4, dk = cn & 15;
            if (r_lo < Mreal) {
                const int bb = r_lo / L_, ll = r_lo - bb * L_;
                *(unsigned*)&C[(((size_t)bb * H_ + hh) * L_ + ll) * DK_ + dk] =
                    pk(acc[mt][nt][0] * osc, acc[mt][nt][1] * osc);
            }
            if (r_hi < Mreal) {
                const int bb = r_hi / L_, ll = r_hi - bb * L_;
                *(unsigned*)&C[(((size_t)bb * H_ + hh) * L_ + ll) * DK_ + dk] =
                    pk(acc[mt][nt][2] * osc, acc[mt][nt][3] * osc);
            }
        }
    }
}

// ---------------- 4) bf16 flash attention (ldmatrix, exp2 domain) ----------------
__global__ void __launch_bounds__(256) attn_bf16(
    const __nv_bfloat16* __restrict__ q, const __nv_bfloat16* __restrict__ k,
    const __nv_bfloat16* __restrict__ v, __nv_bfloat16* __restrict__ o)
{
    __shared__ __align__(16) __nv_bfloat16 Ks[2][KT_][24];   // [j][dk], stride 48B
    __shared__ __align__(16) __nv_bfloat16 Vs[2][KT_][24];   // [j][dk], stride 48B
    __shared__ __align__(16) unsigned Pp[8][16][36];          // per-warp P pairs (32 used), stride 144B

    const int bh = blockIdx.x;
    const int b = bh >> 3, h = bh & 7;
    const int qt = blockIdx.y;
    const int tid = threadIdx.x, lane = tid & 31, warp = tid >> 5;
    const int g = lane >> 2, tg = lane & 3;

    const __nv_bfloat16* qp = q + (size_t)bh * L_ * DK_;
    const __nv_bfloat16* kp = k + (size_t)bh * L_ * DK_;
    const __nv_bfloat16* vp = v + (size_t)bh * L_ * DK_;

    const int r0 = qt * QT_ + warp * 16 + g;
    const int r1 = r0 + 8;
    const int r0c = r0 < L_ ? r0 : L_ - 1;
    const int r1c = r1 < L_ ? r1 : L_ - 1;
    const unsigned qa0 = *(const unsigned*)&qp[(size_t)r0c * DK_ + 2 * tg];
    const unsigned qa1 = *(const unsigned*)&qp[(size_t)r1c * DK_ + 2 * tg];
    const unsigned qa2 = *(const unsigned*)&qp[(size_t)r0c * DK_ + 2 * tg + 8];
    const unsigned qa3 = *(const unsigned*)&qp[(size_t)r1c * DK_ + 2 * tg + 8];

    float m0 = -1e30f, m1 = -1e30f, l0 = 0.f, l1 = 0.f;
    float oc[2][4];
    #pragma unroll
    for (int nt = 0; nt < 2; nt++)
        #pragma unroll
        for (int c = 0; c < 4; c++) oc[nt][c] = 0.f;

    const int srow = (tid & 127) >> 1;
    const int shalf = (tid & 1) * 8;
    const bool isv = tid >= 128;

    auto stage = [&](int buf, int j0) {
        int jc = j0 + srow; if (jc > L_ - 1) jc = L_ - 1;
        const __nv_bfloat16* src = (isv ? vp : kp) + (size_t)jc * DK_ + shalf;
        if (isv) cp16(&Vs[buf][srow][shalf], src);
        else     cp16(&Ks[buf][srow][shalf], src);
    };

    stage(0, 0);
    cp_commit();

    #pragma unroll 1
    for (int ti = 0; ti < NKTILES_; ti++) {
        const int buf = ti & 1;
        const int j0 = ti * KT_;
        cp_wait0();
        __syncthreads();
        if (ti + 1 < NKTILES_) { stage(buf ^ 1, j0 + KT_); cp_commit(); }

        float sc[8][4];
        #pragma unroll
        for (int nt = 0; nt < 8; nt++)
            #pragma unroll
            for (int c = 0; c < 4; c++) sc[nt][c] = 0.f;
        #pragma unroll
        for (int ntp = 0; ntp < 4; ntp++) {
            unsigned b0, b1, b2, b3;
            const int jrow = ntp * 16 + (lane & 7) + ((lane >> 4) & 1) * 8;
            const int kcol = ((lane >> 3) & 1) * 8;
            ldsm4(b0, b1, b2, b3, &Ks[buf][jrow][kcol]);
            mma_bf16(sc[2*ntp][0], sc[2*ntp][1], sc[2*ntp][2], sc[2*ntp][3],
                     qa0, qa1, qa2, qa3, b0, b1);
            mma_bf16(sc[2*ntp+1][0], sc[2*ntp+1][1], sc[2*ntp+1][2], sc[2*ntp+1][3],
                     qa0, qa1, qa2, qa3, b2, b3);
        }
        if (j0 + KT_ > L_) {
            #pragma unroll
            for (int nt = 0; nt < 8; nt++) {
                const int c = j0 + nt * 8 + 2 * tg;
                if (c     >= L_) { sc[nt][0] = -1e30f; sc[nt][2] = -1e30f; }
                if (c + 1 >= L_) { sc[nt][1] = -1e30f; sc[nt][3] = -1e30f; }
            }
        }
        float nm0 = m0, nm1 = m1;
        #pragma unroll
        for (int nt = 0; nt < 8; nt++) {
            nm0 = fmaxf(nm0, fmaxf(sc[nt][0], sc[nt][1]));
            nm1 = fmaxf(nm1, fmaxf(sc[nt][2], sc[nt][3]));
        }
        nm0 = fmaxf(nm0, __shfl_xor_sync(0xffffffffu, nm0, 1));
        nm0 = fmaxf(nm0, __shfl_xor_sync(0xffffffffu, nm0, 2));
        nm1 = fmaxf(nm1, __shfl_xor_sync(0xffffffffu, nm1, 1));
        nm1 = fmaxf(nm1, __shfl_xor_sync(0xffffffffu, nm1, 2));
        const float f0 = ex2(m0 - nm0);
        const float f1 = ex2(m1 - nm1);
        m0 = nm0; m1 = nm1;
        l0 *= f0; l1 *= f1;
        #pragma unroll
        for (int nt = 0; nt < 2; nt++) {
            oc[nt][0] *= f0; oc[nt][1] *= f0;
            oc[nt][2] *= f1; oc[nt][3] *= f1;
        }
        float rs0 = 0.f, rs1 = 0.f;
        #pragma unroll
        for (int nt = 0; nt < 8; nt++) {
            const float p0 = ex2(sc[nt][0] - m0);
            const float p1 = ex2(sc[nt][1] - m0);
            const float p2 = ex2(sc[nt][2] - m1);
            const float p3 = ex2(sc[nt][3] - m1);
            rs0 += p0 + p1;
            rs1 += p2 + p3;
            Pp[warp][g    ][nt * 4 + tg] = pk(p0, p1);
            Pp[warp][g + 8][nt * 4 + tg] = pk(p2, p3);
        }
        rs0 += __shfl_xor_sync(0xffffffffu, rs0, 1);
        rs0 += __shfl_xor_sync(0xffffffffu, rs0, 2);
        rs1 += __shfl_xor_sync(0xffffffffu, rs1, 1);
        rs1 += __shfl_xor_sync(0xffffffffu, rs1, 2);
        l0 += rs0; l1 += rs1;
        __syncwarp();
        #pragma unroll
        for (int ks = 0; ks < 4; ks++) {
            unsigned a0, a1, a2, a3;
            const unsigned* pa = &Pp[warp][(lane & 7) + ((lane >> 3) & 1) * 8]
                                         [ks * 8 + ((lane >> 4) & 1) * 4];
            ldsm4(a0, a1, a2, a3, pa);
            unsigned v0, v1, v2, v3;
            const int jrow = ks * 16 + (lane & 7) + ((lane >> 3) & 1) * 8;
            const int dkc = ((lane >> 4) & 1) * 8;
            ldsm4t(v0, v1, v2, v3, &Vs[buf][jrow][dkc]);
            mma_bf16(oc[0][0], oc[0][1], oc[0][2], oc[0][3], a0, a1, a2, a3, v0, v1);
            mma_bf16(oc[1][0], oc[1][1], oc[1][2], oc[1][3], a0, a1, a2, a3, v2, v3);
        }
        __syncwarp();
    }

    const float inv0 = 1.f / l0;
    const float inv1 = 1.f / l1;
    #pragma unroll
    for (int nt = 0; nt < 2; nt++) {
        const int dn = h * DK_ + nt * 8 + 2 * tg;
        if (r0 < L_)
            *(unsigned*)&o[((size_t)b * L_ + r0) * HK_ + dn] =
                pk(oc[nt][0] * inv0, oc[nt][1] * inv0);
        if (r1 < L_)
            *(unsigned*)&o[((size_t)b * L_ + r1) * HK_ + dn] =
                pk(oc[nt][2] * inv1, oc[nt][3] * inv1);
    }
}

// ---------------- 5) logits GEMV: warp per row (fp32 x) ----------------
__global__ void __launch_bounds__(256) logits_k(
    const float* __restrict__ x, const float* __restrict__ Wfin,
    const float* __restrict__ bfin, float* __restrict__ logits)
{
    const int row  = (int)((blockIdx.x * (size_t)blockDim.x + threadIdx.x) >> 5);
    const int lane = threadIdx.x & 31;
    if (row >= M_) return;
    float4 xv = ((const float4*)(x + (size_t)row * D_))[lane];
    float4 wv = ((const float4*)Wfin)[lane];
    float s = xv.x * wv.x + xv.y * wv.y + xv.z * wv.z + xv.w * wv.w;
    #pragma unroll
    for (int off = 16; off; off >>= 1) s += __shfl_xor_sync(0xffffffffu, s, off);
    if (lane == 0) logits[row] = s + bfin[0];
}

// ---------------- 6) bias add + softmax + scatter ----------------
__global__ void __launch_bounds__(1024) finalize_k(
    const float* __restrict__ logits, const float* __restrict__ ab,
    const int* __restrict__ sel, const int* __restrict__ unsel,
    float* __restrict__ out)
{
    __shared__ float red[32];
    const int b = blockIdx.x, t = threadIdx.x;
    const int lane = t & 31, warp = t >> 5;
    const int last = sel[b * S_ + S_ - 1];
    const float* abrow = ab + ((size_t)b * N_ + last) * N_;

    int u = 0;
    float val = -3.0e38f;
    const bool active = (t < U_);
    if (active) {
        u = unsel[b * U_ + t];
        val = logits[b * L_ + 1 + t] + abrow[u];
    }
    float m = val;
    #pragma unroll
    for (int off = 16; off; off >>= 1) m = fmaxf(m, __shfl_xor_sync(0xffffffffu, m, off));
    if (lane == 0) red[warp] = m;
    __syncthreads();
    if (warp == 0) {
        float mm = red[lane];
        #pragma unroll
        for (int off = 16; off; off >>= 1) mm = fmaxf(mm, __shfl_xor_sync(0xffffffffu, mm, off));
        red[lane] = mm;
    }
    __syncthreads();
    m = red[0];
    __syncthreads();
    const float e = active ? __expf(val - m) : 0.f;
    float s = e;
    #pragma unroll
    for (int off = 16; off; off >>= 1) s += __shfl_xor_sync(0xffffffffu, s, off);
    if (lane == 0) red[warp] = s;
    __syncthreads();
    if (warp == 0) {
        float ss = red[lane];
        #pragma unroll
        for (int off = 16; off; off >>= 1) ss += __shfl_xor_sync(0xffffffffu, ss, off);
        red[lane] = ss;
    }
    __syncthreads();
    const float inv = 1.f / red[0];

    for (int i = t; i < N_; i += 1024) out[(size_t)b * N_ + i] = -2.0f;
    __syncthreads();
    if (active) {
        float p = e * inv;
        if (p <= 1e-5f) p += 1e-7f;
        out[(size_t)b * N_ + u] = p;
    }
}

// ---------------- launch ----------------
extern "C" void kernel_launch(void* const* d_in, const int* in_sizes, int n_in,
                              void* d_out, int out_size) {
    (void)in_sizes; (void)n_in; (void)out_size;
    const float* data   = (const float*)d_in[0];
    const float* ab     = (const float*)d_in[1];
    const float* Wfirst = (const float*)d_in[2];
    const float* bfirst = (const float*)d_in[3];
    const float* Wlast  = (const float*)d_in[4];
    const float* blast  = (const float*)d_in[5];
    const float* Wq     = (const float*)d_in[6];
    const float* Wk     = (const float*)d_in[7];
    const float* Wv     = (const float*)d_in[8];
    const float* Wo     = (const float*)d_in[9];
    const float* bo     = (const float*)d_in[10];
    const float* W1     = (const float*)d_in[11];
    const float* b1     = (const float*)d_in[12];
    const float* W2     = (const float*)d_in[13];
    const float* b2     = (const float*)d_in[14];
    const float* Wfin   = (const float*)d_in[15];
    const float* bfin   = (const float*)d_in[16];
    const int*   sel    = (const int*)d_in[17];
    float* out = (float*)d_out;

    void *px, *pout1, *plog, *pun;
    void *pxb, *pout1b, *phb, *pqb, *pkb, *pvb, *pob, *pwb;
    cudaGetSymbolAddress(&px,     g_x);
    cudaGetSymbolAddress(&pout1,  g_out1);
    cudaGetSymbolAddress(&plog,   g_logits);
    cudaGetSymbolAddress(&pun,    g_unsel);
    cudaGetSymbolAddress(&pxb,    g_xb);
    cudaGetSymbolAddress(&pout1b, g_out1b);
    cudaGetSymbolAddress(&phb,    g_hb);
    cudaGetSymbolAddress(&pqb,    g_qb);
    cudaGetSymbolAddress(&pkb,    g_kb);
    cudaGetSymbolAddress(&pvb,    g_vb);
    cudaGetSymbolAddress(&pob,    g_ob);
    cudaGetSymbolAddress(&pwb,    g_wb);
    float* x      = (float*)px;
    float* out1   = (float*)pout1;
    float* logits = (float*)plog;
    int*   unsel  = (int*)pun;
    __nv_bfloat16* xb    = (__nv_bfloat16*)pxb;
    __nv_bfloat16* out1b = (__nv_bfloat16*)pout1b;
    __nv_bfloat16* hb    = (__nv_bfloat16*)phb;
    __nv_bfloat16* qb    = (__nv_bfloat16*)pqb;
    __nv_bfloat16* kb    = (__nv_bfloat16*)pkb;
    __nv_bfloat16* vb    = (__nv_bfloat16*)pvb;
    __nv_bfloat16* ob    = (__nv_bfloat16*)pob;
    __nv_bfloat16* wb    = (__nv_bfloat16*)pwb;

    cvt_w_k<<<(WB_TOTAL_ + 255) / 256, 256>>>(Wq, Wk, Wv, Wo, W1, W2, wb);
    unselect_k<<<B_, 1024>>>(sel, unsel);
    build_x0_k<<<dim3(L_, B_), D_>>>(data, sel, unsel, Wfirst, bfirst, Wlast, blast, x, xb);

    const dim3 gwo(1, MT_);           // N=128
    const dim3 gff1(FF_ / 128, MT_);  // (4, 201)
    const dim3 gff2(1, MT_);          // N=128
    const dim3 gqkv(3, MT_);          // 3 outputs, full N=128 each
    const dim3 gattn(B_ * H_, QTILES_);
    for (int il = 0; il < NL_; il++) {
        const __nv_bfloat16* wqb = wb + (size_t)il * D_ * HK_;
        const __nv_bfloat16* wkb = wb + SQW_ + (size_t)il * D_ * HK_;
        const __nv_bfloat16* wvb = wb + 2 * SQW_ + (size_t)il * D_ * HK_;
        const __nv_bfloat16* wob = wb + 3 * SQW_ + (size_t)il * HK_ * D_;
        const __nv_bfloat16* w1b = wb + 4 * SQW_ + (size_t)il * D_ * FF_;
        const __nv_bfloat16* w2b = wb + 4 * SQW_ + SFW_ + (size_t)il * FF_ * D_;
        const float* bol = bo + (size_t)il * D_;
        const float* b1l = b1 + (size_t)il * FF_;
        const float* b2l = b2 + (size_t)il * D_;

        gemm_qkv<<<gqkv, 256>>>(xb, wqb, wkb, wvb, qb, kb, vb, M_);
        attn_bf16<<<gattn, 256>>>(qb, kb, vb, ob);
        gemm_bf16<1><<<gwo, 256>>>(ob, wob, out1, out1b, bol, x, M_, D_, HK_);
        gemm_bf16<2><<<gff1, 256>>>(out1b, w1b, nullptr, hb, b1l, nullptr, M_, FF_, D_);
        gemm_bf16<1><<<gff2, 256>>>(hb, w2b, x, xb, b2l, out1, M_, D_, FF_);
    }

    logits_k<<<(M_ * 32 + 255) / 256, 256>>>(x, Wfin, bfin, logits);
    finalize_k<<<B_, 1024>>>(logits, ab, sel, unsel, out);
}

// round 9
// speedup vs baseline: 7.7651x; 1.0098x over previous
#include <cuda_runtime.h>
#include <cuda_bf16.h>

// ---------------- problem constants ----------------
namespace {
constexpr int B_  = 32;
constexpr int N_  = 1000;
constexpr int S_  = 200;
constexpr int D_  = 128;
constexpr int H_  = 8;
constexpr int DK_ = 16;
constexpr int FF_ = 512;
constexpr int NL_ = 3;
constexpr int HK_ = H_ * DK_;          // 128
constexpr int U_  = N_ - S_;           // 800 unselected
constexpr int L_  = U_ + 2;            // 802 sequence length
constexpr int M_  = B_ * L_;           // 25664 rows
constexpr int MT_ = ((M_ + 127) / 128); // 201 row-tiles
constexpr int MP_ = MT_ * 128;         // padded rows
constexpr int QT_ = 128;               // attention query tile
constexpr int KT_ = 64;                // attention key tile
constexpr int QTILES_  = (L_ + QT_ - 1) / QT_;  // 7
constexpr int NKTILES_ = (L_ + KT_ - 1) / KT_;  // 13
constexpr float LOG2E = 1.44269504088896f;
constexpr float QS_ = 0.25f * LOG2E;   // folded into Q at QKV epilogue
constexpr int SQW_ = NL_ * D_ * HK_;   // 49152
constexpr int SFW_ = NL_ * D_ * FF_;   // 196608
constexpr int WB_TOTAL_ = 4 * SQW_ + 2 * SFW_;  // 589824
constexpr int CVT_BLKS_ = (WB_TOTAL_ + 1023) / 1024;  // 576
// dynamic smem layout for mlp_k
constexpr int SM_AF_   = 0;                  // bf16 [128][136] : phase1 A (ob), reused as h
constexpr int SM_OB1_  = 34816;              // bf16 [128][136] : out1 bf16
constexpr int SM_BS_   = 69632;              // bf16 [3][16][136]
constexpr int SM_LOG_  = 82688;              // float [128]
constexpr int SM_MLP_  = 83200;
}

// ---------------- device scratch (no runtime allocation allowed) ----------------
__device__ float g_x    [MP_ * D_];
__device__ float g_logits[M_];
__device__ int   g_unsel[B_ * U_];
__device__ __nv_bfloat16 g_xb [MP_ * D_];
__device__ __nv_bfloat16 g_qb [M_ * D_];   // [B,H,L,DK]
__device__ __nv_bfloat16 g_kb [M_ * D_];
__device__ __nv_bfloat16 g_vb [M_ * D_];
__device__ __nv_bfloat16 g_ob [MP_ * D_];
__device__ __nv_bfloat16 g_wb [WB_TOTAL_];

// ---------------- helpers ----------------
__device__ __forceinline__ float ex2(float x) {
    float y;
    asm("ex2.approx.f32 %0, %1;" : "=f"(y) : "f"(x));
    return y;
}

__device__ __forceinline__ unsigned pk(float lo, float hi) {
    unsigned r;
    asm("cvt.rn.bf16x2.f32 %0, %1, %2;" : "=r"(r) : "f"(hi), "f"(lo));
    return r;
}

__device__ __forceinline__ void ldsm4(unsigned& r0, unsigned& r1, unsigned& r2, unsigned& r3,
                                      const void* p) {
    unsigned a = (unsigned)__cvta_generic_to_shared(p);
    asm volatile("ldmatrix.sync.aligned.m8n8.x4.shared.b16 {%0,%1,%2,%3}, [%4];"
                 : "=r"(r0), "=r"(r1), "=r"(r2), "=r"(r3) : "r"(a));
}
__device__ __forceinline__ void ldsm4t(unsigned& r0, unsigned& r1, unsigned& r2, unsigned& r3,
                                       const void* p) {
    unsigned a = (unsigned)__cvta_generic_to_shared(p);
    asm volatile("ldmatrix.sync.aligned.m8n8.x4.trans.shared.b16 {%0,%1,%2,%3}, [%4];"
                 : "=r"(r0), "=r"(r1), "=r"(r2), "=r"(r3) : "r"(a));
}

__device__ __forceinline__ void mma_bf16(float& d0, float& d1, float& d2, float& d3,
                                         unsigned a0, unsigned a1, unsigned a2, unsigned a3,
                                         unsigned b0, unsigned b1) {
    asm volatile(
        "mma.sync.aligned.m16n8k16.row.col.f32.bf16.bf16.f32 "
        "{%0,%1,%2,%3}, {%4,%5,%6,%7}, {%8,%9}, {%0,%1,%2,%3};"
        : "+f"(d0), "+f"(d1), "+f"(d2), "+f"(d3)
        : "r"(a0), "r"(a1), "r"(a2), "r"(a3), "r"(b0), "r"(b1));
}

__device__ __forceinline__ void cp16(void* smem, const void* gmem) {
    unsigned s = (unsigned)__cvta_generic_to_shared(smem);
    asm volatile("cp.async.ca.shared.global [%0], [%1], 16;" :: "r"(s), "l"(gmem));
}
__device__ __forceinline__ void cp_commit() { asm volatile("cp.async.commit_group;"); }
__device__ __forceinline__ void cp_wait0()  { asm volatile("cp.async.wait_group 0;"); }
__device__ __forceinline__ void cp_wait1()  { asm volatile("cp.async.wait_group 1;"); }

// ---------------- 1) fused prologue: weight cvt + unselect + build x0 ----------------
__global__ void __launch_bounds__(1024) prolog_k(
    const float* __restrict__ data, const int* __restrict__ sel,
    const float* __restrict__ Wf, const float* __restrict__ bf,
    const float* __restrict__ Wl, const float* __restrict__ bl,
    const float* __restrict__ Wq, const float* __restrict__ Wk,
    const float* __restrict__ Wv, const float* __restrict__ Wo,
    const float* __restrict__ W1, const float* __restrict__ W2,
    __nv_bfloat16* __restrict__ wb,
    int* __restrict__ unsel,
    float* __restrict__ x, __nv_bfloat16* __restrict__ xb)
{
    const int t = threadIdx.x;
    if (blockIdx.x >= 32) {
        const int i = (blockIdx.x - 32) * 1024 + t;
        if (i >= WB_TOTAL_) return;
        float v;
        if      (i <     SQW_)        v = Wq[i];
        else if (i < 2 * SQW_)        v = Wk[i - SQW_];
        else if (i < 3 * SQW_)        v = Wv[i - 2 * SQW_];
        else if (i < 4 * SQW_)        v = Wo[i - 3 * SQW_];
        else if (i < 4 * SQW_ + SFW_) v = W1[i - 4 * SQW_];
        else                          v = W2[i - 4 * SQW_ - SFW_];
        wb[i] = __float2bfloat16(v);
        return;
    }

    const int b = blockIdx.x;
    __shared__ int keep[1024];
    __shared__ int scan[1024];
    __shared__ float vin[2][128];

    keep[t] = (t < N_) ? 1 : 0;
    __syncthreads();
    if (t < S_) keep[sel[b * S_ + t]] = 0;
    __syncthreads();
    const int k = keep[t];
    scan[t] = k;
    __syncthreads();
    #pragma unroll
    for (int off = 1; off < 1024; off <<= 1) {
        int add = (t >= off) ? scan[t - off] : 0;
        __syncthreads();
        scan[t] += add;
        __syncthreads();
    }
    if (k && t < N_) unsel[b * U_ + scan[t] - 1] = t;

    // endpoint rows: ef = first @ Wfirst + bfirst ; el = last @ Wlast + blast
    const int node_f = sel[b * S_];
    const int node_l = sel[b * S_ + S_ - 1];
    if (t < 128)       vin[0][t]       = data[((size_t)b * N_ + node_f) * D_ + t];
    else if (t < 256)  vin[1][t - 128] = data[((size_t)b * N_ + node_l) * D_ + t - 128];
    __syncthreads();   // also makes unsel gmem writes visible block-wide
    if (t < 256) {
        const int which = t >> 7, tt = t & 127;
        const float* W  = which ? Wl : Wf;
        const float* bb = which ? bl : bf;
        float acc = bb[tt];
        #pragma unroll 16
        for (int i = 0; i < D_; i++) acc = fmaf(vin[which][i], W[i * D_ + tt], acc);
        const int l = which ? (L_ - 1) : 0;
        const size_t ro = ((size_t)b * L_ + l) * D_ + tt;
        x[ro] = acc;
        xb[ro] = __float2bfloat16(acc);
    }
    // gather middle rows
    for (int i = t; i < U_ * D_; i += 1024) {
        const int row = i >> 7, col = i & 127;
        const int node = unsel[b * U_ + row];
        const float v = data[((size_t)b * N_ + node) * D_ + col];
        const size_t ro = ((size_t)b * L_ + 1 + row) * D_ + col;
        x[ro] = v;
        xb[ro] = __float2bfloat16(v);
    }
}

// ================= 128x128x128 sub-GEMM: A resident in smem, B streamed =================
// 256 threads, 8 warps 4(M)x2(N); warp tile 32x64; acc[2][8][4].
__device__ __forceinline__ void sub_gemm128(
    const __nv_bfloat16* __restrict__ Wsrc, int wld, int wcol0,
    const __nv_bfloat16 (*Asm)[136],
    __nv_bfloat16 (*Bsm)[16][136],
    int wm, int wn, int lane, int tid,
    float acc[2][8][4])
{
    const int brow = tid >> 4, bcol = (tid & 15) * 8;
    __syncthreads();   // prior readers of Bsm / writers of Asm done
    cp16(&Bsm[0][brow][bcol], &Wsrc[(size_t)brow * wld + wcol0 + bcol]);
    cp_commit();
    cp16(&Bsm[1][brow][bcol], &Wsrc[(size_t)(16 + brow) * wld + wcol0 + bcol]);
    cp_commit();
    int buf = 0;
    #pragma unroll 1
    for (int kt = 0; kt < 8; kt++) {
        if (kt + 1 < 8) cp_wait1(); else cp_wait0();
        __syncthreads();
        if (kt + 2 < 8) {
            const int nb = (buf + 2 >= 3) ? buf - 1 : buf + 2;
            cp16(&Bsm[nb][brow][bcol], &Wsrc[(size_t)((kt + 2) * 16 + brow) * wld + wcol0 + bcol]);
            cp_commit();
        }
        unsigned aa[2][4];
        #pragma unroll
        for (int mt = 0; mt < 2; mt++) {
            const int row = wm * 32 + mt * 16 + (lane & 7) + ((lane >> 3) & 1) * 8;
            const int c8 = kt * 16 + ((lane >> 4) & 1) * 8;
            ldsm4(aa[mt][0], aa[mt][1], aa[mt][2], aa[mt][3], &Asm[row][c8]);
        }
        const int kr = (lane & 7) + ((lane >> 3) & 1) * 8;
        #pragma unroll
        for (int ntp = 0; ntp < 4; ntp++) {
            unsigned b0, b1, b2, b3;
            const int nn = wn * 64 + ntp * 16 + ((lane >> 4) & 1) * 8;
            ldsm4t(b0, b1, b2, b3, &Bsm[buf][kr][nn]);
            #pragma unroll
            for (int mt = 0; mt < 2; mt++) {
                mma_bf16(acc[mt][2*ntp][0], acc[mt][2*ntp][1], acc[mt][2*ntp][2], acc[mt][2*ntp][3],
                         aa[mt][0], aa[mt][1], aa[mt][2], aa[mt][3], b0, b1);
                mma_bf16(acc[mt][2*ntp+1][0], acc[mt][2*ntp+1][1], acc[mt][2*ntp+1][2], acc[mt][2*ntp+1][3],
                         aa[mt][0], aa[mt][1], aa[mt][2], aa[mt][3], b2, b3);
            }
        }
        buf = (buf + 1 == 3) ? 0 : buf + 1;
    }
}

// ---------------- 2) fused MLP: out1 = o@Wo+bo+x ; x' = out1 + relu(out1@W1+b1)@W2 + b2 ----
// optional fused logits (last layer): logits[r] = x'[r,:] . Wfin + bfin
__global__ void __launch_bounds__(256) mlp_k(
    const __nv_bfloat16* __restrict__ ob,
    const __nv_bfloat16* __restrict__ Wo, const float* __restrict__ bo,
    const __nv_bfloat16* __restrict__ W1, const float* __restrict__ b1,
    const __nv_bfloat16* __restrict__ W2, const float* __restrict__ b2,
    float* __restrict__ xf, __nv_bfloat16* __restrict__ xb,
    const float* __restrict__ Wfin, const float* __restrict__ bfin,
    float* __restrict__ logits, int Mreal)
{
    extern __shared__ char dyn[];
    __nv_bfloat16 (*Af)[136]  = (__nv_bfloat16(*)[136])(dyn + SM_AF_);
    __nv_bfloat16 (*Ob1)[136] = (__nv_bfloat16(*)[136])(dyn + SM_OB1_);
    __nv_bfloat16 (*Bs)[16][136] = (__nv_bfloat16(*)[16][136])(dyn + SM_BS_);
    float* slog = (float*)(dyn + SM_LOG_);

    const int bm = blockIdx.x * 128;
    const int tid = threadIdx.x;
    const int warp = tid >> 5, lane = tid & 31;
    const int wm = warp >> 1, wn = warp & 1;
    const int g = lane >> 2, tg = lane & 3;

    // stage ob tile resident (128x128 bf16)
    #pragma unroll
    for (int i = 0; i < 8; i++) {
        const int idx = tid + i * 256;
        cp16(&Af[idx >> 4][(idx & 15) * 8], &ob[(size_t)(bm + (idx >> 4)) * D_ + (idx & 15) * 8]);
    }
    cp_commit();
    cp_wait0();

    // phase 1: acc = o @ Wo
    float acc[2][8][4];
    #pragma unroll
    for (int a = 0; a < 2; a++)
        #pragma unroll
        for (int b = 0; b < 8; b++)
            #pragma unroll
            for (int c = 0; c < 4; c++) acc[a][b][c] = 0.f;
    sub_gemm128(Wo, D_, 0, Af, Bs, wm, wn, lane, tid, acc);

    // epilogue 1: out1 = acc + bo + x ; keep fp32 in regs, write bf16 to Ob1
    #pragma unroll
    for (int mt = 0; mt < 2; mt++) {
        const int lr_lo = wm * 32 + mt * 16 + g;
        const int lr_hi = lr_lo + 8;
        #pragma unroll
        for (int nt = 0; nt < 8; nt++) {
            const int cn = wn * 64 + nt * 8 + tg * 2;
            const float b0 = bo[cn], b1v = bo[cn + 1];
            const float2 rlo = *(const float2*)&xf[(size_t)(bm + lr_lo) * D_ + cn];
            const float2 rhi = *(const float2*)&xf[(size_t)(bm + lr_hi) * D_ + cn];
            acc[mt][nt][0] += b0 + rlo.x;  acc[mt][nt][1] += b1v + rlo.y;
            acc[mt][nt][2] += b0 + rhi.x;  acc[mt][nt][3] += b1v + rhi.y;
            *(unsigned*)&Ob1[lr_lo][cn] = pk(acc[mt][nt][0], acc[mt][nt][1]);
            *(unsigned*)&Ob1[lr_hi][cn] = pk(acc[mt][nt][2], acc[mt][nt][3]);
        }
    }

    // phases 2+3 per 128-col FF chunk: h = relu(out1@W1_c + b1_c) ; acc += h@W2_c
    #pragma unroll 1
    for (int c = 0; c < 4; c++) {
        float acch[2][8][4];
        #pragma unroll
        for (int a = 0; a < 2; a++)
            #pragma unroll
            for (int b = 0; b < 8; b++)
                #pragma unroll
                for (int d = 0; d < 4; d++) acch[a][b][d] = 0.f;
        sub_gemm128(W1, FF_, c * 128, Ob1, Bs, wm, wn, lane, tid, acch);
        // write h = relu(acch + b1) into Af (ob no longer needed)
        #pragma unroll
        for (int mt = 0; mt < 2; mt++) {
            const int lr_lo = wm * 32 + mt * 16 + g;
            const int lr_hi = lr_lo + 8;
            #pragma unroll
            for (int nt = 0; nt < 8; nt++) {
                const int cn = wn * 64 + nt * 8 + tg * 2;
                const float bb0 = b1[c * 128 + cn], bb1 = b1[c * 128 + cn + 1];
                const float v0 = fmaxf(acch[mt][nt][0] + bb0, 0.f);
                const float v1 = fmaxf(acch[mt][nt][1] + bb1, 0.f);
                const float v2 = fmaxf(acch[mt][nt][2] + bb0, 0.f);
                const float v3 = fmaxf(acch[mt][nt][3] + bb1, 0.f);
                *(unsigned*)&Af[lr_lo][cn] = pk(v0, v1);
                *(unsigned*)&Af[lr_hi][cn] = pk(v2, v3);
            }
        }
        sub_gemm128(W2 + (size_t)c * 128 * D_, D_, 0, Af, Bs, wm, wn, lane, tid, acc);
    }

    // final epilogue: x' = acc + b2 ; optional logits
    const bool do_log = (Wfin != nullptr);
    if (do_log && tid < 128) slog[tid] = 0.f;
    if (do_log) __syncthreads();

    float part[2][2] = {{0.f, 0.f}, {0.f, 0.f}};
    #pragma unroll
    for (int mt = 0; mt < 2; mt++) {
        const int lr_lo = wm * 32 + mt * 16 + g;
        const int lr_hi = lr_lo + 8;
        #pragma unroll
        for (int nt = 0; nt < 8; nt++) {
            const int cn = wn * 64 + nt * 8 + tg * 2;
            const float b0 = b2[cn], b1v = b2[cn + 1];
            const float v0 = acc[mt][nt][0] + b0, v1 = acc[mt][nt][1] + b1v;
            const float v2 = acc[mt][nt][2] + b0, v3 = acc[mt][nt][3] + b1v;
            *(float2*)&xf[(size_t)(bm + lr_lo) * D_ + cn] = make_float2(v0, v1);
            *(float2*)&xf[(size_t)(bm + lr_hi) * D_ + cn] = make_float2(v2, v3);
            *(unsigned*)&xb[(size_t)(bm + lr_lo) * D_ + cn] = pk(v0, v1);
            *(unsigned*)&xb[(size_t)(bm + lr_hi) * D_ + cn] = pk(v2, v3);
            if (do_log) {
                const float w0 = Wfin[cn], w1 = Wfin[cn + 1];
                part[mt][0] += v0 * w0 + v1 * w1;
                part[mt][1] += v2 * w0 + v3 * w1;
            }
        }
    }
    if (do_log) {
        #pragma unroll
        for (int mt = 0; mt < 2; mt++) {
            #pragma unroll
            for (int hh = 0; hh < 2; hh++) {
                part[mt][hh] += __shfl_xor_sync(0xffffffffu, part[mt][hh], 1);
                part[mt][hh] += __shfl_xor_sync(0xffffffffu, part[mt][hh], 2);
            }
        }
        if (tg == 0) {
            #pragma unroll
            for (int mt = 0; mt < 2; mt++) {
                atomicAdd(&slog[wm * 32 + mt * 16 + g],     part[mt][0]);
                atomicAdd(&slog[wm * 32 + mt * 16 + g + 8], part[mt][1]);
            }
        }
        __syncthreads();
        if (tid < 128 && bm + tid < Mreal) logits[bm + tid] = slog[tid] + bfin[0];
    }
}

// ---------------- 3) fused QKV GEMM (unchanged from R8) ----------------
struct GemmSmem {
    __nv_bfloat16 As[3][128][24];   // 48B stride
    __nv_bfloat16 Bs[3][16][136];   // 272B stride
};

__device__ __forceinline__ void gemm_step(
    const GemmSmem& sm, int buf, int wm, int wn, int lane, float acc[2][8][4])
{
    unsigned aa[2][4];
    #pragma unroll
    for (int mt = 0; mt < 2; mt++) {
        const int row = wm * 32 + mt * 16 + (lane & 7) + ((lane >> 3) & 1) * 8;
        const int c8 = ((lane >> 4) & 1) * 8;
        ldsm4(aa[mt][0], aa[mt][1], aa[mt][2], aa[mt][3], &sm.As[buf][row][c8]);
    }
    const int kr = (lane & 7) + ((lane >> 3) & 1) * 8;
    #pragma unroll
    for (int ntp = 0; ntp < 4; ntp++) {
        unsigned b0, b1, b2, b3;
        const int nn = wn * 64 + ntp * 16 + ((lane >> 4) & 1) * 8;
        ldsm4t(b0, b1, b2, b3, &sm.Bs[buf][kr][nn]);
        #pragma unroll
        for (int mt = 0; mt < 2; mt++) {
            mma_bf16(acc[mt][2*ntp][0], acc[mt][2*ntp][1], acc[mt][2*ntp][2], acc[mt][2*ntp][3],
                     aa[mt][0], aa[mt][1], aa[mt][2], aa[mt][3], b0, b1);
            mma_bf16(acc[mt][2*ntp+1][0], acc[mt][2*ntp+1][1], acc[mt][2*ntp+1][2], acc[mt][2*ntp+1][3],
                     aa[mt][0], aa[mt][1], aa[mt][2], aa[mt][3], b2, b3);
        }
    }
}

__global__ void __launch_bounds__(256) gemm_qkv(
    const __nv_bfloat16* __restrict__ A,
    const __nv_bfloat16* __restrict__ Wq, const __nv_bfloat16* __restrict__ Wk,
    const __nv_bfloat16* __restrict__ Wv,
    __nv_bfloat16* __restrict__ Cq, __nv_bfloat16* __restrict__ Ck,
    __nv_bfloat16* __restrict__ Cv, int Mreal)
{
    __shared__ GemmSmem sm;
    const int which = blockIdx.x;
    const __nv_bfloat16* W = (which == 0) ? Wq : (which == 1) ? Wk : Wv;
    __nv_bfloat16* C = (which == 0) ? Cq : (which == 1) ? Ck : Cv;
    const float osc = (which == 0) ? QS_ : 1.f;
    const int bm = blockIdx.y * 128;
    const int tid = threadIdx.x;
    const int warp = tid >> 5, lane = tid & 31;
    const int wm = warp >> 1, wn = warp & 1;
    const int g = lane >> 2, tg = lane & 3;

    const int arow = tid >> 1, ahalf = (tid & 1) * 8;
    const int brow = tid >> 4, bcol = (tid & 15) * 8;

    float acc[2][8][4];
    #pragma unroll
    for (int a = 0; a < 2; a++)
        #pragma unroll
        for (int b = 0; b < 8; b++)
            #pragma unroll
            for (int c = 0; c < 4; c++) acc[a][b][c] = 0.f;

    cp16(&sm.As[0][arow][ahalf], &A[(size_t)(bm + arow) * D_ + ahalf]);
    cp16(&sm.Bs[0][brow][bcol], &W[(size_t)brow * HK_ + bcol]);
    cp_commit();
    cp16(&sm.As[1][arow][ahalf], &A[(size_t)(bm + arow) * D_ + 16 + ahalf]);
    cp16(&sm.Bs[1][brow][bcol], &W[(size_t)(16 + brow) * HK_ + bcol]);
    cp_commit();

    int buf = 0;
    #pragma unroll 1
    for (int kt = 0; kt < 8; kt++) {
        if (kt + 1 < 8) cp_wait1(); else cp_wait0();
        __syncthreads();
        if (kt + 2 < 8) {
            const int k0 = (kt + 2) * 16;
            const int nb = (buf + 2 >= 3) ? buf - 1 : buf + 2;
            cp16(&sm.As[nb][arow][ahalf], &A[(size_t)(bm + arow) * D_ + k0 + ahalf]);
            cp16(&sm.Bs[nb][brow][bcol], &W[(size_t)(k0 + brow) * HK_ + bcol]);
            cp_commit();
        }
        gemm_step(sm, buf, wm, wn, lane, acc);
        buf = (buf + 1 == 3) ? 0 : buf + 1;
    }

    #pragma unroll
    for (int mt = 0; mt < 2; mt++) {
        const int r_lo = bm + wm * 32 + mt * 16 + g;
        const int r_hi = r_lo + 8;
        #pragma unroll
        for (int nt = 0; nt < 8; nt++) {
            const int cn = wn * 64 + nt * 8 + tg * 2;
            const int hh = cn >> 4, dk = cn & 15;
            if (r_lo < Mreal) {
                const int bb = r_lo / L_, ll = r_lo - bb * L_;
                *(unsigned*)&C[(((size_t)bb * H_ + hh) * L_ + ll) * DK_ + dk] =
                    pk(acc[mt][nt][0] * osc, acc[mt][nt][1] * osc);
            }
            if (r_hi < Mreal) {
                const int bb = r_hi / L_, ll = r_hi - bb * L_;
                *(unsigned*)&C[(((size_t)bb * H_ + hh) * L_ + ll) * DK_ + dk] =
                    pk(acc[mt][nt][2] * osc, acc[mt][nt][3] * osc);
            }
        }
    }
}

// ---------------- 4) bf16 flash attention (unchanged from R8) ----------------
__global__ void __launch_bounds__(256) attn_bf16(
    const __nv_bfloat16* __restrict__ q, const __nv_bfloat16* __restrict__ k,
    const __nv_bfloat16* __restrict__ v, __nv_bfloat16* __restrict__ o)
{
    __shared__ __align__(16) __nv_bfloat16 Ks[2][KT_][24];
    __shared__ __align__(16) __nv_bfloat16 Vs[2][KT_][24];
    __shared__ __align__(16) unsigned Pp[8][16][36];

    const int bh = blockIdx.x;
    const int b = bh >> 3, h = bh & 7;
    const int qt = blockIdx.y;
    const int tid = threadIdx.x, lane = tid & 31, warp = tid >> 5;
    const int g = lane >> 2, tg = lane & 3;

    const __nv_bfloat16* qp = q + (size_t)bh * L_ * DK_;
    const __nv_bfloat16* kp = k + (size_t)bh * L_ * DK_;
    const __nv_bfloat16* vp = v + (size_t)bh * L_ * DK_;

    const int r0 = qt * QT_ + warp * 16 + g;
    const int r1 = r0 + 8;
    const int r0c = r0 < L_ ? r0 : L_ - 1;
    const int r1c = r1 < L_ ? r1 : L_ - 1;
    const unsigned qa0 = *(const unsigned*)&qp[(size_t)r0c * DK_ + 2 * tg];
    const unsigned qa1 = *(const unsigned*)&qp[(size_t)r1c * DK_ + 2 * tg];
    const unsigned qa2 = *(const unsigned*)&qp[(size_t)r0c * DK_ + 2 * tg + 8];
    const unsigned qa3 = *(const unsigned*)&qp[(size_t)r1c * DK_ + 2 * tg + 8];

    float m0 = -1e30f, m1 = -1e30f, l0 = 0.f, l1 = 0.f;
    float oc[2][4];
    #pragma unroll
    for (int nt = 0; nt < 2; nt++)
        #pragma unroll
        for (int c = 0; c < 4; c++) oc[nt][c] = 0.f;

    const int srow = (tid & 127) >> 1;
    const int shalf = (tid & 1) * 8;
    const bool isv = tid >= 128;

    auto stage = [&](int buf, int j0) {
        int jc = j0 + srow; if (jc > L_ - 1) jc = L_ - 1;
        const __nv_bfloat16* src = (isv ? vp : kp) + (size_t)jc * DK_ + shalf;
        if (isv) cp16(&Vs[buf][srow][shalf], src);
        else     cp16(&Ks[buf][srow][shalf], src);
    };

    stage(0, 0);
    cp_commit();

    #pragma unroll 1
    for (int ti = 0; ti < NKTILES_; ti++) {
        const int buf = ti & 1;
        const int j0 = ti * KT_;
        cp_wait0();
        __syncthreads();
        if (ti + 1 < NKTILES_) { stage(buf ^ 1, j0 + KT_); cp_commit(); }

        float sc[8][4];
        #pragma unroll
        for (int nt = 0; nt < 8; nt++)
            #pragma unroll
            for (int c = 0; c < 4; c++) sc[nt][c] = 0.f;
        #pragma unroll
        for (int ntp = 0; ntp < 4; ntp++) {
            unsigned b0, b1, b2, b3;
            const int jrow = ntp * 16 + (lane & 7) + ((lane >> 4) & 1) * 8;
            const int kcol = ((lane >> 3) & 1) * 8;
            ldsm4(b0, b1, b2, b3, &Ks[buf][jrow][kcol]);
            mma_bf16(sc[2*ntp][0], sc[2*ntp][1], sc[2*ntp][2], sc[2*ntp][3],
                     qa0, qa1, qa2, qa3, b0, b1);
            mma_bf16(sc[2*ntp+1][0], sc[2*ntp+1][1], sc[2*ntp+1][2], sc[2*ntp+1][3],
                     qa0, qa1, qa2, qa3, b2, b3);
        }
        if (j0 + KT_ > L_) {
            #pragma unroll
            for (int nt = 0; nt < 8; nt++) {
                const int c = j0 + nt * 8 + 2 * tg;
                if (c     >= L_) { sc[nt][0] = -1e30f; sc[nt][2] = -1e30f; }
                if (c + 1 >= L_) { sc[nt][1] = -1e30f; sc[nt][3] = -1e30f; }
            }
        }
        float nm0 = m0, nm1 = m1;
        #pragma unroll
        for (int nt = 0; nt < 8; nt++) {
            nm0 = fmaxf(nm0, fmaxf(sc[nt][0], sc[nt][1]));
            nm1 = fmaxf(nm1, fmaxf(sc[nt][2], sc[nt][3]));
        }
        nm0 = fmaxf(nm0, __shfl_xor_sync(0xffffffffu, nm0, 1));
        nm0 = fmaxf(nm0, __shfl_xor_sync(0xffffffffu, nm0, 2));
        nm1 = fmaxf(nm1, __shfl_xor_sync(0xffffffffu, nm1, 1));
        nm1 = fmaxf(nm1, __shfl_xor_sync(0xffffffffu, nm1, 2));
        const float f0 = ex2(m0 - nm0);
        const float f1 = ex2(m1 - nm1);
        m0 = nm0; m1 = nm1;
        l0 *= f0; l1 *= f1;
        #pragma unroll
        for (int nt = 0; nt < 2; nt++) {
            oc[nt][0] *= f0; oc[nt][1] *= f0;
            oc[nt][2] *= f1; oc[nt][3] *= f1;
        }
        float rs0 = 0.f, rs1 = 0.f;
        #pragma unroll
        for (int nt = 0; nt < 8; nt++) {
            const float p0 = ex2(sc[nt][0] - m0);
            const float p1 = ex2(sc[nt][1] - m0);
            const float p2 = ex2(sc[nt][2] - m1);
            const float p3 = ex2(sc[nt][3] - m1);
            rs0 += p0 + p1;
            rs1 += p2 + p3;
            Pp[warp][g    ][nt * 4 + tg] = pk(p0, p1);
            Pp[warp][g + 8][nt * 4 + tg] = pk(p2, p3);
        }
        rs0 += __shfl_xor_sync(0xffffffffu, rs0, 1);
        rs0 += __shfl_xor_sync(0xffffffffu, rs0, 2);
        rs1 += __shfl_xor_sync(0xffffffffu, rs1, 1);
        rs1 += __shfl_xor_sync(0xffffffffu, rs1, 2);
        l0 += rs0; l1 += rs1;
        __syncwarp();
        #pragma unroll
        for (int ks = 0; ks < 4; ks++) {
            unsigned a0, a1, a2, a3;
            const unsigned* pa = &Pp[warp][(lane & 7) + ((lane >> 3) & 1) * 8]
                                         [ks * 8 + ((lane >> 4) & 1) * 4];
            ldsm4(a0, a1, a2, a3, pa);
            unsigned v0, v1, v2, v3;
            const int jrow = ks * 16 + (lane & 7) + ((lane >> 3) & 1) * 8;
            const int dkc = ((lane >> 4) & 1) * 8;
            ldsm4t(v0, v1, v2, v3, &Vs[buf][jrow][dkc]);
            mma_bf16(oc[0][0], oc[0][1], oc[0][2], oc[0][3], a0, a1, a2, a3, v0, v1);
            mma_bf16(oc[1][0], oc[1][1], oc[1][2], oc[1][3], a0, a1, a2, a3, v2, v3);
        }
        __syncwarp();
    }

    const float inv0 = 1.f / l0;
    const float inv1 = 1.f / l1;
    #pragma unroll
    for (int nt = 0; nt < 2; nt++) {
        const int dn = h * DK_ + nt * 8 + 2 * tg;
        if (r0 < L_)
            *(unsigned*)&o[((size_t)b * L_ + r0) * HK_ + dn] =
                pk(oc[nt][0] * inv0, oc[nt][1] * inv0);
        if (r1 < L_)
            *(unsigned*)&o[((size_t)b * L_ + r1) * HK_ + dn] =
                pk(oc[nt][2] * inv1, oc[nt][3] * inv1);
    }
}

// ---------------- 5) bias add + softmax + scatter (unchanged) ----------------
__global__ void __launch_bounds__(1024) finalize_k(
    const float* __restrict__ logits, const float* __restrict__ ab,
    const int* __restrict__ sel, const int* __restrict__ unsel,
    float* __restrict__ out)
{
    __shared__ float red[32];
    const int b = blockIdx.x, t = threadIdx.x;
    const int lane = t & 31, warp = t >> 5;
    const int last = sel[b * S_ + S_ - 1];
    const float* abrow = ab + ((size_t)b * N_ + last) * N_;

    int u = 0;
    float val = -3.0e38f;
    const bool active = (t < U_);
    if (active) {
        u = unsel[b * U_ + t];
        val = logits[b * L_ + 1 + t] + abrow[u];
    }
    float m = val;
    #pragma unroll
    for (int off = 16; off; off >>= 1) m = fmaxf(m, __shfl_xor_sync(0xffffffffu, m, off));
    if (lane == 0) red[warp] = m;
    __syncthreads();
    if (warp == 0) {
        float mm = red[lane];
        #pragma unroll
        for (int off = 16; off; off >>= 1) mm = fmaxf(mm, __shfl_xor_sync(0xffffffffu, mm, off));
        red[lane] = mm;
    }
    __syncthreads();
    m = red[0];
    __syncthreads();
    const float e = active ? __expf(val - m) : 0.f;
    float s = e;
    #pragma unroll
    for (int off = 16; off; off >>= 1) s += __shfl_xor_sync(0xffffffffu, s, off);
    if (lane == 0) red[warp] = s;
    __syncthreads();
    if (warp == 0) {
        float ss = red[lane];
        #pragma unroll
        for (int off = 16; off; off >>= 1) ss += __shfl_xor_sync(0xffffffffu, ss, off);
        red[lane] = ss;
    }
    __syncthreads();
    const float inv = 1.f / red[0];

    for (int i = t; i < N_; i += 1024) out[(size_t)b * N_ + i] = -2.0f;
    __syncthreads();
    if (active) {
        float p = e * inv;
        if (p <= 1e-5f) p += 1e-7f;
        out[(size_t)b * N_ + u] = p;
    }
}

// ---------------- launch ----------------
extern "C" void kernel_launch(void* const* d_in, const int* in_sizes, int n_in,
                              void* d_out, int out_size) {
    (void)in_sizes; (void)n_in; (void)out_size;
    const float* data   = (const float*)d_in[0];
    const float* ab     = (const float*)d_in[1];
    const float* Wfirst = (const float*)d_in[2];
    const float* bfirst = (const float*)d_in[3];
    const float* Wlast  = (const float*)d_in[4];
    const float* blast  = (const float*)d_in[5];
    const float* Wq     = (const float*)d_in[6];
    const float* Wk     = (const float*)d_in[7];
    const float* Wv     = (const float*)d_in[8];
    const float* Wo     = (const float*)d_in[9];
    const float* bo     = (const float*)d_in[10];
    const float* W1     = (const float*)d_in[11];
    const float* b1     = (const float*)d_in[12];
    const float* W2     = (const float*)d_in[13];
    const float* b2     = (const float*)d_in[14];
    const float* Wfin   = (const float*)d_in[15];
    const float* bfin   = (const float*)d_in[16];
    const int*   sel    = (const int*)d_in[17];
    float* out = (float*)d_out;

    void *px, *plog, *pun, *pxb, *pqb, *pkb, *pvb, *pob, *pwb;
    cudaGetSymbolAddress(&px,   g_x);
    cudaGetSymbolAddress(&plog, g_logits);
    cudaGetSymbolAddress(&pun,  g_unsel);
    cudaGetSymbolAddress(&pxb,  g_xb);
    cudaGetSymbolAddress(&pqb,  g_qb);
    cudaGetSymbolAddress(&pkb,  g_kb);
    cudaGetSymbolAddress(&pvb,  g_vb);
    cudaGetSymbolAddress(&pob,  g_ob);
    cudaGetSymbolAddress(&pwb,  g_wb);
    float* x      = (float*)px;
    float* logits = (float*)plog;
    int*   unsel  = (int*)pun;
    __nv_bfloat16* xb = (__nv_bfloat16*)pxb;
    __nv_bfloat16* qb = (__nv_bfloat16*)pqb;
    __nv_bfloat16* kb = (__nv_bfloat16*)pkb;
    __nv_bfloat16* vb = (__nv_bfloat16*)pvb;
    __nv_bfloat16* obuf = (__nv_bfloat16*)pob;
    __nv_bfloat16* wb = (__nv_bfloat16*)pwb;

    cudaFuncSetAttribute(mlp_k, cudaFuncAttributeMaxDynamicSharedMemorySize, SM_MLP_);

    prolog_k<<<32 + CVT_BLKS_, 1024>>>(data, sel, Wfirst, bfirst, Wlast, blast,
                                       Wq, Wk, Wv, Wo, W1, W2, wb, unsel, x, xb);

    const dim3 gqkv(3, MT_);
    const dim3 gattn(B_ * H_, QTILES_);
    for (int il = 0; il < NL_; il++) {
        const __nv_bfloat16* wqb = wb + (size_t)il * D_ * HK_;
        const __nv_bfloat16* wkb = wb + SQW_ + (size_t)il * D_ * HK_;
        const __nv_bfloat16* wvb = wb + 2 * SQW_ + (size_t)il * D_ * HK_;
        const __nv_bfloat16* wob = wb + 3 * SQW_ + (size_t)il * HK_ * D_;
        const __nv_bfloat16* w1b = wb + 4 * SQW_ + (size_t)il * D_ * FF_;
        const __nv_bfloat16* w2b = wb + 4 * SQW_ + SFW_ + (size_t)il * FF_ * D_;
        const float* bol = bo + (size_t)il * D_;
        const float* b1l = b1 + (size_t)il * FF_;
        const float* b2l = b2 + (size_t)il * D_;
        const bool last = (il == NL_ - 1);

        gemm_qkv<<<gqkv, 256>>>(xb, wqb, wkb, wvb, qb, kb, vb, M_);
        attn_bf16<<<gattn, 256>>>(qb, kb, vb, obuf);
        mlp_k<<<MT_, 256, SM_MLP_>>>(obuf, wob, bol, w1b, b1l, w2b, b2l, x, xb,
                                     last ? Wfin : nullptr, last ? bfin : nullptr,
                                     logits, M_);
    }

    finalize_k<<<B_, 1024>>>(logits, ab, sel, unsel, out);
}